// round 2
// baseline (speedup 1.0000x reference)
#include <cuda_runtime.h>
#include <cstring>

#define B_  4
#define T_  2048
#define E_  1024
#define H_  16
#define HS_ 64
#define M_  (B_*T_)   // 8192

typedef unsigned long long u64;

// ---------------- scratch (allocation-free: __device__ globals) ----------------
__device__ float g_h [(size_t)M_*E_];
__device__ float g_q [(size_t)M_*E_];
__device__ float g_k [(size_t)M_*E_];
__device__ float g_v [(size_t)M_*E_];
__device__ float g_y [(size_t)M_*E_];
__device__ float g_x2[(size_t)M_*E_];
__device__ float g_ff[(size_t)M_*4*E_];

// ---------------- packed f32x2 helpers ----------------
__device__ __forceinline__ u64 dup2(float v) {
    u64 r; asm("mov.b64 %0, {%1, %1};" : "=l"(r) : "f"(v)); return r;
}
__device__ __forceinline__ void ffma2(u64 &d, u64 a, u64 b) {
    asm("fma.rn.f32x2 %0, %1, %2, %0;" : "+l"(d) : "l"(a), "l"(b));
}
__device__ __forceinline__ void fmul2(u64 &d, u64 a, u64 b) {
    asm("mul.rn.f32x2 %0, %1, %2;" : "=l"(d) : "l"(a), "l"(b));
}
__device__ __forceinline__ float2 asf2(u64 v) {
    union { u64 u; float2 f; } c; c.u = v; return c.f;
}

// ---------------- LayerNorm (weight only, eps=1e-5) ----------------
__global__ __launch_bounds__(256) void ln_kernel(
    const float* __restrict__ X, const float* __restrict__ w,
    float* __restrict__ O)
{
    int row = blockIdx.x;
    int tid = threadIdx.x;
    const float* x = X + (size_t)row * E_;

    float4 v = *(const float4*)(x + tid * 4);
    float s  = v.x + v.y + v.z + v.w;
    float sq = v.x*v.x + v.y*v.y + v.z*v.z + v.w*v.w;

    #pragma unroll
    for (int o = 16; o; o >>= 1) {
        s  += __shfl_xor_sync(0xFFFFFFFFu, s,  o);
        sq += __shfl_xor_sync(0xFFFFFFFFu, sq, o);
    }
    __shared__ float ss[8], ssq[8], red[2];
    int wid = tid >> 5, lane = tid & 31;
    if (lane == 0) { ss[wid] = s; ssq[wid] = sq; }
    __syncthreads();
    if (tid == 0) {
        float a = 0.f, b = 0.f;
        #pragma unroll
        for (int i = 0; i < 8; i++) { a += ss[i]; b += ssq[i]; }
        float mean = a * (1.0f / E_);
        float var  = b * (1.0f / E_) - mean * mean;
        red[0] = mean;
        red[1] = rsqrtf(var + 1e-5f);
    }
    __syncthreads();
    float mean = red[0], rs = red[1];
    float4 wv = *(const float4*)(w + tid * 4);
    float4 o4;
    o4.x = (v.x - mean) * rs * wv.x;
    o4.y = (v.y - mean) * rs * wv.y;
    o4.z = (v.z - mean) * rs * wv.z;
    o4.w = (v.w - mean) * rs * wv.w;
    *(float4*)(O + (size_t)row * E_ + tid * 4) = o4;
}

// ---------------- SGEMM: C[M,N] = A[M,K] @ B[K,N] (+epilogue) ----------------
// 128x128 tile, BK=16, 256 threads, 8x8 per thread, f32x2 packed inner loop.
// OP: 0 = none, 1 = +bias+res, 2 = relu(+bias)
#define OP_NONE      0
#define OP_BIAS_RES  1
#define OP_RELU_BIAS 2

template<int OP>
__global__ __launch_bounds__(256) void sgemm_kernel(
    const float* __restrict__ A, const float* __restrict__ B,
    const float* __restrict__ bias, const float* __restrict__ res,
    float* __restrict__ C, int M, int N, int K)
{
    __shared__ float As[16][132];   // padded: conflict-light stores, 16B-aligned rows
    __shared__ float Bs[16][128];

    int tid = threadIdx.x;
    int tx = tid & 15, ty = tid >> 4;
    int bx = blockIdx.x * 128, by = blockIdx.y * 128;

    int arow = tid >> 2;            // 0..63 (+64 for second load)
    int acol = (tid & 3) << 2;      // 0,4,8,12
    int brow = tid >> 5;            // 0..7  (+8 for second load)
    int bcol = (tid & 31) << 2;     // 0..124

    const float* Aptr = A + (size_t)(by + arow) * K + acol;
    const float* Bptr = B + (size_t)brow * N + bx + bcol;
    const size_t AK64 = (size_t)64 * K;
    const size_t BN8  = (size_t)8  * N;
    const size_t BN16 = (size_t)16 * N;

    u64 acc[8][4];
    #pragma unroll
    for (int i = 0; i < 8; i++)
        #pragma unroll
        for (int j = 0; j < 4; j++) acc[i][j] = 0ull;

    int ntiles = K / 16;

    float4 ra0 = *(const float4*)(Aptr);
    float4 ra1 = *(const float4*)(Aptr + AK64);
    float4 rb0 = *(const float4*)(Bptr);
    float4 rb1 = *(const float4*)(Bptr + BN8);

    for (int t = 0; t < ntiles; t++) {
        // regs -> smem
        As[acol+0][arow]     = ra0.x; As[acol+1][arow]     = ra0.y;
        As[acol+2][arow]     = ra0.z; As[acol+3][arow]     = ra0.w;
        As[acol+0][arow+64]  = ra1.x; As[acol+1][arow+64]  = ra1.y;
        As[acol+2][arow+64]  = ra1.z; As[acol+3][arow+64]  = ra1.w;
        *(float4*)&Bs[brow  ][bcol] = rb0;
        *(float4*)&Bs[brow+8][bcol] = rb1;
        __syncthreads();

        // prefetch next tile (overlaps with compute)
        if (t + 1 < ntiles) {
            Aptr += 16; Bptr += BN16;
            ra0 = *(const float4*)(Aptr);
            ra1 = *(const float4*)(Aptr + AK64);
            rb0 = *(const float4*)(Bptr);
            rb1 = *(const float4*)(Bptr + BN8);
        }

        #pragma unroll
        for (int k = 0; k < 16; k++) {
            ulonglong2 b01 = *(const ulonglong2*)&Bs[k][tx*8];
            ulonglong2 b23 = *(const ulonglong2*)&Bs[k][tx*8 + 4];
            float4 a0 = *(const float4*)&As[k][ty*8];
            float4 a1 = *(const float4*)&As[k][ty*8 + 4];
            u64 ad[8];
            ad[0]=dup2(a0.x); ad[1]=dup2(a0.y); ad[2]=dup2(a0.z); ad[3]=dup2(a0.w);
            ad[4]=dup2(a1.x); ad[5]=dup2(a1.y); ad[6]=dup2(a1.z); ad[7]=dup2(a1.w);
            #pragma unroll
            for (int i = 0; i < 8; i++) {
                ffma2(acc[i][0], ad[i], b01.x);
                ffma2(acc[i][1], ad[i], b01.y);
                ffma2(acc[i][2], ad[i], b23.x);
                ffma2(acc[i][3], ad[i], b23.y);
            }
        }
        __syncthreads();
    }

    // epilogue
    int row0 = by + ty * 8;
    int col0 = bx + tx * 8;
    float bb[8];
    if (OP == OP_BIAS_RES || OP == OP_RELU_BIAS) {
        float4 b0 = *(const float4*)&bias[col0];
        float4 b1 = *(const float4*)&bias[col0 + 4];
        bb[0]=b0.x; bb[1]=b0.y; bb[2]=b0.z; bb[3]=b0.w;
        bb[4]=b1.x; bb[5]=b1.y; bb[6]=b1.z; bb[7]=b1.w;
    }
    #pragma unroll
    for (int i = 0; i < 8; i++) {
        int row = row0 + i;
        float v[8];
        #pragma unroll
        for (int jp = 0; jp < 4; jp++) {
            float2 f = asf2(acc[i][jp]);
            v[2*jp] = f.x; v[2*jp+1] = f.y;
        }
        if (OP == OP_BIAS_RES) {
            float4 r0 = *(const float4*)&res[(size_t)row * N + col0];
            float4 r1 = *(const float4*)&res[(size_t)row * N + col0 + 4];
            v[0]+=bb[0]+r0.x; v[1]+=bb[1]+r0.y; v[2]+=bb[2]+r0.z; v[3]+=bb[3]+r0.w;
            v[4]+=bb[4]+r1.x; v[5]+=bb[5]+r1.y; v[6]+=bb[6]+r1.z; v[7]+=bb[7]+r1.w;
        } else if (OP == OP_RELU_BIAS) {
            #pragma unroll
            for (int j = 0; j < 8; j++) v[j] = fmaxf(v[j] + bb[j], 0.0f);
        }
        *(float4*)&C[(size_t)row * N + col0    ] = make_float4(v[0],v[1],v[2],v[3]);
        *(float4*)&C[(size_t)row * N + col0 + 4] = make_float4(v[4],v[5],v[6],v[7]);
    }
}

// ---------------- Causal flash attention, fp32, f32x2 packed ----------------
// grid: (T/128, B*H). 128 threads; thread tid owns q-row r = qb*128+tid.
// KV tiles of 64 keys staged in SMEM (broadcast reads); online softmax in
// 32-key chunks to keep registers bounded (q:64 + o:64 + s:32 floats).
__global__ __launch_bounds__(128) void attn_kernel(
    const float* __restrict__ Q, const float* __restrict__ Kg,
    const float* __restrict__ V, float* __restrict__ Y)
{
    __shared__ float ks[64][64];
    __shared__ float vs[64][64];

    int tid = threadIdx.x;
    int bh  = blockIdx.y;
    int b   = bh >> 4;       // H_ = 16
    int h   = bh & 15;
    int r   = blockIdx.x * 128 + tid;

    const float* qrow = Q + ((size_t)(b * T_ + r)) * E_ + h * HS_;
    u64 q2[32];
    #pragma unroll
    for (int i = 0; i < 16; i++) {
        ulonglong2 t = *(const ulonglong2*)(qrow + i * 4);
        q2[2*i] = t.x; q2[2*i+1] = t.y;
    }

    u64 o2[32];
    #pragma unroll
    for (int i = 0; i < 32; i++) o2[i] = 0ull;
    float m = -1e30f, l = 0.0f;
    const float scale = 0.03125f;   // E^-0.5 = 1/32

    const float* Kbh = Kg + (size_t)b * T_ * E_ + h * HS_;
    const float* Vbh = V  + (size_t)b * T_ * E_ + h * HS_;

    int kend = blockIdx.x * 128 + 128;   // keys needed by this q-block
    int lr = tid >> 1;
    int lc = (tid & 1) * 32;

    for (int j0 = 0; j0 < kend; j0 += 64) {
        const float* kp = Kbh + (size_t)(j0 + lr) * E_ + lc;
        const float* vp = Vbh + (size_t)(j0 + lr) * E_ + lc;
        #pragma unroll
        for (int i = 0; i < 8; i++) {
            *(float4*)&ks[lr][lc + 4*i] = *(const float4*)(kp + 4*i);
            *(float4*)&vs[lr][lc + 4*i] = *(const float4*)(vp + 4*i);
        }
        __syncthreads();

        #pragma unroll
        for (int c = 0; c < 2; c++) {
            int cbase = j0 + c * 32;
            if (cbase <= r) {
                float s[32];
                #pragma unroll
                for (int j = 0; j < 32; j++) {
                    u64 a2 = 0ull;
                    const float* krow = &ks[c*32 + j][0];
                    #pragma unroll
                    for (int dd = 0; dd < 32; dd++)
                        ffma2(a2, q2[dd], *(const u64*)(krow + 2*dd));
                    float2 f = asf2(a2);
                    float sv = (f.x + f.y) * scale;
                    s[j] = (cbase + j <= r) ? sv : -1e30f;
                }
                float mn = m;
                #pragma unroll
                for (int j = 0; j < 32; j++) mn = fmaxf(mn, s[j]);
                float corr = __expf(m - mn);
                m = mn;
                l *= corr;
                u64 cd = dup2(corr);
                #pragma unroll
                for (int dd = 0; dd < 32; dd++) fmul2(o2[dd], o2[dd], cd);
                #pragma unroll
                for (int j = 0; j < 32; j++) {
                    float p = __expf(s[j] - m);
                    l += p;
                    u64 pd = dup2(p);
                    const float* vrow = &vs[c*32 + j][0];
                    #pragma unroll
                    for (int dd = 0; dd < 32; dd++)
                        ffma2(o2[dd], pd, *(const u64*)(vrow + 2*dd));
                }
            }
        }
        __syncthreads();
    }

    float inv = 1.0f / l;
    float* yrow = Y + ((size_t)(b * T_ + r)) * E_ + h * HS_;
    #pragma unroll
    for (int i = 0; i < 32; i++) {
        float2 f = asf2(o2[i]);
        *(float2*)(yrow + 2*i) = make_float2(f.x * inv, f.y * inv);
    }
}

// ---------------- launch ----------------
extern "C" void kernel_launch(void* const* d_in, const int* in_sizes, int n_in,
                              void* d_out, int out_size)
{
    const float* x    = (const float*)d_in[0];
    const float* Wq   = (const float*)d_in[1];
    const float* Wk   = (const float*)d_in[2];
    const float* Wv   = (const float*)d_in[3];
    const float* Wo   = (const float*)d_in[4];
    const float* bo   = (const float*)d_in[5];
    const float* ln1w = (const float*)d_in[6];
    const float* ln2w = (const float*)d_in[7];
    const float* W1   = (const float*)d_in[8];
    const float* b1   = (const float*)d_in[9];
    const float* W2   = (const float*)d_in[10];
    const float* b2   = (const float*)d_in[11];
    float* out = (float*)d_out;

    float *ph, *pq, *pk, *pv, *py, *px2, *pff;
    cudaGetSymbolAddress((void**)&ph,  g_h);
    cudaGetSymbolAddress((void**)&pq,  g_q);
    cudaGetSymbolAddress((void**)&pk,  g_k);
    cudaGetSymbolAddress((void**)&pv,  g_v);
    cudaGetSymbolAddress((void**)&py,  g_y);
    cudaGetSymbolAddress((void**)&px2, g_x2);
    cudaGetSymbolAddress((void**)&pff, g_ff);

    dim3 gE (E_  / 128, M_ / 128);   // (8, 64)
    dim3 g4E(4*E_/ 128, M_ / 128);   // (32, 64)

    // 1) h = LN1(x)
    ln_kernel<<<M_, 256>>>(x, ln1w, ph);
    // 2) q,k,v = h @ W{q,k,v}
    sgemm_kernel<OP_NONE><<<gE, 256>>>(ph, Wq, nullptr, nullptr, pq, M_, E_, E_);
    sgemm_kernel<OP_NONE><<<gE, 256>>>(ph, Wk, nullptr, nullptr, pk, M_, E_, E_);
    sgemm_kernel<OP_NONE><<<gE, 256>>>(ph, Wv, nullptr, nullptr, pv, M_, E_, E_);
    // 3) y = causal-softmax-attention(q,k,v)
    attn_kernel<<<dim3(T_/128, B_*H_), 128>>>(pq, pk, pv, py);
    // 4) x2 = x + y @ Wo + bo
    sgemm_kernel<OP_BIAS_RES><<<gE, 256>>>(py, Wo, bo, x, px2, M_, E_, E_);
    // 5) h2 = LN2(x2)  (reuse g_h)
    ln_kernel<<<M_, 256>>>(px2, ln2w, ph);
    // 6) ff = relu(h2 @ W1 + b1)
    sgemm_kernel<OP_RELU_BIAS><<<g4E, 256>>>(ph, W1, b1, nullptr, pff, M_, 4*E_, E_);
    // 7) out = x2 + ff @ W2 + b2
    sgemm_kernel<OP_BIAS_RES><<<gE, 256>>>(pff, W2, b2, px2, out, M_, E_, 4*E_);
}

// round 5
// speedup vs baseline: 1.5301x; 1.5301x over previous
#include <cuda_runtime.h>
#include <cuda_bf16.h>
#include <cstdint>

#define B_  4
#define T_  2048
#define E_  1024
#define H_  16
#define HS_ 64
#define M_  (B_*T_)    // 8192
#define FF_ (4*E_)     // 4096

typedef unsigned long long u64;
typedef __nv_bfloat16 bf16;

// ======================= scratch pool (__device__ global) =======================
#define SZ_HB   ((size_t)M_*E_*2)      // bf16 [M,E]
#define SZ_F32  ((size_t)M_*E_*4)      // f32  [M,E]
#define SZ_FFB  ((size_t)M_*FF_*2)     // bf16 [M,4E]
#define SZ_WB   ((size_t)E_*E_*2)      // bf16 [E,E]
#define SZ_W1B  ((size_t)E_*FF_*2)     // bf16 [4E,E] or [E,4E]

constexpr size_t O_HHI  = 0;
constexpr size_t O_HLO  = O_HHI  + SZ_HB;
constexpr size_t O_Q    = O_HLO  + SZ_HB;
constexpr size_t O_K    = O_Q    + SZ_F32;
constexpr size_t O_V    = O_K    + SZ_F32;
constexpr size_t O_YHI  = O_V    + SZ_F32;
constexpr size_t O_YLO  = O_YHI  + SZ_HB;
constexpr size_t O_X2   = O_YLO  + SZ_HB;
constexpr size_t O_FFHI = O_X2   + SZ_F32;
constexpr size_t O_FFLO = O_FFHI + SZ_FFB;
constexpr size_t O_WQH  = O_FFLO + SZ_FFB;
constexpr size_t O_WQL  = O_WQH  + SZ_WB;
constexpr size_t O_WKH  = O_WQL  + SZ_WB;
constexpr size_t O_WKL  = O_WKH  + SZ_WB;
constexpr size_t O_WVH  = O_WKL  + SZ_WB;
constexpr size_t O_WVL  = O_WVH  + SZ_WB;
constexpr size_t O_WOH  = O_WVL  + SZ_WB;
constexpr size_t O_WOL  = O_WOH  + SZ_WB;
constexpr size_t O_W1H  = O_WOL  + SZ_WB;
constexpr size_t O_W1L  = O_W1H  + SZ_W1B;
constexpr size_t O_W2H  = O_W1L  + SZ_W1B;
constexpr size_t O_W2L  = O_W2H  + SZ_W1B;
constexpr size_t POOLSZ = O_W2L  + SZ_W1B;

__device__ __align__(1024) unsigned char g_pool[POOLSZ];

// ======================= PTX helpers =======================
__device__ __forceinline__ uint32_t s2u(const void* p){
    uint32_t a;
    asm("{ .reg .u64 t; cvta.to.shared.u64 t, %1; cvt.u32.u64 %0, t; }" : "=r"(a) : "l"(p));
    return a;
}
__device__ __forceinline__ void cp16(uint32_t s, const void* g){
    asm volatile("cp.async.cg.shared.global [%0], [%1], 16;" :: "r"(s), "l"(g));
}
__device__ __forceinline__ void ldm4(uint32_t (&r)[4], uint32_t a){
    asm volatile("ldmatrix.sync.aligned.m8n8.x4.shared.b16 {%0,%1,%2,%3}, [%4];"
                 : "=r"(r[0]), "=r"(r[1]), "=r"(r[2]), "=r"(r[3]) : "r"(a));
}
__device__ __forceinline__ void mma_bf16(float (&c)[4], const uint32_t* a, uint32_t b0, uint32_t b1){
    asm volatile(
        "mma.sync.aligned.m16n8k16.row.col.f32.bf16.bf16.f32 "
        "{%0,%1,%2,%3}, {%4,%5,%6,%7}, {%8,%9}, {%0,%1,%2,%3};"
        : "+f"(c[0]), "+f"(c[1]), "+f"(c[2]), "+f"(c[3])
        : "r"(a[0]), "r"(a[1]), "r"(a[2]), "r"(a[3]), "r"(b0), "r"(b1));
}

// ======================= packed f32x2 helpers (attention) =======================
__device__ __forceinline__ u64 dup2(float v) {
    u64 r; asm("mov.b64 %0, {%1, %1};" : "=l"(r) : "f"(v)); return r;
}
__device__ __forceinline__ void ffma2(u64 &d, u64 a, u64 b) {
    asm("fma.rn.f32x2 %0, %1, %2, %0;" : "+l"(d) : "l"(a), "l"(b));
}
__device__ __forceinline__ void fmul2(u64 &d, u64 a, u64 b) {
    asm("mul.rn.f32x2 %0, %1, %2;" : "=l"(d) : "l"(a), "l"(b));
}
__device__ __forceinline__ float2 asf2(u64 v) {
    union { u64 u; float2 f; } c; c.u = v; return c.f;
}
__device__ __forceinline__ void split_bf16(float v, bf16 &hi, bf16 &lo){
    hi = __float2bfloat16(v);
    lo = __float2bfloat16(v - __bfloat162float(hi));
}

// ======================= LayerNorm -> bf16 hi/lo splits =======================
__global__ __launch_bounds__(256) void ln_split_kernel(
    const float* __restrict__ X, const float* __restrict__ w,
    bf16* __restrict__ Ohi, bf16* __restrict__ Olo)
{
    int row = blockIdx.x;
    int tid = threadIdx.x;
    const float* x = X + (size_t)row * E_;

    float4 v = *(const float4*)(x + tid * 4);
    float s  = v.x + v.y + v.z + v.w;
    float sq = v.x*v.x + v.y*v.y + v.z*v.z + v.w*v.w;

    #pragma unroll
    for (int o = 16; o; o >>= 1) {
        s  += __shfl_xor_sync(0xFFFFFFFFu, s,  o);
        sq += __shfl_xor_sync(0xFFFFFFFFu, sq, o);
    }
    __shared__ float ss[8], ssq[8], red[2];
    int wid = tid >> 5, lane = tid & 31;
    if (lane == 0) { ss[wid] = s; ssq[wid] = sq; }
    __syncthreads();
    if (tid == 0) {
        float a = 0.f, b = 0.f;
        #pragma unroll
        for (int i = 0; i < 8; i++) { a += ss[i]; b += ssq[i]; }
        float mean = a * (1.0f / E_);
        float var  = b * (1.0f / E_) - mean * mean;
        red[0] = mean;
        red[1] = rsqrtf(var + 1e-5f);
    }
    __syncthreads();
    float mean = red[0], rs = red[1];
    float4 wv = *(const float4*)(w + tid * 4);
    float o0 = (v.x - mean) * rs * wv.x;
    float o1 = (v.y - mean) * rs * wv.y;
    float o2 = (v.z - mean) * rs * wv.z;
    float o3 = (v.w - mean) * rs * wv.w;

    bf16 h0,h1,h2,h3,l0,l1,l2,l3;
    split_bf16(o0,h0,l0); split_bf16(o1,h1,l1);
    split_bf16(o2,h2,l2); split_bf16(o3,h3,l3);
    size_t off = (size_t)row * E_ + tid * 4;
    __nv_bfloat162 ph0; ph0.x=h0; ph0.y=h1;
    __nv_bfloat162 ph1; ph1.x=h2; ph1.y=h3;
    __nv_bfloat162 pl0; pl0.x=l0; pl0.y=l1;
    __nv_bfloat162 pl1; pl1.x=l2; pl1.y=l3;
    *(__nv_bfloat162*)(Ohi + off)     = ph0;
    *(__nv_bfloat162*)(Ohi + off + 2) = ph1;
    *(__nv_bfloat162*)(Olo + off)     = pl0;
    *(__nv_bfloat162*)(Olo + off + 2) = pl1;
}

// ======================= weight transpose + split: W[K,N] -> Wt_{hi,lo}[N,K] ======
__global__ __launch_bounds__(256) void wsplit_kernel(
    const float* __restrict__ W, bf16* __restrict__ Whi, bf16* __restrict__ Wlo,
    int K, int N)
{
    __shared__ float t[32][33];
    int n0 = blockIdx.x * 32, k0 = blockIdx.y * 32;
    int tx = threadIdx.x, ty0 = threadIdx.y;
    #pragma unroll
    for (int dy = 0; dy < 32; dy += 8) {
        int ty = ty0 + dy;
        t[ty][tx] = W[(size_t)(k0 + ty) * N + n0 + tx];
    }
    __syncthreads();
    #pragma unroll
    for (int dy = 0; dy < 32; dy += 8) {
        int ty = ty0 + dy;
        float v = t[tx][ty];              // element (k=k0+tx, n=n0+ty)
        bf16 hi, lo; split_bf16(v, hi, lo);
        size_t o = (size_t)(n0 + ty) * K + k0 + tx;
        Whi[o] = hi;
        Wlo[o] = lo;
    }
}

// ======================= HMMA GEMM (bf16 hi/lo split, fp32 accum) ============
// C[M,N] = A[M,K] @ B[K,N] with B pre-transposed as Bt[N,K] (hi/lo).
// mma.sync m16n8k16 row.col: A [M,K] K-major, B [N,K] K-major -> both plain ldmatrix.
// BM=BN=128, BK=32, 256 thr, warp tile 64x32 (warps 2x4).
// OP: 0 = f32 C; 1 = acc+bias+res -> f32; 2 = relu(acc+bias) -> bf16 hi/lo
#define BM 128
#define BN 128
#define BK 32
#define ROWB   80          // padded row stride bytes (32 bf16 = 64B + 16B pad)
#define MTILE  (128*ROWB)  // 10240B per matrix tile
#define BUFSZ  (4*MTILE)   // Ahi,Alo,Bhi,Blo = 40960B
#define SMEM_SZ (2*BUFSZ)  // 81920B double-buffered

template<int OP>
__global__ __launch_bounds__(256, 1) void gemm_tc(
    const bf16* __restrict__ Ahi, const bf16* __restrict__ Alo,
    const bf16* __restrict__ Bhi, const bf16* __restrict__ Blo,
    const float* __restrict__ bias, const float* __restrict__ res,
    float* __restrict__ C, bf16* __restrict__ Chi, bf16* __restrict__ Clo,
    int M, int N, int K)
{
    extern __shared__ __align__(128) unsigned char smem[];
    uint32_t sb = s2u(smem);
    int tid = threadIdx.x;
    int lane = tid & 31, wid = tid >> 5;
    int warp_m = wid & 1, warp_n = wid >> 1;   // 2 x 4
    int bx = blockIdx.x * BN, by = blockIdx.y * BM;

    // ---- load addressing: 2 chunks (16B) per thread per matrix ----
    int ch0 = tid * 2;
    int r0l = ch0 >> 2,        c0l = ch0 & 3;
    int r1l = (ch0 + 1) >> 2,  c1l = (ch0 + 1) & 3;
    uint32_t so0 = (uint32_t)(r0l * ROWB + c0l * 16);
    uint32_t so1 = (uint32_t)(r1l * ROWB + c1l * 16);

    const bf16* gAhi = Ahi + (size_t)(by) * K;
    const bf16* gAlo = Alo + (size_t)(by) * K;
    const bf16* gBhi = Bhi + (size_t)(bx) * K;
    const bf16* gBlo = Blo + (size_t)(bx) * K;

    float acc[4][4][4];
    #pragma unroll
    for (int i = 0; i < 4; i++)
        #pragma unroll
        for (int j = 0; j < 4; j++)
            #pragma unroll
            for (int q = 0; q < 4; q++) acc[i][j][q] = 0.f;

    int nt = K / BK;

    auto issue_tile = [&](int t, int buf) {
        uint32_t base = sb + buf * BUFSZ;
        int k0 = t * BK;
        const bf16* a0 = gAhi + (size_t)r0l * K + k0 + c0l * 8;
        const bf16* a1 = gAhi + (size_t)r1l * K + k0 + c1l * 8;
        cp16(base + so0, a0);
        cp16(base + so1, a1);
        const bf16* b0 = gAlo + (size_t)r0l * K + k0 + c0l * 8;
        const bf16* b1 = gAlo + (size_t)r1l * K + k0 + c1l * 8;
        cp16(base + MTILE + so0, b0);
        cp16(base + MTILE + so1, b1);
        const bf16* c0 = gBhi + (size_t)r0l * K + k0 + c0l * 8;
        const bf16* c1 = gBhi + (size_t)r1l * K + k0 + c1l * 8;
        cp16(base + 2*MTILE + so0, c0);
        cp16(base + 2*MTILE + so1, c1);
        const bf16* d0 = gBlo + (size_t)r0l * K + k0 + c0l * 8;
        const bf16* d1 = gBlo + (size_t)r1l * K + k0 + c1l * 8;
        cp16(base + 3*MTILE + so0, d0);
        cp16(base + 3*MTILE + so1, d1);
        asm volatile("cp.async.commit_group;" ::: "memory");
    };

    issue_tile(0, 0);

    // fragment addresses (byte offsets within a matrix tile), lane-dependent
    uint32_t a_row = (uint32_t)(warp_m * 64 + (lane & 15));
    uint32_t a_cb  = (uint32_t)((lane >> 4) * 16);
    uint32_t b_row = (uint32_t)(warp_n * 32 + (lane & 7) + ((lane >> 4) & 1) * 8);
    uint32_t b_cb  = (uint32_t)(((lane >> 3) & 1) * 16);

    for (int t = 0; t < nt; t++) {
        int buf = t & 1;
        if (t + 1 < nt) {
            issue_tile(t + 1, buf ^ 1);
            asm volatile("cp.async.wait_group 1;" ::: "memory");
        } else {
            asm volatile("cp.async.wait_group 0;" ::: "memory");
        }
        __syncthreads();

        uint32_t base  = sb + buf * BUFSZ;
        uint32_t sAhi = base;
        uint32_t sAlo = base + MTILE;
        uint32_t sBhi = base + 2*MTILE;
        uint32_t sBlo = base + 3*MTILE;

        #pragma unroll
        for (int s = 0; s < 2; s++) {           // two k16 steps in BK=32
            uint32_t kb = (uint32_t)(s * 32);
            uint32_t ahi[4][4], alo[4][4], bhi[2][4], blo[2][4];
            #pragma unroll
            for (int mt = 0; mt < 4; mt++) {
                uint32_t ao = (a_row + mt * 16) * ROWB + kb + a_cb;
                ldm4(ahi[mt], sAhi + ao);
                ldm4(alo[mt], sAlo + ao);
            }
            #pragma unroll
            for (int ntp = 0; ntp < 2; ntp++) {
                uint32_t bo = (b_row + ntp * 16) * ROWB + kb + b_cb;
                ldm4(bhi[ntp], sBhi + bo);
                ldm4(blo[ntp], sBlo + bo);
            }
            #pragma unroll
            for (int mt = 0; mt < 4; mt++) {
                #pragma unroll
                for (int ntp = 0; ntp < 2; ntp++) {
                    #pragma unroll
                    for (int hf = 0; hf < 2; hf++) {
                        int ntj = ntp * 2 + hf;
                        mma_bf16(acc[mt][ntj], ahi[mt], bhi[ntp][hf*2], bhi[ntp][hf*2+1]);
                        mma_bf16(acc[mt][ntj], ahi[mt], blo[ntp][hf*2], blo[ntp][hf*2+1]);
                        mma_bf16(acc[mt][ntj], alo[mt], bhi[ntp][hf*2], bhi[ntp][hf*2+1]);
                    }
                }
            }
        }
        __syncthreads();
    }

    // -------- epilogue --------
    int er = by + warp_m * 64 + (lane >> 2);
    int ec = bx + warp_n * 32 + (lane & 3) * 2;
    #pragma unroll
    for (int mt = 0; mt < 4; mt++) {
        #pragma unroll
        for (int half = 0; half < 2; half++) {
            int row = er + mt * 16 + half * 8;
            #pragma unroll
            for (int ntj = 0; ntj < 4; ntj++) {
                int col = ec + ntj * 8;
                float v0 = acc[mt][ntj][half*2];
                float v1 = acc[mt][ntj][half*2+1];
                if (OP == 0) {
                    *(float2*)&C[(size_t)row * N + col] = make_float2(v0, v1);
                } else if (OP == 1) {
                    float2 rv = *(const float2*)&res[(size_t)row * N + col];
                    float2 bv = *(const float2*)&bias[col];
                    *(float2*)&C[(size_t)row * N + col] =
                        make_float2(v0 + bv.x + rv.x, v1 + bv.y + rv.y);
                } else {
                    float2 bv = *(const float2*)&bias[col];
                    float w0 = fmaxf(v0 + bv.x, 0.0f);
                    float w1 = fmaxf(v1 + bv.y, 0.0f);
                    bf16 h0,l0,h1,l1;
                    split_bf16(w0, h0, l0);
                    split_bf16(w1, h1, l1);
                    __nv_bfloat162 hh; hh.x = h0; hh.y = h1;
                    __nv_bfloat162 ll; ll.x = l0; ll.y = l1;
                    *(__nv_bfloat162*)&Chi[(size_t)row * N + col] = hh;
                    *(__nv_bfloat162*)&Clo[(size_t)row * N + col] = ll;
                }
            }
        }
    }
}

// ======================= Causal flash attention, fp32 (writes bf16 hi/lo y) =====
__global__ __launch_bounds__(128) void attn_kernel(
    const float* __restrict__ Q, const float* __restrict__ Kg,
    const float* __restrict__ V, bf16* __restrict__ Yhi, bf16* __restrict__ Ylo)
{
    __shared__ float ks[64][64];
    __shared__ float vs[64][64];

    int tid = threadIdx.x;
    int bh  = blockIdx.y;
    int b   = bh >> 4;
    int h   = bh & 15;
    int r   = blockIdx.x * 128 + tid;

    const float* qrow = Q + ((size_t)(b * T_ + r)) * E_ + h * HS_;
    u64 q2[32];
    #pragma unroll
    for (int i = 0; i < 16; i++) {
        ulonglong2 t = *(const ulonglong2*)(qrow + i * 4);
        q2[2*i] = t.x; q2[2*i+1] = t.y;
    }

    u64 o2[32];
    #pragma unroll
    for (int i = 0; i < 32; i++) o2[i] = 0ull;
    float m = -1e30f, l = 0.0f;
    const float scale = 0.03125f;

    const float* Kbh = Kg + (size_t)b * T_ * E_ + h * HS_;
    const float* Vbh = V  + (size_t)b * T_ * E_ + h * HS_;

    int kend = blockIdx.x * 128 + 128;
    int lr = tid >> 1;
    int lc = (tid & 1) * 32;

    for (int j0 = 0; j0 < kend; j0 += 64) {
        const float* kp = Kbh + (size_t)(j0 + lr) * E_ + lc;
        const float* vp = Vbh + (size_t)(j0 + lr) * E_ + lc;
        #pragma unroll
        for (int i = 0; i < 8; i++) {
            *(float4*)&ks[lr][lc + 4*i] = *(const float4*)(kp + 4*i);
            *(float4*)&vs[lr][lc + 4*i] = *(const float4*)(vp + 4*i);
        }
        __syncthreads();

        #pragma unroll
        for (int c = 0; c < 2; c++) {
            int cbase = j0 + c * 32;
            if (cbase <= r) {
                float s[32];
                #pragma unroll
                for (int j = 0; j < 32; j++) {
                    u64 a2 = 0ull;
                    const float* krow = &ks[c*32 + j][0];
                    #pragma unroll
                    for (int dd = 0; dd < 32; dd++)
                        ffma2(a2, q2[dd], *(const u64*)(krow + 2*dd));
                    float2 f = asf2(a2);
                    float sv = (f.x + f.y) * scale;
                    s[j] = (cbase + j <= r) ? sv : -1e30f;
                }
                float mn = m;
                #pragma unroll
                for (int j = 0; j < 32; j++) mn = fmaxf(mn, s[j]);
                float corr = __expf(m - mn);
                m = mn;
                l *= corr;
                u64 cd = dup2(corr);
                #pragma unroll
                for (int dd = 0; dd < 32; dd++) fmul2(o2[dd], o2[dd], cd);
                #pragma unroll
                for (int j = 0; j < 32; j++) {
                    float p = __expf(s[j] - m);
                    l += p;
                    u64 pd = dup2(p);
                    const float* vrow = &vs[c*32 + j][0];
                    #pragma unroll
                    for (int dd = 0; dd < 32; dd++)
                        ffma2(o2[dd], pd, *(const u64*)(vrow + 2*dd));
                }
            }
        }
        __syncthreads();
    }

    float inv = 1.0f / l;
    size_t yoff = ((size_t)(b * T_ + r)) * E_ + h * HS_;
    bf16* yh = Yhi + yoff;
    bf16* yl = Ylo + yoff;
    #pragma unroll
    for (int i = 0; i < 32; i++) {
        float2 f = asf2(o2[i]);
        float v0 = f.x * inv, v1 = f.y * inv;
        bf16 h0,l0,h1,l1;
        split_bf16(v0, h0, l0);
        split_bf16(v1, h1, l1);
        __nv_bfloat162 hh; hh.x = h0; hh.y = h1;
        __nv_bfloat162 ll; ll.x = l0; ll.y = l1;
        *(__nv_bfloat162*)(yh + 2*i) = hh;
        *(__nv_bfloat162*)(yl + 2*i) = ll;
    }
}

// ======================= launch =======================
extern "C" void kernel_launch(void* const* d_in, const int* in_sizes, int n_in,
                              void* d_out, int out_size)
{
    const float* x    = (const float*)d_in[0];
    const float* Wq   = (const float*)d_in[1];
    const float* Wk   = (const float*)d_in[2];
    const float* Wv   = (const float*)d_in[3];
    const float* Wo   = (const float*)d_in[4];
    const float* bo   = (const float*)d_in[5];
    const float* ln1w = (const float*)d_in[6];
    const float* ln2w = (const float*)d_in[7];
    const float* W1   = (const float*)d_in[8];
    const float* b1   = (const float*)d_in[9];
    const float* W2   = (const float*)d_in[10];
    const float* b2   = (const float*)d_in[11];
    float* out = (float*)d_out;

    unsigned char* pool;
    cudaGetSymbolAddress((void**)&pool, g_pool);

    bf16*  hhi  = (bf16*)(pool + O_HHI);
    bf16*  hlo  = (bf16*)(pool + O_HLO);
    float* q    = (float*)(pool + O_Q);
    float* k    = (float*)(pool + O_K);
    float* v    = (float*)(pool + O_V);
    bf16*  yhi  = (bf16*)(pool + O_YHI);
    bf16*  ylo  = (bf16*)(pool + O_YLO);
    float* x2   = (float*)(pool + O_X2);
    bf16*  ffhi = (bf16*)(pool + O_FFHI);
    bf16*  fflo = (bf16*)(pool + O_FFLO);
    bf16*  wqh = (bf16*)(pool + O_WQH), *wql = (bf16*)(pool + O_WQL);
    bf16*  wkh = (bf16*)(pool + O_WKH), *wkl = (bf16*)(pool + O_WKL);
    bf16*  wvh = (bf16*)(pool + O_WVH), *wvl = (bf16*)(pool + O_WVL);
    bf16*  woh = (bf16*)(pool + O_WOH), *wol = (bf16*)(pool + O_WOL);
    bf16*  w1h = (bf16*)(pool + O_W1H), *w1l = (bf16*)(pool + O_W1L);
    bf16*  w2h = (bf16*)(pool + O_W2H), *w2l = (bf16*)(pool + O_W2L);

    cudaFuncSetAttribute(gemm_tc<0>, cudaFuncAttributeMaxDynamicSharedMemorySize, SMEM_SZ);
    cudaFuncSetAttribute(gemm_tc<1>, cudaFuncAttributeMaxDynamicSharedMemorySize, SMEM_SZ);
    cudaFuncSetAttribute(gemm_tc<2>, cudaFuncAttributeMaxDynamicSharedMemorySize, SMEM_SZ);

    dim3 tb(32, 8);
    // weight transpose + split
    wsplit_kernel<<<dim3(E_/32,  E_/32),  tb>>>(Wq, wqh, wql, E_,  E_);
    wsplit_kernel<<<dim3(E_/32,  E_/32),  tb>>>(Wk, wkh, wkl, E_,  E_);
    wsplit_kernel<<<dim3(E_/32,  E_/32),  tb>>>(Wv, wvh, wvl, E_,  E_);
    wsplit_kernel<<<dim3(E_/32,  E_/32),  tb>>>(Wo, woh, wol, E_,  E_);
    wsplit_kernel<<<dim3(FF_/32, E_/32),  tb>>>(W1, w1h, w1l, E_,  FF_);
    wsplit_kernel<<<dim3(E_/32,  FF_/32), tb>>>(W2, w2h, w2l, FF_, E_);

    dim3 gE (E_  / BN, M_ / BM);   // (8, 64)
    dim3 g4E(FF_ / BN, M_ / BM);   // (32, 64)

    // 1) h = LN1(x) -> bf16 splits
    ln_split_kernel<<<M_, 256>>>(x, ln1w, hhi, hlo);
    // 2) q,k,v = h @ W{q,k,v}  (f32 out)
    gemm_tc<0><<<gE, 256, SMEM_SZ>>>(hhi, hlo, wqh, wql, nullptr, nullptr, q, nullptr, nullptr, M_, E_, E_);
    gemm_tc<0><<<gE, 256, SMEM_SZ>>>(hhi, hlo, wkh, wkl, nullptr, nullptr, k, nullptr, nullptr, M_, E_, E_);
    gemm_tc<0><<<gE, 256, SMEM_SZ>>>(hhi, hlo, wvh, wvl, nullptr, nullptr, v, nullptr, nullptr, M_, E_, E_);
    // 3) y = attention(q,k,v) -> bf16 splits
    attn_kernel<<<dim3(T_/128, B_*H_), 128>>>(q, k, v, yhi, ylo);
    // 4) x2 = x + y @ Wo + bo
    gemm_tc<1><<<gE, 256, SMEM_SZ>>>(yhi, ylo, woh, wol, bo, x, x2, nullptr, nullptr, M_, E_, E_);
    // 5) h2 = LN2(x2) -> bf16 splits (reuse h buffers)
    ln_split_kernel<<<M_, 256>>>(x2, ln2w, hhi, hlo);
    // 6) ff = relu(h2 @ W1 + b1) -> bf16 splits
    gemm_tc<2><<<g4E, 256, SMEM_SZ>>>(hhi, hlo, w1h, w1l, b1, nullptr, nullptr, ffhi, fflo, M_, FF_, E_);
    // 7) out = x2 + ff @ W2 + b2
    gemm_tc<1><<<gE, 256, SMEM_SZ>>>(ffhi, fflo, w2h, w2l, b2, x2, out, nullptr, nullptr, M_, E_, FF_);
}

// round 6
// speedup vs baseline: 2.1842x; 1.4275x over previous
#include <cuda_runtime.h>
#include <cuda_bf16.h>
#include <cstdint>

#define B_  4
#define T_  2048
#define E_  1024
#define H_  16
#define HS_ 64
#define M_  (B_*T_)    // 8192
#define FF_ (4*E_)     // 4096

typedef unsigned long long u64;
typedef __nv_bfloat16 bf16;

// ======================= scratch pool (__device__ global) =======================
#define SZ_HB   ((size_t)M_*E_*2)      // bf16 [M,E]
#define SZ_F32  ((size_t)M_*E_*4)      // f32  [M,E]
#define SZ_FFB  ((size_t)M_*FF_*2)     // bf16 [M,4E]
#define SZ_WB   ((size_t)E_*E_*2)      // bf16 [E,E]
#define SZ_W1B  ((size_t)E_*FF_*2)     // bf16

constexpr size_t O_HHI  = 0;
constexpr size_t O_HLO  = O_HHI  + SZ_HB;
constexpr size_t O_QHI  = O_HLO  + SZ_HB;   // repurposed f32 q/k/v area -> 6 bf16 bufs
constexpr size_t O_QLO  = O_QHI  + SZ_HB;
constexpr size_t O_KHI  = O_QLO  + SZ_HB;
constexpr size_t O_KLO  = O_KHI  + SZ_HB;
constexpr size_t O_VHI  = O_KLO  + SZ_HB;
constexpr size_t O_VLO  = O_VHI  + SZ_HB;
constexpr size_t O_YHI  = O_VLO  + SZ_HB;
constexpr size_t O_YLO  = O_YHI  + SZ_HB;
constexpr size_t O_X2   = O_YLO  + SZ_HB;
constexpr size_t O_FFHI = O_X2   + SZ_F32;
constexpr size_t O_FFLO = O_FFHI + SZ_FFB;
constexpr size_t O_WQH  = O_FFLO + SZ_FFB;
constexpr size_t O_WQL  = O_WQH  + SZ_WB;
constexpr size_t O_WKH  = O_WQL  + SZ_WB;
constexpr size_t O_WKL  = O_WKH  + SZ_WB;
constexpr size_t O_WVH  = O_WKL  + SZ_WB;
constexpr size_t O_WVL  = O_WVH  + SZ_WB;
constexpr size_t O_WOH  = O_WVL  + SZ_WB;
constexpr size_t O_WOL  = O_WOH  + SZ_WB;
constexpr size_t O_W1H  = O_WOL  + SZ_WB;
constexpr size_t O_W1L  = O_W1H  + SZ_W1B;
constexpr size_t O_W2H  = O_W1L  + SZ_W1B;
constexpr size_t O_W2L  = O_W2H  + SZ_W1B;
constexpr size_t POOLSZ = O_W2L  + SZ_W1B;

__device__ __align__(1024) unsigned char g_pool[POOLSZ];

// ======================= PTX helpers =======================
__device__ __forceinline__ uint32_t s2u(const void* p){
    uint32_t a;
    asm("{ .reg .u64 t; cvta.to.shared.u64 t, %1; cvt.u32.u64 %0, t; }" : "=r"(a) : "l"(p));
    return a;
}
__device__ __forceinline__ void cp16(uint32_t s, const void* g){
    asm volatile("cp.async.cg.shared.global [%0], [%1], 16;" :: "r"(s), "l"(g));
}
__device__ __forceinline__ void ldm4(uint32_t (&r)[4], uint32_t a){
    asm volatile("ldmatrix.sync.aligned.m8n8.x4.shared.b16 {%0,%1,%2,%3}, [%4];"
                 : "=r"(r[0]), "=r"(r[1]), "=r"(r[2]), "=r"(r[3]) : "r"(a));
}
__device__ __forceinline__ void ldm4t(uint32_t (&r)[4], uint32_t a){
    asm volatile("ldmatrix.sync.aligned.m8n8.x4.trans.shared.b16 {%0,%1,%2,%3}, [%4];"
                 : "=r"(r[0]), "=r"(r[1]), "=r"(r[2]), "=r"(r[3]) : "r"(a));
}
__device__ __forceinline__ void mma_bf16(float (&c)[4], const uint32_t* a, uint32_t b0, uint32_t b1){
    asm volatile(
        "mma.sync.aligned.m16n8k16.row.col.f32.bf16.bf16.f32 "
        "{%0,%1,%2,%3}, {%4,%5,%6,%7}, {%8,%9}, {%0,%1,%2,%3};"
        : "+f"(c[0]), "+f"(c[1]), "+f"(c[2]), "+f"(c[3])
        : "r"(a[0]), "r"(a[1]), "r"(a[2]), "r"(a[3]), "r"(b0), "r"(b1));
}
// pack two f32 -> bf16x2 reg: low half = lo_val, high half = hi_val
__device__ __forceinline__ uint32_t packbf(float lo_val, float hi_val){
    uint32_t r;
    asm("cvt.rn.bf16x2.f32 %0, %1, %2;" : "=r"(r) : "f"(hi_val), "f"(lo_val));
    return r;
}
__device__ __forceinline__ void split_bf16(float v, bf16 &hi, bf16 &lo){
    hi = __float2bfloat16(v);
    lo = __float2bfloat16(v - __bfloat162float(hi));
}

// ======================= LayerNorm -> bf16 hi/lo splits =======================
__global__ __launch_bounds__(256) void ln_split_kernel(
    const float* __restrict__ X, const float* __restrict__ w,
    bf16* __restrict__ Ohi, bf16* __restrict__ Olo)
{
    int row = blockIdx.x;
    int tid = threadIdx.x;
    const float* x = X + (size_t)row * E_;

    float4 v = *(const float4*)(x + tid * 4);
    float s  = v.x + v.y + v.z + v.w;
    float sq = v.x*v.x + v.y*v.y + v.z*v.z + v.w*v.w;

    #pragma unroll
    for (int o = 16; o; o >>= 1) {
        s  += __shfl_xor_sync(0xFFFFFFFFu, s,  o);
        sq += __shfl_xor_sync(0xFFFFFFFFu, sq, o);
    }
    __shared__ float ss[8], ssq[8], red[2];
    int wid = tid >> 5, lane = tid & 31;
    if (lane == 0) { ss[wid] = s; ssq[wid] = sq; }
    __syncthreads();
    if (tid == 0) {
        float a = 0.f, b = 0.f;
        #pragma unroll
        for (int i = 0; i < 8; i++) { a += ss[i]; b += ssq[i]; }
        float mean = a * (1.0f / E_);
        float var  = b * (1.0f / E_) - mean * mean;
        red[0] = mean;
        red[1] = rsqrtf(var + 1e-5f);
    }
    __syncthreads();
    float mean = red[0], rs = red[1];
    float4 wv = *(const float4*)(w + tid * 4);
    float o0 = (v.x - mean) * rs * wv.x;
    float o1 = (v.y - mean) * rs * wv.y;
    float o2 = (v.z - mean) * rs * wv.z;
    float o3 = (v.w - mean) * rs * wv.w;

    bf16 h0,h1,h2,h3,l0,l1,l2,l3;
    split_bf16(o0,h0,l0); split_bf16(o1,h1,l1);
    split_bf16(o2,h2,l2); split_bf16(o3,h3,l3);
    size_t off = (size_t)row * E_ + tid * 4;
    __nv_bfloat162 ph0; ph0.x=h0; ph0.y=h1;
    __nv_bfloat162 ph1; ph1.x=h2; ph1.y=h3;
    __nv_bfloat162 pl0; pl0.x=l0; pl0.y=l1;
    __nv_bfloat162 pl1; pl1.x=l2; pl1.y=l3;
    *(__nv_bfloat162*)(Ohi + off)     = ph0;
    *(__nv_bfloat162*)(Ohi + off + 2) = ph1;
    *(__nv_bfloat162*)(Olo + off)     = pl0;
    *(__nv_bfloat162*)(Olo + off + 2) = pl1;
}

// ======================= weight transpose + split: W[K,N] -> Wt_{hi,lo}[N,K] ======
__global__ __launch_bounds__(256) void wsplit_kernel(
    const float* __restrict__ W, bf16* __restrict__ Whi, bf16* __restrict__ Wlo,
    int K, int N)
{
    __shared__ float t[32][33];
    int n0 = blockIdx.x * 32, k0 = blockIdx.y * 32;
    int tx = threadIdx.x, ty0 = threadIdx.y;
    #pragma unroll
    for (int dy = 0; dy < 32; dy += 8) {
        int ty = ty0 + dy;
        t[ty][tx] = W[(size_t)(k0 + ty) * N + n0 + tx];
    }
    __syncthreads();
    #pragma unroll
    for (int dy = 0; dy < 32; dy += 8) {
        int ty = ty0 + dy;
        float v = t[tx][ty];
        bf16 hi, lo; split_bf16(v, hi, lo);
        size_t o = (size_t)(n0 + ty) * K + k0 + tx;
        Whi[o] = hi;
        Wlo[o] = lo;
    }
}

// ======================= HMMA GEMM (bf16 hi/lo split, fp32 accum) ============
// OP: 1 = acc+bias+res -> f32; 2 = relu(acc+bias) -> bf16 hi/lo; 3 = acc*scale -> bf16 hi/lo
#define BM 128
#define BN 128
#define BK 32
#define ROWB   80
#define MTILE  (128*ROWB)
#define BUFSZ  (4*MTILE)
#define SMEM_SZ (2*BUFSZ)

template<int OP>
__global__ __launch_bounds__(256, 1) void gemm_tc(
    const bf16* __restrict__ Ahi, const bf16* __restrict__ Alo,
    const bf16* __restrict__ Bhi, const bf16* __restrict__ Blo,
    const float* __restrict__ bias, const float* __restrict__ res,
    float* __restrict__ C, bf16* __restrict__ Chi, bf16* __restrict__ Clo,
    float scale, int M, int N, int K)
{
    extern __shared__ __align__(128) unsigned char smem[];
    uint32_t sb = s2u(smem);
    int tid = threadIdx.x;
    int lane = tid & 31, wid = tid >> 5;
    int warp_m = wid & 1, warp_n = wid >> 1;
    int bx = blockIdx.x * BN, by = blockIdx.y * BM;

    int ch0 = tid * 2;
    int r0l = ch0 >> 2,        c0l = ch0 & 3;
    int r1l = (ch0 + 1) >> 2,  c1l = (ch0 + 1) & 3;
    uint32_t so0 = (uint32_t)(r0l * ROWB + c0l * 16);
    uint32_t so1 = (uint32_t)(r1l * ROWB + c1l * 16);

    const bf16* gAhi = Ahi + (size_t)(by) * K;
    const bf16* gAlo = Alo + (size_t)(by) * K;
    const bf16* gBhi = Bhi + (size_t)(bx) * K;
    const bf16* gBlo = Blo + (size_t)(bx) * K;

    float acc[4][4][4];
    #pragma unroll
    for (int i = 0; i < 4; i++)
        #pragma unroll
        for (int j = 0; j < 4; j++)
            #pragma unroll
            for (int q = 0; q < 4; q++) acc[i][j][q] = 0.f;

    int nt = K / BK;

    auto issue_tile = [&](int t, int buf) {
        uint32_t base = sb + buf * BUFSZ;
        int k0 = t * BK;
        cp16(base + so0,           gAhi + (size_t)r0l * K + k0 + c0l * 8);
        cp16(base + so1,           gAhi + (size_t)r1l * K + k0 + c1l * 8);
        cp16(base + MTILE + so0,   gAlo + (size_t)r0l * K + k0 + c0l * 8);
        cp16(base + MTILE + so1,   gAlo + (size_t)r1l * K + k0 + c1l * 8);
        cp16(base + 2*MTILE + so0, gBhi + (size_t)r0l * K + k0 + c0l * 8);
        cp16(base + 2*MTILE + so1, gBhi + (size_t)r1l * K + k0 + c1l * 8);
        cp16(base + 3*MTILE + so0, gBlo + (size_t)r0l * K + k0 + c0l * 8);
        cp16(base + 3*MTILE + so1, gBlo + (size_t)r1l * K + k0 + c1l * 8);
        asm volatile("cp.async.commit_group;" ::: "memory");
    };

    issue_tile(0, 0);

    uint32_t a_row = (uint32_t)(warp_m * 64 + (lane & 15));
    uint32_t a_cb  = (uint32_t)((lane >> 4) * 16);
    uint32_t b_row = (uint32_t)(warp_n * 32 + (lane & 7) + ((lane >> 4) & 1) * 8);
    uint32_t b_cb  = (uint32_t)(((lane >> 3) & 1) * 16);

    for (int t = 0; t < nt; t++) {
        int buf = t & 1;
        if (t + 1 < nt) {
            issue_tile(t + 1, buf ^ 1);
            asm volatile("cp.async.wait_group 1;" ::: "memory");
        } else {
            asm volatile("cp.async.wait_group 0;" ::: "memory");
        }
        __syncthreads();

        uint32_t base  = sb + buf * BUFSZ;
        uint32_t sAhi = base;
        uint32_t sAlo = base + MTILE;
        uint32_t sBhi = base + 2*MTILE;
        uint32_t sBlo = base + 3*MTILE;

        #pragma unroll
        for (int s = 0; s < 2; s++) {
            uint32_t kb = (uint32_t)(s * 32);
            uint32_t ahi[4][4], alo[4][4], bhi[2][4], blo[2][4];
            #pragma unroll
            for (int mt = 0; mt < 4; mt++) {
                uint32_t ao = (a_row + mt * 16) * ROWB + kb + a_cb;
                ldm4(ahi[mt], sAhi + ao);
                ldm4(alo[mt], sAlo + ao);
            }
            #pragma unroll
            for (int ntp = 0; ntp < 2; ntp++) {
                uint32_t bo = (b_row + ntp * 16) * ROWB + kb + b_cb;
                ldm4(bhi[ntp], sBhi + bo);
                ldm4(blo[ntp], sBlo + bo);
            }
            // pass-outer ordering: 16 independent acc chains per pass
            #pragma unroll
            for (int mt = 0; mt < 4; mt++)
                #pragma unroll
                for (int ntp = 0; ntp < 2; ntp++)
                    #pragma unroll
                    for (int hf = 0; hf < 2; hf++)
                        mma_bf16(acc[mt][ntp*2+hf], ahi[mt], bhi[ntp][hf*2], bhi[ntp][hf*2+1]);
            #pragma unroll
            for (int mt = 0; mt < 4; mt++)
                #pragma unroll
                for (int ntp = 0; ntp < 2; ntp++)
                    #pragma unroll
                    for (int hf = 0; hf < 2; hf++)
                        mma_bf16(acc[mt][ntp*2+hf], ahi[mt], blo[ntp][hf*2], blo[ntp][hf*2+1]);
            #pragma unroll
            for (int mt = 0; mt < 4; mt++)
                #pragma unroll
                for (int ntp = 0; ntp < 2; ntp++)
                    #pragma unroll
                    for (int hf = 0; hf < 2; hf++)
                        mma_bf16(acc[mt][ntp*2+hf], alo[mt], bhi[ntp][hf*2], bhi[ntp][hf*2+1]);
        }
        __syncthreads();
    }

    // -------- epilogue --------
    int er = by + warp_m * 64 + (lane >> 2);
    int ec = bx + warp_n * 32 + (lane & 3) * 2;
    #pragma unroll
    for (int mt = 0; mt < 4; mt++) {
        #pragma unroll
        for (int half = 0; half < 2; half++) {
            int row = er + mt * 16 + half * 8;
            #pragma unroll
            for (int ntj = 0; ntj < 4; ntj++) {
                int col = ec + ntj * 8;
                float v0 = acc[mt][ntj][half*2];
                float v1 = acc[mt][ntj][half*2+1];
                if (OP == 1) {
                    float2 rv = *(const float2*)&res[(size_t)row * N + col];
                    float2 bv = *(const float2*)&bias[col];
                    *(float2*)&C[(size_t)row * N + col] =
                        make_float2(v0 + bv.x + rv.x, v1 + bv.y + rv.y);
                } else if (OP == 2) {
                    float2 bv = *(const float2*)&bias[col];
                    float w0 = fmaxf(v0 + bv.x, 0.0f);
                    float w1 = fmaxf(v1 + bv.y, 0.0f);
                    bf16 h0,l0,h1,l1;
                    split_bf16(w0, h0, l0);
                    split_bf16(w1, h1, l1);
                    __nv_bfloat162 hh; hh.x = h0; hh.y = h1;
                    __nv_bfloat162 ll; ll.x = l0; ll.y = l1;
                    *(__nv_bfloat162*)&Chi[(size_t)row * N + col] = hh;
                    *(__nv_bfloat162*)&Clo[(size_t)row * N + col] = ll;
                } else {
                    float w0 = v0 * scale;
                    float w1 = v1 * scale;
                    bf16 h0,l0,h1,l1;
                    split_bf16(w0, h0, l0);
                    split_bf16(w1, h1, l1);
                    __nv_bfloat162 hh; hh.x = h0; hh.y = h1;
                    __nv_bfloat162 ll; ll.x = l0; ll.y = l1;
                    *(__nv_bfloat162*)&Chi[(size_t)row * N + col] = hh;
                    *(__nv_bfloat162*)&Clo[(size_t)row * N + col] = ll;
                }
            }
        }
    }
}

// ======================= Tensor-core causal flash attention ====================
// grid (16, 64): blockIdx.x = q-tile (128 rows), blockIdx.y = b*16+h.
// 256 threads = 8 warps; warp w owns q-rows [w*16, w*16+16).
// Q pre-scaled by 1/32. All matmuls 3-pass bf16 hi/lo, fp32 accum.
#define AROWB 144                    // 64 bf16 = 128B + 16B pad
#define ATILE (128*AROWB)            // 18432
#define ASM_QHI 0
#define ASM_QLO ATILE
#define ASM_KV  (2*ATILE)
#define AKV_KHI 0
#define AKV_KLO ATILE
#define AKV_VHI (2*ATILE)
#define AKV_VLO (3*ATILE)
#define AKVSTAGE (4*ATILE)
#define ASMEM (2*ATILE + 2*AKVSTAGE) // 184320

__global__ __launch_bounds__(256, 1) void attn_tc(
    const bf16* __restrict__ Qhi, const bf16* __restrict__ Qlo,
    const bf16* __restrict__ Khi, const bf16* __restrict__ Klo,
    const bf16* __restrict__ Vhi, const bf16* __restrict__ Vlo,
    bf16* __restrict__ Yhi, bf16* __restrict__ Ylo)
{
    extern __shared__ __align__(128) unsigned char asmem[];
    uint32_t sb = s2u(asmem);
    int tid = threadIdx.x, lane = tid & 31, wid = tid >> 5;
    int qt = blockIdx.x, bh = blockIdx.y;
    int b = bh >> 4, h = bh & 15;

    size_t rowbase = (size_t)b * T_;
    size_t qoff = (rowbase + qt * 128) * E_ + h * HS_;

    // loader indexing: 128 rows x 8 chunks(16B) per matrix; 4 chunks/thread
    int chb = tid * 4;
    int lrow[4], lch[4];
    uint32_t soff[4];
    #pragma unroll
    for (int i = 0; i < 4; i++) {
        lrow[i] = (chb + i) >> 3;
        lch[i]  = (chb + i) & 7;
        soff[i] = (uint32_t)(lrow[i] * AROWB + lch[i] * 16);
    }

    // stage Q (group 0)
    #pragma unroll
    for (int i = 0; i < 4; i++) {
        size_t g = qoff + (size_t)lrow[i] * E_ + lch[i] * 8;
        cp16(sb + ASM_QHI + soff[i], Qhi + g);
        cp16(sb + ASM_QLO + soff[i], Qlo + g);
    }
    asm volatile("cp.async.commit_group;" ::: "memory");

    auto load_kv = [&](int kt, int buf) {
        size_t ko = (rowbase + kt * 128) * E_ + h * HS_;
        uint32_t base = sb + ASM_KV + buf * AKVSTAGE;
        #pragma unroll
        for (int i = 0; i < 4; i++) {
            size_t g = ko + (size_t)lrow[i] * E_ + lch[i] * 8;
            cp16(base + AKV_KHI + soff[i], Khi + g);
            cp16(base + AKV_KLO + soff[i], Klo + g);
            cp16(base + AKV_VHI + soff[i], Vhi + g);
            cp16(base + AKV_VLO + soff[i], Vlo + g);
        }
        asm volatile("cp.async.commit_group;" ::: "memory");
    };
    load_kv(0, 0);

    asm volatile("cp.async.wait_group 1;" ::: "memory");   // Q done
    __syncthreads();

    // Q A-fragments (4 k16-steps over d=64), hi & lo
    uint32_t a_row = (uint32_t)(wid * 16 + (lane & 15));
    uint32_t a_cb  = (uint32_t)((lane >> 4) * 16);
    uint32_t qfh[4][4], qfl[4][4];
    #pragma unroll
    for (int s = 0; s < 4; s++) {
        uint32_t ao = a_row * AROWB + s * 32 + a_cb;
        ldm4(qfh[s], sb + ASM_QHI + ao);
        ldm4(qfl[s], sb + ASM_QLO + ao);
    }

    float oacc[8][4];
    #pragma unroll
    for (int i = 0; i < 8; i++)
        #pragma unroll
        for (int j = 0; j < 4; j++) oacc[i][j] = 0.f;
    float m0 = -1e30f, m1 = -1e30f, l0 = 0.f, l1 = 0.f;

    uint32_t b_rowo = (uint32_t)((lane & 7) + ((lane >> 4) & 1) * 8);
    uint32_t b_cbo  = (uint32_t)(((lane >> 3) & 1) * 16);
    uint32_t v_rowo = (uint32_t)(lane & 15);
    uint32_t v_cbo  = (uint32_t)(((lane >> 4) & 1) * 16);

    for (int kt = 0; kt <= qt; kt++) {
        int buf = kt & 1;
        if (kt < qt) {
            load_kv(kt + 1, buf ^ 1);
            asm volatile("cp.async.wait_group 1;" ::: "memory");
        } else {
            asm volatile("cp.async.wait_group 0;" ::: "memory");
        }
        __syncthreads();
        uint32_t kb = sb + ASM_KV + buf * AKVSTAGE;

        // ---- S = Q K^T (16 q-rows x 128 keys per warp) ----
        float sacc[16][4];
        #pragma unroll
        for (int j = 0; j < 16; j++)
            #pragma unroll
            for (int q = 0; q < 4; q++) sacc[j][q] = 0.f;

        #pragma unroll
        for (int g = 0; g < 2; g++) {
            #pragma unroll
            for (int s = 0; s < 4; s++) {
                uint32_t kfh[4][4], kfl[4][4];
                #pragma unroll
                for (int np = 0; np < 4; np++) {
                    uint32_t bo = (uint32_t)(g * 64 + np * 16 + b_rowo) * AROWB + s * 32 + b_cbo;
                    ldm4(kfh[np], kb + AKV_KHI + bo);
                    ldm4(kfl[np], kb + AKV_KLO + bo);
                }
                #pragma unroll
                for (int np = 0; np < 4; np++)
                    #pragma unroll
                    for (int hf = 0; hf < 2; hf++)
                        mma_bf16(sacc[g*8+np*2+hf], qfh[s], kfh[np][hf*2], kfh[np][hf*2+1]);
                #pragma unroll
                for (int np = 0; np < 4; np++)
                    #pragma unroll
                    for (int hf = 0; hf < 2; hf++)
                        mma_bf16(sacc[g*8+np*2+hf], qfh[s], kfl[np][hf*2], kfl[np][hf*2+1]);
                #pragma unroll
                for (int np = 0; np < 4; np++)
                    #pragma unroll
                    for (int hf = 0; hf < 2; hf++)
                        mma_bf16(sacc[g*8+np*2+hf], qfl[s], kfh[np][hf*2], kfh[np][hf*2+1]);
            }
        }

        // ---- causal mask (diagonal tile only) ----
        if (kt == qt) {
            int qr0 = wid * 16 + (lane >> 2);
            int kc  = (lane & 3) * 2;
            #pragma unroll
            for (int j = 0; j < 16; j++) {
                int k0i = j * 8 + kc;
                if (k0i     > qr0)     sacc[j][0] = -1e30f;
                if (k0i + 1 > qr0)     sacc[j][1] = -1e30f;
                if (k0i     > qr0 + 8) sacc[j][2] = -1e30f;
                if (k0i + 1 > qr0 + 8) sacc[j][3] = -1e30f;
            }
        }

        // ---- online softmax ----
        float mx0 = m0, mx1 = m1;
        #pragma unroll
        for (int j = 0; j < 16; j++) {
            mx0 = fmaxf(mx0, fmaxf(sacc[j][0], sacc[j][1]));
            mx1 = fmaxf(mx1, fmaxf(sacc[j][2], sacc[j][3]));
        }
        mx0 = fmaxf(mx0, __shfl_xor_sync(0xFFFFFFFFu, mx0, 1));
        mx0 = fmaxf(mx0, __shfl_xor_sync(0xFFFFFFFFu, mx0, 2));
        mx1 = fmaxf(mx1, __shfl_xor_sync(0xFFFFFFFFu, mx1, 1));
        mx1 = fmaxf(mx1, __shfl_xor_sync(0xFFFFFFFFu, mx1, 2));
        float cor0 = __expf(m0 - mx0);
        float cor1 = __expf(m1 - mx1);
        m0 = mx0; m1 = mx1;
        float rs0 = 0.f, rs1 = 0.f;
        #pragma unroll
        for (int j = 0; j < 16; j++) {
            float p0 = __expf(sacc[j][0] - m0);
            float p1 = __expf(sacc[j][1] - m0);
            float p2 = __expf(sacc[j][2] - m1);
            float p3 = __expf(sacc[j][3] - m1);
            sacc[j][0] = p0; sacc[j][1] = p1; sacc[j][2] = p2; sacc[j][3] = p3;
            rs0 += p0 + p1; rs1 += p2 + p3;
        }
        rs0 += __shfl_xor_sync(0xFFFFFFFFu, rs0, 1);
        rs0 += __shfl_xor_sync(0xFFFFFFFFu, rs0, 2);
        rs1 += __shfl_xor_sync(0xFFFFFFFFu, rs1, 1);
        rs1 += __shfl_xor_sync(0xFFFFFFFFu, rs1, 2);
        l0 = l0 * cor0 + rs0;
        l1 = l1 * cor1 + rs1;
        #pragma unroll
        for (int dt = 0; dt < 8; dt++) {
            oacc[dt][0] *= cor0; oacc[dt][1] *= cor0;
            oacc[dt][2] *= cor1; oacc[dt][3] *= cor1;
        }

        // ---- O += P V  (P from registers: C-frag -> A-frag) ----
        #pragma unroll
        for (int s = 0; s < 8; s++) {
            // P fragments (k16 = keys 16s..16s+15 from S tiles 2s, 2s+1)
            uint32_t pah[4], pal[4];
            #pragma unroll
            for (int tt = 0; tt < 2; tt++) {
                const float* sc = sacc[2*s + tt];
                float h0f = __bfloat162float(__float2bfloat16(sc[0]));
                float h1f = __bfloat162float(__float2bfloat16(sc[1]));
                float h2f = __bfloat162float(__float2bfloat16(sc[2]));
                float h3f = __bfloat162float(__float2bfloat16(sc[3]));
                pah[tt*2+0] = packbf(sc[0], sc[1]);
                pah[tt*2+1] = packbf(sc[2], sc[3]);
                pal[tt*2+0] = packbf(sc[0]-h0f, sc[1]-h1f);
                pal[tt*2+1] = packbf(sc[2]-h2f, sc[3]-h3f);
            }
            // reorder to A-frag register order: a0=(r0,klo) a1=(r1,klo) a2=(r0,khi) a3=(r1,khi)
            // pah currently: [0]=(r0,tile2s) [1]=(r1,tile2s) [2]=(r0,tile2s+1) [3]=(r1,tile2s+1)
            // tile2s = k0-7, tile2s+1 = k8-15 -> already matches a0..a3 order.

            uint32_t vfh[4][4], vfl[4][4];
            #pragma unroll
            for (int dc = 0; dc < 4; dc++) {
                uint32_t vo = (uint32_t)(s * 16 + v_rowo) * AROWB + dc * 32 + v_cbo;
                ldm4t(vfh[dc], kb + AKV_VHI + vo);
                ldm4t(vfl[dc], kb + AKV_VLO + vo);
            }
            #pragma unroll
            for (int dc = 0; dc < 4; dc++) {
                mma_bf16(oacc[dc*2+0], pah, vfh[dc][0], vfh[dc][1]);
                mma_bf16(oacc[dc*2+1], pah, vfh[dc][2], vfh[dc][3]);
            }
            #pragma unroll
            for (int dc = 0; dc < 4; dc++) {
                mma_bf16(oacc[dc*2+0], pah, vfl[dc][0], vfl[dc][1]);
                mma_bf16(oacc[dc*2+1], pah, vfl[dc][2], vfl[dc][3]);
            }
            #pragma unroll
            for (int dc = 0; dc < 4; dc++) {
                mma_bf16(oacc[dc*2+0], pal, vfh[dc][0], vfh[dc][1]);
                mma_bf16(oacc[dc*2+1], pal, vfh[dc][2], vfh[dc][3]);
            }
        }
        __syncthreads();   // protect smem buffer before next prefetch overwrites
    }

    // ---- epilogue: y = O / l, write bf16 hi/lo ----
    float inv0 = 1.0f / l0;
    float inv1 = 1.0f / l1;
    int qr = qt * 128 + wid * 16 + (lane >> 2);
    size_t y0 = (rowbase + qr) * E_ + h * HS_ + (lane & 3) * 2;
    size_t y1 = y0 + (size_t)8 * E_;
    #pragma unroll
    for (int dt = 0; dt < 8; dt++) {
        float w0 = oacc[dt][0] * inv0, w1 = oacc[dt][1] * inv0;
        float w2 = oacc[dt][2] * inv1, w3 = oacc[dt][3] * inv1;
        bf16 h0,lo0,h1,lo1,h2,lo2,h3,lo3;
        split_bf16(w0,h0,lo0); split_bf16(w1,h1,lo1);
        split_bf16(w2,h2,lo2); split_bf16(w3,h3,lo3);
        __nv_bfloat162 hh0; hh0.x=h0; hh0.y=h1;
        __nv_bfloat162 ll0; ll0.x=lo0; ll0.y=lo1;
        __nv_bfloat162 hh1; hh1.x=h2; hh1.y=h3;
        __nv_bfloat162 ll1; ll1.x=lo2; ll1.y=lo3;
        *(__nv_bfloat162*)(Yhi + y0 + dt*8) = hh0;
        *(__nv_bfloat162*)(Ylo + y0 + dt*8) = ll0;
        *(__nv_bfloat162*)(Yhi + y1 + dt*8) = hh1;
        *(__nv_bfloat162*)(Ylo + y1 + dt*8) = ll1;
    }
}

// ======================= launch =======================
extern "C" void kernel_launch(void* const* d_in, const int* in_sizes, int n_in,
                              void* d_out, int out_size)
{
    const float* x    = (const float*)d_in[0];
    const float* Wq   = (const float*)d_in[1];
    const float* Wk   = (const float*)d_in[2];
    const float* Wv   = (const float*)d_in[3];
    const float* Wo   = (const float*)d_in[4];
    const float* bo   = (const float*)d_in[5];
    const float* ln1w = (const float*)d_in[6];
    const float* ln2w = (const float*)d_in[7];
    const float* W1   = (const float*)d_in[8];
    const float* b1   = (const float*)d_in[9];
    const float* W2   = (const float*)d_in[10];
    const float* b2   = (const float*)d_in[11];
    float* out = (float*)d_out;

    unsigned char* pool;
    cudaGetSymbolAddress((void**)&pool, g_pool);

    bf16*  hhi  = (bf16*)(pool + O_HHI);
    bf16*  hlo  = (bf16*)(pool + O_HLO);
    bf16*  qhi  = (bf16*)(pool + O_QHI), *qlo = (bf16*)(pool + O_QLO);
    bf16*  khi  = (bf16*)(pool + O_KHI), *klo = (bf16*)(pool + O_KLO);
    bf16*  vhi  = (bf16*)(pool + O_VHI), *vlo = (bf16*)(pool + O_VLO);
    bf16*  yhi  = (bf16*)(pool + O_YHI), *ylo = (bf16*)(pool + O_YLO);
    float* x2   = (float*)(pool + O_X2);
    bf16*  ffhi = (bf16*)(pool + O_FFHI);
    bf16*  fflo = (bf16*)(pool + O_FFLO);
    bf16*  wqh = (bf16*)(pool + O_WQH), *wql = (bf16*)(pool + O_WQL);
    bf16*  wkh = (bf16*)(pool + O_WKH), *wkl = (bf16*)(pool + O_WKL);
    bf16*  wvh = (bf16*)(pool + O_WVH), *wvl = (bf16*)(pool + O_WVL);
    bf16*  woh = (bf16*)(pool + O_WOH), *wol = (bf16*)(pool + O_WOL);
    bf16*  w1h = (bf16*)(pool + O_W1H), *w1l = (bf16*)(pool + O_W1L);
    bf16*  w2h = (bf16*)(pool + O_W2H), *w2l = (bf16*)(pool + O_W2L);

    cudaFuncSetAttribute(gemm_tc<1>, cudaFuncAttributeMaxDynamicSharedMemorySize, SMEM_SZ);
    cudaFuncSetAttribute(gemm_tc<2>, cudaFuncAttributeMaxDynamicSharedMemorySize, SMEM_SZ);
    cudaFuncSetAttribute(gemm_tc<3>, cudaFuncAttributeMaxDynamicSharedMemorySize, SMEM_SZ);
    cudaFuncSetAttribute(attn_tc,    cudaFuncAttributeMaxDynamicSharedMemorySize, ASMEM);

    dim3 tb(32, 8);
    wsplit_kernel<<<dim3(E_/32,  E_/32),  tb>>>(Wq, wqh, wql, E_,  E_);
    wsplit_kernel<<<dim3(E_/32,  E_/32),  tb>>>(Wk, wkh, wkl, E_,  E_);
    wsplit_kernel<<<dim3(E_/32,  E_/32),  tb>>>(Wv, wvh, wvl, E_,  E_);
    wsplit_kernel<<<dim3(E_/32,  E_/32),  tb>>>(Wo, woh, wol, E_,  E_);
    wsplit_kernel<<<dim3(FF_/32, E_/32),  tb>>>(W1, w1h, w1l, E_,  FF_);
    wsplit_kernel<<<dim3(E_/32,  FF_/32), tb>>>(W2, w2h, w2l, FF_, E_);

    dim3 gE (E_  / BN, M_ / BM);
    dim3 g4E(FF_ / BN, M_ / BM);

    // 1) h = LN1(x)
    ln_split_kernel<<<M_, 256>>>(x, ln1w, hhi, hlo);
    // 2) q,k,v projections -> bf16 hi/lo (q pre-scaled by 1/32 = E^-0.5)
    gemm_tc<3><<<gE, 256, SMEM_SZ>>>(hhi, hlo, wqh, wql, nullptr, nullptr, nullptr, qhi, qlo, 0.03125f, M_, E_, E_);
    gemm_tc<3><<<gE, 256, SMEM_SZ>>>(hhi, hlo, wkh, wkl, nullptr, nullptr, nullptr, khi, klo, 1.0f,     M_, E_, E_);
    gemm_tc<3><<<gE, 256, SMEM_SZ>>>(hhi, hlo, wvh, wvl, nullptr, nullptr, nullptr, vhi, vlo, 1.0f,     M_, E_, E_);
    // 3) y = causal attention (tensor cores)
    attn_tc<<<dim3(T_/128, B_*H_), 256, ASMEM>>>(qhi, qlo, khi, klo, vhi, vlo, yhi, ylo);
    // 4) x2 = x + y @ Wo + bo
    gemm_tc<1><<<gE, 256, SMEM_SZ>>>(yhi, ylo, woh, wol, bo, x, x2, nullptr, nullptr, 1.0f, M_, E_, E_);
    // 5) h2 = LN2(x2)
    ln_split_kernel<<<M_, 256>>>(x2, ln2w, hhi, hlo);
    // 6) ff = relu(h2 @ W1 + b1)
    gemm_tc<2><<<g4E, 256, SMEM_SZ>>>(hhi, hlo, w1h, w1l, b1, nullptr, nullptr, ffhi, fflo, 1.0f, M_, FF_, E_);
    // 7) out = x2 + ff @ W2 + b2
    gemm_tc<1><<<gE, 256, SMEM_SZ>>>(ffhi, fflo, w2h, w2l, b2, x2, out, nullptr, nullptr, 1.0f, M_, E_, FF_);
}

// round 7
// speedup vs baseline: 2.2104x; 1.0120x over previous
#include <cuda_runtime.h>
#include <cuda_bf16.h>
#include <cstdint>

#define B_  4
#define T_  2048
#define E_  1024
#define H_  16
#define HS_ 64
#define M_  (B_*T_)    // 8192
#define FF_ (4*E_)     // 4096

typedef unsigned long long u64;
typedef __nv_bfloat16 bf16;

// ======================= scratch pool (__device__ global) =======================
#define SZ_HB   ((size_t)M_*E_*2)
#define SZ_F32  ((size_t)M_*E_*4)
#define SZ_FFB  ((size_t)M_*FF_*2)
#define SZ_WB   ((size_t)E_*E_*2)
#define SZ_W1B  ((size_t)E_*FF_*2)

constexpr size_t O_HHI  = 0;
constexpr size_t O_HLO  = O_HHI  + SZ_HB;
constexpr size_t O_QHI  = O_HLO  + SZ_HB;
constexpr size_t O_QLO  = O_QHI  + SZ_HB;
constexpr size_t O_KHI  = O_QLO  + SZ_HB;
constexpr size_t O_KLO  = O_KHI  + SZ_HB;
constexpr size_t O_VHI  = O_KLO  + SZ_HB;
constexpr size_t O_VLO  = O_VHI  + SZ_HB;
constexpr size_t O_YHI  = O_VLO  + SZ_HB;
constexpr size_t O_YLO  = O_YHI  + SZ_HB;
constexpr size_t O_X2   = O_YLO  + SZ_HB;
constexpr size_t O_FFHI = O_X2   + SZ_F32;
constexpr size_t O_FFLO = O_FFHI + SZ_FFB;
constexpr size_t O_WQH  = O_FFLO + SZ_FFB;
constexpr size_t O_WQL  = O_WQH  + SZ_WB;
constexpr size_t O_WKH  = O_WQL  + SZ_WB;
constexpr size_t O_WKL  = O_WKH  + SZ_WB;
constexpr size_t O_WVH  = O_WKL  + SZ_WB;
constexpr size_t O_WVL  = O_WVH  + SZ_WB;
constexpr size_t O_WOH  = O_WVL  + SZ_WB;
constexpr size_t O_WOL  = O_WOH  + SZ_WB;
constexpr size_t O_W1H  = O_WOL  + SZ_WB;
constexpr size_t O_W1L  = O_W1H  + SZ_W1B;
constexpr size_t O_W2H  = O_W1L  + SZ_W1B;
constexpr size_t O_W2L  = O_W2H  + SZ_W1B;
constexpr size_t POOLSZ = O_W2L  + SZ_W1B;

__device__ __align__(1024) unsigned char g_pool[POOLSZ];

// ======================= PTX helpers =======================
__device__ __forceinline__ uint32_t s2u(const void* p){
    uint32_t a;
    asm("{ .reg .u64 t; cvta.to.shared.u64 t, %1; cvt.u32.u64 %0, t; }" : "=r"(a) : "l"(p));
    return a;
}
__device__ __forceinline__ void cp16(uint32_t s, const void* g){
    asm volatile("cp.async.cg.shared.global [%0], [%1], 16;" :: "r"(s), "l"(g));
}
__device__ __forceinline__ void ldm4(uint32_t (&r)[4], uint32_t a){
    asm volatile("ldmatrix.sync.aligned.m8n8.x4.shared.b16 {%0,%1,%2,%3}, [%4];"
                 : "=r"(r[0]), "=r"(r[1]), "=r"(r[2]), "=r"(r[3]) : "r"(a));
}
__device__ __forceinline__ void ldm4t(uint32_t (&r)[4], uint32_t a){
    asm volatile("ldmatrix.sync.aligned.m8n8.x4.trans.shared.b16 {%0,%1,%2,%3}, [%4];"
                 : "=r"(r[0]), "=r"(r[1]), "=r"(r[2]), "=r"(r[3]) : "r"(a));
}
__device__ __forceinline__ void mma_bf16(float (&c)[4], const uint32_t* a, uint32_t b0, uint32_t b1){
    asm volatile(
        "mma.sync.aligned.m16n8k16.row.col.f32.bf16.bf16.f32 "
        "{%0,%1,%2,%3}, {%4,%5,%6,%7}, {%8,%9}, {%0,%1,%2,%3};"
        : "+f"(c[0]), "+f"(c[1]), "+f"(c[2]), "+f"(c[3])
        : "r"(a[0]), "r"(a[1]), "r"(a[2]), "r"(a[3]), "r"(b0), "r"(b1));
}
__device__ __forceinline__ uint32_t packbf(float lo_val, float hi_val){
    uint32_t r;
    asm("cvt.rn.bf16x2.f32 %0, %1, %2;" : "=r"(r) : "f"(hi_val), "f"(lo_val));
    return r;
}
__device__ __forceinline__ void split_bf16(float v, bf16 &hi, bf16 &lo){
    hi = __float2bfloat16(v);
    lo = __float2bfloat16(v - __bfloat162float(hi));
}

// ======================= LayerNorm -> bf16 hi/lo splits =======================
__global__ __launch_bounds__(256) void ln_split_kernel(
    const float* __restrict__ X, const float* __restrict__ w,
    bf16* __restrict__ Ohi, bf16* __restrict__ Olo)
{
    int row = blockIdx.x;
    int tid = threadIdx.x;
    const float* x = X + (size_t)row * E_;

    float4 v = *(const float4*)(x + tid * 4);
    float s  = v.x + v.y + v.z + v.w;
    float sq = v.x*v.x + v.y*v.y + v.z*v.z + v.w*v.w;

    #pragma unroll
    for (int o = 16; o; o >>= 1) {
        s  += __shfl_xor_sync(0xFFFFFFFFu, s,  o);
        sq += __shfl_xor_sync(0xFFFFFFFFu, sq, o);
    }
    __shared__ float ss[8], ssq[8], red[2];
    int wid = tid >> 5, lane = tid & 31;
    if (lane == 0) { ss[wid] = s; ssq[wid] = sq; }
    __syncthreads();
    if (tid == 0) {
        float a = 0.f, b = 0.f;
        #pragma unroll
        for (int i = 0; i < 8; i++) { a += ss[i]; b += ssq[i]; }
        float mean = a * (1.0f / E_);
        float var  = b * (1.0f / E_) - mean * mean;
        red[0] = mean;
        red[1] = rsqrtf(var + 1e-5f);
    }
    __syncthreads();
    float mean = red[0], rs = red[1];
    float4 wv = *(const float4*)(w + tid * 4);
    float o0 = (v.x - mean) * rs * wv.x;
    float o1 = (v.y - mean) * rs * wv.y;
    float o2 = (v.z - mean) * rs * wv.z;
    float o3 = (v.w - mean) * rs * wv.w;

    bf16 h0,h1,h2,h3,l0,l1,l2,l3;
    split_bf16(o0,h0,l0); split_bf16(o1,h1,l1);
    split_bf16(o2,h2,l2); split_bf16(o3,h3,l3);
    size_t off = (size_t)row * E_ + tid * 4;
    __nv_bfloat162 ph0; ph0.x=h0; ph0.y=h1;
    __nv_bfloat162 ph1; ph1.x=h2; ph1.y=h3;
    __nv_bfloat162 pl0; pl0.x=l0; pl0.y=l1;
    __nv_bfloat162 pl1; pl1.x=l2; pl1.y=l3;
    *(__nv_bfloat162*)(Ohi + off)     = ph0;
    *(__nv_bfloat162*)(Ohi + off + 2) = ph1;
    *(__nv_bfloat162*)(Olo + off)     = pl0;
    *(__nv_bfloat162*)(Olo + off + 2) = pl1;
}

// ======================= weight transpose + split =======================
__global__ __launch_bounds__(256) void wsplit_kernel(
    const float* __restrict__ W, bf16* __restrict__ Whi, bf16* __restrict__ Wlo,
    int K, int N)
{
    __shared__ float t[32][33];
    int n0 = blockIdx.x * 32, k0 = blockIdx.y * 32;
    int tx = threadIdx.x, ty0 = threadIdx.y;
    #pragma unroll
    for (int dy = 0; dy < 32; dy += 8) {
        int ty = ty0 + dy;
        t[ty][tx] = W[(size_t)(k0 + ty) * N + n0 + tx];
    }
    __syncthreads();
    #pragma unroll
    for (int dy = 0; dy < 32; dy += 8) {
        int ty = ty0 + dy;
        float v = t[tx][ty];
        bf16 hi, lo; split_bf16(v, hi, lo);
        size_t o = (size_t)(n0 + ty) * K + k0 + tx;
        Whi[o] = hi;
        Wlo[o] = lo;
    }
}

// ======================= HMMA GEMM (bf16 hi/lo, fp32 accum), BK=64 ============
// OP: 1 = acc+bias+res -> f32; 2 = relu(acc+bias) -> bf16 hi/lo;
// OP: 3 = fused QKV: sel = blockIdx.x>>3 picks (B,C) set; q scaled by 1/32.
#define BM 128
#define BN 128
#define BK 64
#define ROWB   144
#define MTILE  (128*ROWB)     // 18432
#define BUFSZ  (4*MTILE)      // 73728
#define SMEM_SZ (2*BUFSZ)     // 147456

template<int OP>
__global__ __launch_bounds__(256, 1) void gemm_tc(
    const bf16* __restrict__ Ahi, const bf16* __restrict__ Alo,
    const bf16* __restrict__ B0h, const bf16* __restrict__ B0l,
    const bf16* __restrict__ B1h, const bf16* __restrict__ B1l,
    const bf16* __restrict__ B2h, const bf16* __restrict__ B2l,
    const float* __restrict__ bias, const float* __restrict__ res,
    float* __restrict__ C,
    bf16* __restrict__ C0h, bf16* __restrict__ C0l,
    bf16* __restrict__ C1h, bf16* __restrict__ C1l,
    bf16* __restrict__ C2h, bf16* __restrict__ C2l,
    int M, int N, int K)
{
    extern __shared__ __align__(128) unsigned char smem[];
    uint32_t sb = s2u(smem);
    int tid = threadIdx.x;
    int lane = tid & 31, wid = tid >> 5;
    int warp_m = wid & 1, warp_n = wid >> 1;

    int sel = 0, bxi = blockIdx.x;
    if (OP == 3) { sel = blockIdx.x >> 3; bxi = blockIdx.x & 7; }
    int bx = bxi * BN, by = blockIdx.y * BM;

    const bf16* Bhi = (OP == 3) ? (sel == 0 ? B0h : sel == 1 ? B1h : B2h) : B0h;
    const bf16* Blo = (OP == 3) ? (sel == 0 ? B0l : sel == 1 ? B1l : B2l) : B0l;
    bf16* Chi = (OP == 3) ? (sel == 0 ? C0h : sel == 1 ? C1h : C2h) : C0h;
    bf16* Clo = (OP == 3) ? (sel == 0 ? C0l : sel == 1 ? C1l : C2l) : C0l;
    float scale = (OP == 3 && sel == 0) ? 0.03125f : 1.0f;

    // loader: 128 rows x 8 chunks(16B) per matrix; 4 chunks per thread
    int chb = tid * 4;
    int lrow[4], lc16[4];
    uint32_t soff[4];
    #pragma unroll
    for (int i = 0; i < 4; i++) {
        lrow[i] = (chb + i) >> 3;
        lc16[i] = (chb + i) & 7;
        soff[i] = (uint32_t)(lrow[i] * ROWB + lc16[i] * 16);
    }

    const bf16* gAhi = Ahi + (size_t)(by) * K;
    const bf16* gAlo = Alo + (size_t)(by) * K;
    const bf16* gBhi = Bhi + (size_t)(bx) * K;
    const bf16* gBlo = Blo + (size_t)(bx) * K;

    float acc[4][4][4];
    #pragma unroll
    for (int i = 0; i < 4; i++)
        #pragma unroll
        for (int j = 0; j < 4; j++)
            #pragma unroll
            for (int q = 0; q < 4; q++) acc[i][j][q] = 0.f;

    int nt = K / BK;

    auto issue_tile = [&](int t, int buf) {
        uint32_t base = sb + buf * BUFSZ;
        int k0 = t * BK;
        #pragma unroll
        for (int i = 0; i < 4; i++) {
            size_t go = (size_t)lrow[i] * K + k0 + lc16[i] * 8;
            cp16(base + soff[i],           gAhi + go);
            cp16(base + MTILE + soff[i],   gAlo + go);
            cp16(base + 2*MTILE + soff[i], gBhi + go);
            cp16(base + 3*MTILE + soff[i], gBlo + go);
        }
        asm volatile("cp.async.commit_group;" ::: "memory");
    };

    issue_tile(0, 0);

    uint32_t a_row = (uint32_t)(warp_m * 64 + (lane & 15));
    uint32_t a_cb  = (uint32_t)((lane >> 4) * 16);
    uint32_t b_row = (uint32_t)(warp_n * 32 + (lane & 7) + ((lane >> 4) & 1) * 8);
    uint32_t b_cb  = (uint32_t)(((lane >> 3) & 1) * 16);

    for (int t = 0; t < nt; t++) {
        int buf = t & 1;
        if (t + 1 < nt) {
            issue_tile(t + 1, buf ^ 1);
            asm volatile("cp.async.wait_group 1;" ::: "memory");
        } else {
            asm volatile("cp.async.wait_group 0;" ::: "memory");
        }
        __syncthreads();

        uint32_t base  = sb + buf * BUFSZ;
        uint32_t sAhi = base;
        uint32_t sAlo = base + MTILE;
        uint32_t sBhi = base + 2*MTILE;
        uint32_t sBlo = base + 3*MTILE;

        #pragma unroll
        for (int s = 0; s < 4; s++) {               // four k16 steps in BK=64
            uint32_t kb = (uint32_t)(s * 32);
            uint32_t ahi[4][4], alo[4][4], bhi[2][4], blo[2][4];
            #pragma unroll
            for (int mt = 0; mt < 4; mt++) {
                uint32_t ao = (a_row + mt * 16) * ROWB + kb + a_cb;
                ldm4(ahi[mt], sAhi + ao);
                ldm4(alo[mt], sAlo + ao);
            }
            #pragma unroll
            for (int ntp = 0; ntp < 2; ntp++) {
                uint32_t bo = (b_row + ntp * 16) * ROWB + kb + b_cb;
                ldm4(bhi[ntp], sBhi + bo);
                ldm4(blo[ntp], sBlo + bo);
            }
            #pragma unroll
            for (int mt = 0; mt < 4; mt++)
                #pragma unroll
                for (int ntp = 0; ntp < 2; ntp++)
                    #pragma unroll
                    for (int hf = 0; hf < 2; hf++)
                        mma_bf16(acc[mt][ntp*2+hf], ahi[mt], bhi[ntp][hf*2], bhi[ntp][hf*2+1]);
            #pragma unroll
            for (int mt = 0; mt < 4; mt++)
                #pragma unroll
                for (int ntp = 0; ntp < 2; ntp++)
                    #pragma unroll
                    for (int hf = 0; hf < 2; hf++)
                        mma_bf16(acc[mt][ntp*2+hf], ahi[mt], blo[ntp][hf*2], blo[ntp][hf*2+1]);
            #pragma unroll
            for (int mt = 0; mt < 4; mt++)
                #pragma unroll
                for (int ntp = 0; ntp < 2; ntp++)
                    #pragma unroll
                    for (int hf = 0; hf < 2; hf++)
                        mma_bf16(acc[mt][ntp*2+hf], alo[mt], bhi[ntp][hf*2], bhi[ntp][hf*2+1]);
        }
        __syncthreads();
    }

    // -------- epilogue --------
    int er = by + warp_m * 64 + (lane >> 2);
    int ec = bx + warp_n * 32 + (lane & 3) * 2;
    #pragma unroll
    for (int mt = 0; mt < 4; mt++) {
        #pragma unroll
        for (int half = 0; half < 2; half++) {
            int row = er + mt * 16 + half * 8;
            #pragma unroll
            for (int ntj = 0; ntj < 4; ntj++) {
                int col = ec + ntj * 8;
                float v0 = acc[mt][ntj][half*2];
                float v1 = acc[mt][ntj][half*2+1];
                if (OP == 1) {
                    float2 rv = *(const float2*)&res[(size_t)row * N + col];
                    float2 bv = *(const float2*)&bias[col];
                    *(float2*)&C[(size_t)row * N + col] =
                        make_float2(v0 + bv.x + rv.x, v1 + bv.y + rv.y);
                } else {
                    float w0, w1;
                    if (OP == 2) {
                        float2 bv = *(const float2*)&bias[col];
                        w0 = fmaxf(v0 + bv.x, 0.0f);
                        w1 = fmaxf(v1 + bv.y, 0.0f);
                    } else {
                        w0 = v0 * scale;
                        w1 = v1 * scale;
                    }
                    bf16 h0,l0,h1,l1;
                    split_bf16(w0, h0, l0);
                    split_bf16(w1, h1, l1);
                    __nv_bfloat162 hh; hh.x = h0; hh.y = h1;
                    __nv_bfloat162 ll; ll.x = l0; ll.y = l1;
                    *(__nv_bfloat162*)&Chi[(size_t)row * N + col] = hh;
                    *(__nv_bfloat162*)&Clo[(size_t)row * N + col] = ll;
                }
            }
        }
    }
}

// ======================= Tensor-core causal flash attention ====================
#define AROWB 144
#define ATILE (128*AROWB)
#define ASM_QHI 0
#define ASM_QLO ATILE
#define ASM_KV  (2*ATILE)
#define AKV_KHI 0
#define AKV_KLO ATILE
#define AKV_VHI (2*ATILE)
#define AKV_VLO (3*ATILE)
#define AKVSTAGE (4*ATILE)
#define ASMEM (2*ATILE + 2*AKVSTAGE)

__global__ __launch_bounds__(256, 1) void attn_tc(
    const bf16* __restrict__ Qhi, const bf16* __restrict__ Qlo,
    const bf16* __restrict__ Khi, const bf16* __restrict__ Klo,
    const bf16* __restrict__ Vhi, const bf16* __restrict__ Vlo,
    bf16* __restrict__ Yhi, bf16* __restrict__ Ylo)
{
    extern __shared__ __align__(128) unsigned char asmem[];
    uint32_t sb = s2u(asmem);
    int tid = threadIdx.x, lane = tid & 31, wid = tid >> 5;
    int qt = blockIdx.x, bh = blockIdx.y;
    int b = bh >> 4, h = bh & 15;

    size_t rowbase = (size_t)b * T_;
    size_t qoff = (rowbase + qt * 128) * E_ + h * HS_;

    int chb = tid * 4;
    int lrow[4], lch[4];
    uint32_t soff[4];
    #pragma unroll
    for (int i = 0; i < 4; i++) {
        lrow[i] = (chb + i) >> 3;
        lch[i]  = (chb + i) & 7;
        soff[i] = (uint32_t)(lrow[i] * AROWB + lch[i] * 16);
    }

    #pragma unroll
    for (int i = 0; i < 4; i++) {
        size_t g = qoff + (size_t)lrow[i] * E_ + lch[i] * 8;
        cp16(sb + ASM_QHI + soff[i], Qhi + g);
        cp16(sb + ASM_QLO + soff[i], Qlo + g);
    }
    asm volatile("cp.async.commit_group;" ::: "memory");

    auto load_kv = [&](int kt, int buf) {
        size_t ko = (rowbase + kt * 128) * E_ + h * HS_;
        uint32_t base = sb + ASM_KV + buf * AKVSTAGE;
        #pragma unroll
        for (int i = 0; i < 4; i++) {
            size_t g = ko + (size_t)lrow[i] * E_ + lch[i] * 8;
            cp16(base + AKV_KHI + soff[i], Khi + g);
            cp16(base + AKV_KLO + soff[i], Klo + g);
            cp16(base + AKV_VHI + soff[i], Vhi + g);
            cp16(base + AKV_VLO + soff[i], Vlo + g);
        }
        asm volatile("cp.async.commit_group;" ::: "memory");
    };
    load_kv(0, 0);

    asm volatile("cp.async.wait_group 1;" ::: "memory");
    __syncthreads();

    uint32_t a_row = (uint32_t)(wid * 16 + (lane & 15));
    uint32_t a_cb  = (uint32_t)((lane >> 4) * 16);
    uint32_t qfh[4][4], qfl[4][4];
    #pragma unroll
    for (int s = 0; s < 4; s++) {
        uint32_t ao = a_row * AROWB + s * 32 + a_cb;
        ldm4(qfh[s], sb + ASM_QHI + ao);
        ldm4(qfl[s], sb + ASM_QLO + ao);
    }

    float oacc[8][4];
    #pragma unroll
    for (int i = 0; i < 8; i++)
        #pragma unroll
        for (int j = 0; j < 4; j++) oacc[i][j] = 0.f;
    float m0 = -1e30f, m1 = -1e30f, l0 = 0.f, l1 = 0.f;

    uint32_t b_rowo = (uint32_t)((lane & 7) + ((lane >> 4) & 1) * 8);
    uint32_t b_cbo  = (uint32_t)(((lane >> 3) & 1) * 16);
    uint32_t v_rowo = (uint32_t)(lane & 15);
    uint32_t v_cbo  = (uint32_t)(((lane >> 4) & 1) * 16);

    for (int kt = 0; kt <= qt; kt++) {
        int buf = kt & 1;
        if (kt < qt) {
            load_kv(kt + 1, buf ^ 1);
            asm volatile("cp.async.wait_group 1;" ::: "memory");
        } else {
            asm volatile("cp.async.wait_group 0;" ::: "memory");
        }
        __syncthreads();
        uint32_t kb = sb + ASM_KV + buf * AKVSTAGE;

        // ---- S = Q K^T (3-pass hi/lo) ----
        float sacc[16][4];
        #pragma unroll
        for (int j = 0; j < 16; j++)
            #pragma unroll
            for (int q = 0; q < 4; q++) sacc[j][q] = 0.f;

        #pragma unroll
        for (int g = 0; g < 2; g++) {
            #pragma unroll
            for (int s = 0; s < 4; s++) {
                uint32_t kfh[4][4], kfl[4][4];
                #pragma unroll
                for (int np = 0; np < 4; np++) {
                    uint32_t bo = (uint32_t)(g * 64 + np * 16 + b_rowo) * AROWB + s * 32 + b_cbo;
                    ldm4(kfh[np], kb + AKV_KHI + bo);
                    ldm4(kfl[np], kb + AKV_KLO + bo);
                }
                #pragma unroll
                for (int np = 0; np < 4; np++)
                    #pragma unroll
                    for (int hf = 0; hf < 2; hf++)
                        mma_bf16(sacc[g*8+np*2+hf], qfh[s], kfh[np][hf*2], kfh[np][hf*2+1]);
                #pragma unroll
                for (int np = 0; np < 4; np++)
                    #pragma unroll
                    for (int hf = 0; hf < 2; hf++)
                        mma_bf16(sacc[g*8+np*2+hf], qfh[s], kfl[np][hf*2], kfl[np][hf*2+1]);
                #pragma unroll
                for (int np = 0; np < 4; np++)
                    #pragma unroll
                    for (int hf = 0; hf < 2; hf++)
                        mma_bf16(sacc[g*8+np*2+hf], qfl[s], kfh[np][hf*2], kfh[np][hf*2+1]);
            }
        }

        if (kt == qt) {
            int qr0 = wid * 16 + (lane >> 2);
            int kc  = (lane & 3) * 2;
            #pragma unroll
            for (int j = 0; j < 16; j++) {
                int k0i = j * 8 + kc;
                if (k0i     > qr0)     sacc[j][0] = -1e30f;
                if (k0i + 1 > qr0)     sacc[j][1] = -1e30f;
                if (k0i     > qr0 + 8) sacc[j][2] = -1e30f;
                if (k0i + 1 > qr0 + 8) sacc[j][3] = -1e30f;
            }
        }

        // ---- online softmax ----
        float mx0 = m0, mx1 = m1;
        #pragma unroll
        for (int j = 0; j < 16; j++) {
            mx0 = fmaxf(mx0, fmaxf(sacc[j][0], sacc[j][1]));
            mx1 = fmaxf(mx1, fmaxf(sacc[j][2], sacc[j][3]));
        }
        mx0 = fmaxf(mx0, __shfl_xor_sync(0xFFFFFFFFu, mx0, 1));
        mx0 = fmaxf(mx0, __shfl_xor_sync(0xFFFFFFFFu, mx0, 2));
        mx1 = fmaxf(mx1, __shfl_xor_sync(0xFFFFFFFFu, mx1, 1));
        mx1 = fmaxf(mx1, __shfl_xor_sync(0xFFFFFFFFu, mx1, 2));
        float cor0 = __expf(m0 - mx0);
        float cor1 = __expf(m1 - mx1);
        m0 = mx0; m1 = mx1;
        float rs0 = 0.f, rs1 = 0.f;
        #pragma unroll
        for (int j = 0; j < 16; j++) {
            float p0 = __expf(sacc[j][0] - m0);
            float p1 = __expf(sacc[j][1] - m0);
            float p2 = __expf(sacc[j][2] - m1);
            float p3 = __expf(sacc[j][3] - m1);
            sacc[j][0] = p0; sacc[j][1] = p1; sacc[j][2] = p2; sacc[j][3] = p3;
            rs0 += p0 + p1; rs1 += p2 + p3;
        }
        rs0 += __shfl_xor_sync(0xFFFFFFFFu, rs0, 1);
        rs0 += __shfl_xor_sync(0xFFFFFFFFu, rs0, 2);
        rs1 += __shfl_xor_sync(0xFFFFFFFFu, rs1, 1);
        rs1 += __shfl_xor_sync(0xFFFFFFFFu, rs1, 2);
        l0 = l0 * cor0 + rs0;
        l1 = l1 * cor1 + rs1;
        #pragma unroll
        for (int dt = 0; dt < 8; dt++) {
            oacc[dt][0] *= cor0; oacc[dt][1] *= cor0;
            oacc[dt][2] *= cor1; oacc[dt][3] *= cor1;
        }

        // ---- O += P V  (P single-pass bf16; V hi/lo 2-pass) ----
        #pragma unroll
        for (int s = 0; s < 8; s++) {
            uint32_t pah[4];
            #pragma unroll
            for (int tt = 0; tt < 2; tt++) {
                const float* sc = sacc[2*s + tt];
                pah[tt*2+0] = packbf(sc[0], sc[1]);
                pah[tt*2+1] = packbf(sc[2], sc[3]);
            }
            uint32_t vfh[4][4], vfl[4][4];
            #pragma unroll
            for (int dc = 0; dc < 4; dc++) {
                uint32_t vo = (uint32_t)(s * 16 + v_rowo) * AROWB + dc * 32 + v_cbo;
                ldm4t(vfh[dc], kb + AKV_VHI + vo);
                ldm4t(vfl[dc], kb + AKV_VLO + vo);
            }
            #pragma unroll
            for (int dc = 0; dc < 4; dc++) {
                mma_bf16(oacc[dc*2+0], pah, vfh[dc][0], vfh[dc][1]);
                mma_bf16(oacc[dc*2+1], pah, vfh[dc][2], vfh[dc][3]);
            }
            #pragma unroll
            for (int dc = 0; dc < 4; dc++) {
                mma_bf16(oacc[dc*2+0], pah, vfl[dc][0], vfl[dc][1]);
                mma_bf16(oacc[dc*2+1], pah, vfl[dc][2], vfl[dc][3]);
            }
        }
        __syncthreads();
    }

    float inv0 = 1.0f / l0;
    float inv1 = 1.0f / l1;
    int qr = qt * 128 + wid * 16 + (lane >> 2);
    size_t y0 = (rowbase + qr) * E_ + h * HS_ + (lane & 3) * 2;
    size_t y1 = y0 + (size_t)8 * E_;
    #pragma unroll
    for (int dt = 0; dt < 8; dt++) {
        float w0 = oacc[dt][0] * inv0, w1 = oacc[dt][1] * inv0;
        float w2 = oacc[dt][2] * inv1, w3 = oacc[dt][3] * inv1;
        bf16 h0,lo0,h1,lo1,h2,lo2,h3,lo3;
        split_bf16(w0,h0,lo0); split_bf16(w1,h1,lo1);
        split_bf16(w2,h2,lo2); split_bf16(w3,h3,lo3);
        __nv_bfloat162 hh0; hh0.x=h0; hh0.y=h1;
        __nv_bfloat162 ll0; ll0.x=lo0; ll0.y=lo1;
        __nv_bfloat162 hh1; hh1.x=h2; hh1.y=h3;
        __nv_bfloat162 ll1; ll1.x=lo2; ll1.y=lo3;
        *(__nv_bfloat162*)(Yhi + y0 + dt*8) = hh0;
        *(__nv_bfloat162*)(Ylo + y0 + dt*8) = ll0;
        *(__nv_bfloat162*)(Yhi + y1 + dt*8) = hh1;
        *(__nv_bfloat162*)(Ylo + y1 + dt*8) = ll1;
    }
}

// ======================= launch =======================
extern "C" void kernel_launch(void* const* d_in, const int* in_sizes, int n_in,
                              void* d_out, int out_size)
{
    const float* x    = (const float*)d_in[0];
    const float* Wq   = (const float*)d_in[1];
    const float* Wk   = (const float*)d_in[2];
    const float* Wv   = (const float*)d_in[3];
    const float* Wo   = (const float*)d_in[4];
    const float* bo   = (const float*)d_in[5];
    const float* ln1w = (const float*)d_in[6];
    const float* ln2w = (const float*)d_in[7];
    const float* W1   = (const float*)d_in[8];
    const float* b1   = (const float*)d_in[9];
    const float* W2   = (const float*)d_in[10];
    const float* b2   = (const float*)d_in[11];
    float* out = (float*)d_out;

    unsigned char* pool;
    cudaGetSymbolAddress((void**)&pool, g_pool);

    bf16*  hhi  = (bf16*)(pool + O_HHI);
    bf16*  hlo  = (bf16*)(pool + O_HLO);
    bf16*  qhi  = (bf16*)(pool + O_QHI), *qlo = (bf16*)(pool + O_QLO);
    bf16*  khi  = (bf16*)(pool + O_KHI), *klo = (bf16*)(pool + O_KLO);
    bf16*  vhi  = (bf16*)(pool + O_VHI), *vlo = (bf16*)(pool + O_VLO);
    bf16*  yhi  = (bf16*)(pool + O_YHI), *ylo = (bf16*)(pool + O_YLO);
    float* x2   = (float*)(pool + O_X2);
    bf16*  ffhi = (bf16*)(pool + O_FFHI);
    bf16*  fflo = (bf16*)(pool + O_FFLO);
    bf16*  wqh = (bf16*)(pool + O_WQH), *wql = (bf16*)(pool + O_WQL);
    bf16*  wkh = (bf16*)(pool + O_WKH), *wkl = (bf16*)(pool + O_WKL);
    bf16*  wvh = (bf16*)(pool + O_WVH), *wvl = (bf16*)(pool + O_WVL);
    bf16*  woh = (bf16*)(pool + O_WOH), *wol = (bf16*)(pool + O_WOL);
    bf16*  w1h = (bf16*)(pool + O_W1H), *w1l = (bf16*)(pool + O_W1L);
    bf16*  w2h = (bf16*)(pool + O_W2H), *w2l = (bf16*)(pool + O_W2L);

    cudaFuncSetAttribute(gemm_tc<1>, cudaFuncAttributeMaxDynamicSharedMemorySize, SMEM_SZ);
    cudaFuncSetAttribute(gemm_tc<2>, cudaFuncAttributeMaxDynamicSharedMemorySize, SMEM_SZ);
    cudaFuncSetAttribute(gemm_tc<3>, cudaFuncAttributeMaxDynamicSharedMemorySize, SMEM_SZ);
    cudaFuncSetAttribute(attn_tc,    cudaFuncAttributeMaxDynamicSharedMemorySize, ASMEM);

    dim3 tb(32, 8);
    wsplit_kernel<<<dim3(E_/32,  E_/32),  tb>>>(Wq, wqh, wql, E_,  E_);
    wsplit_kernel<<<dim3(E_/32,  E_/32),  tb>>>(Wk, wkh, wkl, E_,  E_);
    wsplit_kernel<<<dim3(E_/32,  E_/32),  tb>>>(Wv, wvh, wvl, E_,  E_);
    wsplit_kernel<<<dim3(E_/32,  E_/32),  tb>>>(Wo, woh, wol, E_,  E_);
    wsplit_kernel<<<dim3(FF_/32, E_/32),  tb>>>(W1, w1h, w1l, E_,  FF_);
    wsplit_kernel<<<dim3(E_/32,  FF_/32), tb>>>(W2, w2h, w2l, FF_, E_);

    dim3 gE (E_  / BN, M_ / BM);     // (8, 64)
    dim3 gQKV(3 * (E_ / BN), M_ / BM); // (24, 64)
    dim3 g4E(FF_ / BN, M_ / BM);     // (32, 64)

    // 1) h = LN1(x)
    ln_split_kernel<<<M_, 256>>>(x, ln1w, hhi, hlo);
    // 2) fused q,k,v projections -> bf16 hi/lo (q pre-scaled by 1/32)
    gemm_tc<3><<<gQKV, 256, SMEM_SZ>>>(hhi, hlo,
        wqh, wql, wkh, wkl, wvh, wvl,
        nullptr, nullptr, nullptr,
        qhi, qlo, khi, klo, vhi, vlo, M_, E_, E_);
    // 3) y = causal attention
    attn_tc<<<dim3(T_/128, B_*H_), 256, ASMEM>>>(qhi, qlo, khi, klo, vhi, vlo, yhi, ylo);
    // 4) x2 = x + y @ Wo + bo
    gemm_tc<1><<<gE, 256, SMEM_SZ>>>(yhi, ylo,
        woh, wol, woh, wol, woh, wol,
        bo, x, x2,
        nullptr, nullptr, nullptr, nullptr, nullptr, nullptr, M_, E_, E_);
    // 5) h2 = LN2(x2)
    ln_split_kernel<<<M_, 256>>>(x2, ln2w, hhi, hlo);
    // 6) ff = relu(h2 @ W1 + b1)
    gemm_tc<2><<<g4E, 256, SMEM_SZ>>>(hhi, hlo,
        w1h, w1l, w1h, w1l, w1h, w1l,
        b1, nullptr, nullptr,
        ffhi, fflo, nullptr, nullptr, nullptr, nullptr, M_, FF_, E_);
    // 7) out = x2 + ff @ W2 + b2
    gemm_tc<1><<<gE, 256, SMEM_SZ>>>(ffhi, fflo,
        w2h, w2l, w2h, w2l, w2h, w2l,
        b2, x2, out,
        nullptr, nullptr, nullptr, nullptr, nullptr, nullptr, M_, E_, FF_);
}

// round 9
// speedup vs baseline: 2.2113x; 1.0004x over previous
#include <cuda_runtime.h>
#include <cuda_bf16.h>
#include <cstdint>

#define B_  4
#define T_  2048
#define E_  1024
#define H_  16
#define HS_ 64
#define M_  (B_*T_)    // 8192
#define FF_ (4*E_)     // 4096

typedef unsigned long long u64;
typedef __nv_bfloat16 bf16;

// ======================= scratch pool (__device__ global) =======================
#define SZ_HB   ((size_t)M_*E_*2)
#define SZ_F32  ((size_t)M_*E_*4)
#define SZ_FFB  ((size_t)M_*FF_*2)
#define SZ_WB   ((size_t)E_*E_*2)
#define SZ_W1B  ((size_t)E_*FF_*2)

constexpr size_t O_HHI  = 0;
constexpr size_t O_HLO  = O_HHI  + SZ_HB;
constexpr size_t O_QHI  = O_HLO  + SZ_HB;
constexpr size_t O_QLO  = O_QHI  + SZ_HB;
constexpr size_t O_KHI  = O_QLO  + SZ_HB;
constexpr size_t O_KLO  = O_KHI  + SZ_HB;
constexpr size_t O_VHI  = O_KLO  + SZ_HB;
constexpr size_t O_VLO  = O_VHI  + SZ_HB;
constexpr size_t O_YHI  = O_VLO  + SZ_HB;
constexpr size_t O_YLO  = O_YHI  + SZ_HB;
constexpr size_t O_X2   = O_YLO  + SZ_HB;
constexpr size_t O_FFHI = O_X2   + SZ_F32;
constexpr size_t O_FFLO = O_FFHI + SZ_FFB;
constexpr size_t O_WQH  = O_FFLO + SZ_FFB;
constexpr size_t O_WQL  = O_WQH  + SZ_WB;
constexpr size_t O_WKH  = O_WQL  + SZ_WB;
constexpr size_t O_WKL  = O_WKH  + SZ_WB;
constexpr size_t O_WVH  = O_WKL  + SZ_WB;
constexpr size_t O_WVL  = O_WVH  + SZ_WB;
constexpr size_t O_WOH  = O_WVL  + SZ_WB;
constexpr size_t O_WOL  = O_WOH  + SZ_WB;
constexpr size_t O_W1H  = O_WOL  + SZ_WB;
constexpr size_t O_W1L  = O_W1H  + SZ_W1B;
constexpr size_t O_W2H  = O_W1L  + SZ_W1B;
constexpr size_t O_W2L  = O_W2H  + SZ_W1B;
constexpr size_t POOLSZ = O_W2L  + SZ_W1B;

__device__ __align__(1024) unsigned char g_pool[POOLSZ];

// ======================= PTX helpers =======================
__device__ __forceinline__ uint32_t s2u(const void* p){
    uint32_t a;
    asm("{ .reg .u64 t; cvta.to.shared.u64 t, %1; cvt.u32.u64 %0, t; }" : "=r"(a) : "l"(p));
    return a;
}
__device__ __forceinline__ void cp16(uint32_t s, const void* g){
    asm volatile("cp.async.cg.shared.global [%0], [%1], 16;" :: "r"(s), "l"(g));
}
__device__ __forceinline__ void ldm4(uint32_t (&r)[4], uint32_t a){
    asm volatile("ldmatrix.sync.aligned.m8n8.x4.shared.b16 {%0,%1,%2,%3}, [%4];"
                 : "=r"(r[0]), "=r"(r[1]), "=r"(r[2]), "=r"(r[3]) : "r"(a));
}
__device__ __forceinline__ void ldm4t(uint32_t (&r)[4], uint32_t a){
    asm volatile("ldmatrix.sync.aligned.m8n8.x4.trans.shared.b16 {%0,%1,%2,%3}, [%4];"
                 : "=r"(r[0]), "=r"(r[1]), "=r"(r[2]), "=r"(r[3]) : "r"(a));
}
__device__ __forceinline__ void mma_bf16(float (&c)[4], const uint32_t* a, uint32_t b0, uint32_t b1){
    asm volatile(
        "mma.sync.aligned.m16n8k16.row.col.f32.bf16.bf16.f32 "
        "{%0,%1,%2,%3}, {%4,%5,%6,%7}, {%8,%9}, {%0,%1,%2,%3};"
        : "+f"(c[0]), "+f"(c[1]), "+f"(c[2]), "+f"(c[3])
        : "r"(a[0]), "r"(a[1]), "r"(a[2]), "r"(a[3]), "r"(b0), "r"(b1));
}
__device__ __forceinline__ uint32_t packbf(float lo_val, float hi_val){
    uint32_t r;
    asm("cvt.rn.bf16x2.f32 %0, %1, %2;" : "=r"(r) : "f"(hi_val), "f"(lo_val));
    return r;
}
__device__ __forceinline__ void split_bf16(float v, bf16 &hi, bf16 &lo){
    hi = __float2bfloat16(v);
    lo = __float2bfloat16(v - __bfloat162float(hi));
}

// ======================= LayerNorm -> bf16 hi/lo splits =======================
__global__ __launch_bounds__(256) void ln_split_kernel(
    const float* __restrict__ X, const float* __restrict__ w,
    bf16* __restrict__ Ohi, bf16* __restrict__ Olo)
{
    int row = blockIdx.x;
    int tid = threadIdx.x;
    const float* x = X + (size_t)row * E_;

    float4 v = *(const float4*)(x + tid * 4);
    float s  = v.x + v.y + v.z + v.w;
    float sq = v.x*v.x + v.y*v.y + v.z*v.z + v.w*v.w;

    #pragma unroll
    for (int o = 16; o; o >>= 1) {
        s  += __shfl_xor_sync(0xFFFFFFFFu, s,  o);
        sq += __shfl_xor_sync(0xFFFFFFFFu, sq, o);
    }
    __shared__ float ss[8], ssq[8], red[2];
    int wid = tid >> 5, lane = tid & 31;
    if (lane == 0) { ss[wid] = s; ssq[wid] = sq; }
    __syncthreads();
    if (tid == 0) {
        float a = 0.f, b = 0.f;
        #pragma unroll
        for (int i = 0; i < 8; i++) { a += ss[i]; b += ssq[i]; }
        float mean = a * (1.0f / E_);
        float var  = b * (1.0f / E_) - mean * mean;
        red[0] = mean;
        red[1] = rsqrtf(var + 1e-5f);
    }
    __syncthreads();
    float mean = red[0], rs = red[1];
    float4 wv = *(const float4*)(w + tid * 4);
    float o0 = (v.x - mean) * rs * wv.x;
    float o1 = (v.y - mean) * rs * wv.y;
    float o2 = (v.z - mean) * rs * wv.z;
    float o3 = (v.w - mean) * rs * wv.w;

    bf16 h0,h1,h2,h3,l0,l1,l2,l3;
    split_bf16(o0,h0,l0); split_bf16(o1,h1,l1);
    split_bf16(o2,h2,l2); split_bf16(o3,h3,l3);
    size_t off = (size_t)row * E_ + tid * 4;
    __nv_bfloat162 ph0; ph0.x=h0; ph0.y=h1;
    __nv_bfloat162 ph1; ph1.x=h2; ph1.y=h3;
    __nv_bfloat162 pl0; pl0.x=l0; pl0.y=l1;
    __nv_bfloat162 pl1; pl1.x=l2; pl1.y=l3;
    *(__nv_bfloat162*)(Ohi + off)     = ph0;
    *(__nv_bfloat162*)(Ohi + off + 2) = ph1;
    *(__nv_bfloat162*)(Olo + off)     = pl0;
    *(__nv_bfloat162*)(Olo + off + 2) = pl1;
}

// ======================= weight transpose + split =======================
__global__ __launch_bounds__(256) void wsplit_kernel(
    const float* __restrict__ W, bf16* __restrict__ Whi, bf16* __restrict__ Wlo,
    int K, int N)
{
    __shared__ float t[32][33];
    int n0 = blockIdx.x * 32, k0 = blockIdx.y * 32;
    int tx = threadIdx.x, ty0 = threadIdx.y;
    #pragma unroll
    for (int dy = 0; dy < 32; dy += 8) {
        int ty = ty0 + dy;
        t[ty][tx] = W[(size_t)(k0 + ty) * N + n0 + tx];
    }
    __syncthreads();
    #pragma unroll
    for (int dy = 0; dy < 32; dy += 8) {
        int ty = ty0 + dy;
        float v = t[tx][ty];
        bf16 hi, lo; split_bf16(v, hi, lo);
        size_t o = (size_t)(n0 + ty) * K + k0 + tx;
        Whi[o] = hi;
        Wlo[o] = lo;
    }
}

// ======================= HMMA GEMM (bf16 split, fp32 accum), BK=64 ============
// OP: 1 = acc+bias+res -> f32; 2 = relu(acc+bias) -> bf16 hi/lo;
// OP: 3 = fused QKV (sel = blockIdx.x>>3; q scaled by 1/32)
// NPASS: 3 = ah*bh + ah*bl + al*bh;  2 = ah*bh + ah*bl (A-lo dropped)
// NOTE R7 post-mortem: NPASS=2 on activation GEMMs costs ~8e-4 rel_err each —
// only safe for at most ~one GEMM. Currently all NPASS=3.
#define BM 128
#define BN 128
#define BK 64
#define ROWB   144
#define MTILE  (128*ROWB)
#define BUFSZ  (4*MTILE)
#define SMEM_SZ (2*BUFSZ)

template<int OP, int NPASS>
__global__ __launch_bounds__(256, 1) void gemm_tc(
    const bf16* __restrict__ Ahi, const bf16* __restrict__ Alo,
    const bf16* __restrict__ B0h, const bf16* __restrict__ B0l,
    const bf16* __restrict__ B1h, const bf16* __restrict__ B1l,
    const bf16* __restrict__ B2h, const bf16* __restrict__ B2l,
    const float* __restrict__ bias, const float* __restrict__ res,
    float* __restrict__ C,
    bf16* __restrict__ C0h, bf16* __restrict__ C0l,
    bf16* __restrict__ C1h, bf16* __restrict__ C1l,
    bf16* __restrict__ C2h, bf16* __restrict__ C2l,
    int M, int N, int K)
{
    extern __shared__ __align__(128) unsigned char smem[];
    uint32_t sb = s2u(smem);
    int tid = threadIdx.x;
    int lane = tid & 31, wid = tid >> 5;
    int warp_m = wid & 1, warp_n = wid >> 1;

    int sel = 0, bxi = blockIdx.x;
    if (OP == 3) { sel = blockIdx.x >> 3; bxi = blockIdx.x & 7; }
    int bx = bxi * BN, by = blockIdx.y * BM;

    const bf16* Bhi = (OP == 3) ? (sel == 0 ? B0h : sel == 1 ? B1h : B2h) : B0h;
    const bf16* Blo = (OP == 3) ? (sel == 0 ? B0l : sel == 1 ? B1l : B2l) : B0l;
    bf16* Chi = (OP == 3) ? (sel == 0 ? C0h : sel == 1 ? C1h : C2h) : C0h;
    bf16* Clo = (OP == 3) ? (sel == 0 ? C0l : sel == 1 ? C1l : C2l) : C0l;
    float scale = (OP == 3 && sel == 0) ? 0.03125f : 1.0f;

    int chb = tid * 4;
    int lrow[4], lc16[4];
    uint32_t soff[4];
    #pragma unroll
    for (int i = 0; i < 4; i++) {
        lrow[i] = (chb + i) >> 3;
        lc16[i] = (chb + i) & 7;
        soff[i] = (uint32_t)(lrow[i] * ROWB + lc16[i] * 16);
    }

    const bf16* gAhi = Ahi + (size_t)(by) * K;
    const bf16* gAlo = (NPASS == 3) ? (Alo + (size_t)(by) * K) : nullptr;
    const bf16* gBhi = Bhi + (size_t)(bx) * K;
    const bf16* gBlo = Blo + (size_t)(bx) * K;

    float acc[4][4][4];
    #pragma unroll
    for (int i = 0; i < 4; i++)
        #pragma unroll
        for (int j = 0; j < 4; j++)
            #pragma unroll
            for (int q = 0; q < 4; q++) acc[i][j][q] = 0.f;

    int nt = K / BK;

    auto issue_tile = [&](int t, int buf) {
        uint32_t base = sb + buf * BUFSZ;
        int k0 = t * BK;
        #pragma unroll
        for (int i = 0; i < 4; i++) {
            size_t go = (size_t)lrow[i] * K + k0 + lc16[i] * 8;
            cp16(base + soff[i],           gAhi + go);
            if (NPASS == 3) cp16(base + MTILE + soff[i], gAlo + go);
            cp16(base + 2*MTILE + soff[i], gBhi + go);
            cp16(base + 3*MTILE + soff[i], gBlo + go);
        }
        asm volatile("cp.async.commit_group;" ::: "memory");
    };

    issue_tile(0, 0);

    uint32_t a_row = (uint32_t)(warp_m * 64 + (lane & 15));
    uint32_t a_cb  = (uint32_t)((lane >> 4) * 16);
    uint32_t b_row = (uint32_t)(warp_n * 32 + (lane & 7) + ((lane >> 4) & 1) * 8);
    uint32_t b_cb  = (uint32_t)(((lane >> 3) & 1) * 16);

    for (int t = 0; t < nt; t++) {
        int buf = t & 1;
        if (t + 1 < nt) {
            issue_tile(t + 1, buf ^ 1);
            asm volatile("cp.async.wait_group 1;" ::: "memory");
        } else {
            asm volatile("cp.async.wait_group 0;" ::: "memory");
        }
        __syncthreads();

        uint32_t base  = sb + buf * BUFSZ;
        uint32_t sAhi = base;
        uint32_t sAlo = base + MTILE;
        uint32_t sBhi = base + 2*MTILE;
        uint32_t sBlo = base + 3*MTILE;

        #pragma unroll
        for (int s = 0; s < 4; s++) {
            uint32_t kb = (uint32_t)(s * 32);
            uint32_t ahi[4][4], alo[4][4], bhi[2][4], blo[2][4];
            #pragma unroll
            for (int mt = 0; mt < 4; mt++) {
                uint32_t ao = (a_row + mt * 16) * ROWB + kb + a_cb;
                ldm4(ahi[mt], sAhi + ao);
                if (NPASS == 3) ldm4(alo[mt], sAlo + ao);
            }
            #pragma unroll
            for (int ntp = 0; ntp < 2; ntp++) {
                uint32_t bo = (b_row + ntp * 16) * ROWB + kb + b_cb;
                ldm4(bhi[ntp], sBhi + bo);
                ldm4(blo[ntp], sBlo + bo);
            }
            #pragma unroll
            for (int mt = 0; mt < 4; mt++)
                #pragma unroll
                for (int ntp = 0; ntp < 2; ntp++)
                    #pragma unroll
                    for (int hf = 0; hf < 2; hf++)
                        mma_bf16(acc[mt][ntp*2+hf], ahi[mt], bhi[ntp][hf*2], bhi[ntp][hf*2+1]);
            #pragma unroll
            for (int mt = 0; mt < 4; mt++)
                #pragma unroll
                for (int ntp = 0; ntp < 2; ntp++)
                    #pragma unroll
                    for (int hf = 0; hf < 2; hf++)
                        mma_bf16(acc[mt][ntp*2+hf], ahi[mt], blo[ntp][hf*2], blo[ntp][hf*2+1]);
            if (NPASS == 3) {
                #pragma unroll
                for (int mt = 0; mt < 4; mt++)
                    #pragma unroll
                    for (int ntp = 0; ntp < 2; ntp++)
                        #pragma unroll
                        for (int hf = 0; hf < 2; hf++)
                            mma_bf16(acc[mt][ntp*2+hf], alo[mt], bhi[ntp][hf*2], bhi[ntp][hf*2+1]);
            }
        }
        __syncthreads();
    }

    // -------- epilogue --------
    int er = by + warp_m * 64 + (lane >> 2);
    int ec = bx + warp_n * 32 + (lane & 3) * 2;
    #pragma unroll
    for (int mt = 0; mt < 4; mt++) {
        #pragma unroll
        for (int half = 0; half < 2; half++) {
            int row = er + mt * 16 + half * 8;
            #pragma unroll
            for (int ntj = 0; ntj < 4; ntj++) {
                int col = ec + ntj * 8;
                float v0 = acc[mt][ntj][half*2];
                float v1 = acc[mt][ntj][half*2+1];
                if (OP == 1) {
                    float2 rv = *(const float2*)&res[(size_t)row * N + col];
                    float2 bv = *(const float2*)&bias[col];
                    *(float2*)&C[(size_t)row * N + col] =
                        make_float2(v0 + bv.x + rv.x, v1 + bv.y + rv.y);
                } else {
                    float w0, w1;
                    if (OP == 2) {
                        float2 bv = *(const float2*)&bias[col];
                        w0 = fmaxf(v0 + bv.x, 0.0f);
                        w1 = fmaxf(v1 + bv.y, 0.0f);
                    } else {
                        w0 = v0 * scale;
                        w1 = v1 * scale;
                    }
                    bf16 h0,l0,h1,l1;
                    split_bf16(w0, h0, l0);
                    split_bf16(w1, h1, l1);
                    __nv_bfloat162 hh; hh.x = h0; hh.y = h1;
                    __nv_bfloat162 ll; ll.x = l0; ll.y = l1;
                    *(__nv_bfloat162*)&Chi[(size_t)row * N + col] = hh;
                    *(__nv_bfloat162*)&Clo[(size_t)row * N + col] = ll;
                }
            }
        }
    }
}

// ======================= Tensor-core causal flash attention ====================
// QK^T 3-pass hi/lo (R6-validated). PV: P single-pass bf16 x V hi/lo (2-pass).
#define AROWB 144
#define ATILE (128*AROWB)
#define ASM_QHI 0
#define ASM_QLO ATILE
#define ASM_KV  (2*ATILE)
#define AKV_KHI 0
#define AKV_KLO ATILE
#define AKV_VHI (2*ATILE)
#define AKV_VLO (3*ATILE)
#define AKVSTAGE (4*ATILE)
#define ASMEM (2*ATILE + 2*AKVSTAGE)

__global__ __launch_bounds__(256, 1) void attn_tc(
    const bf16* __restrict__ Qhi, const bf16* __restrict__ Qlo,
    const bf16* __restrict__ Khi, const bf16* __restrict__ Klo,
    const bf16* __restrict__ Vhi, const bf16* __restrict__ Vlo,
    bf16* __restrict__ Yhi, bf16* __restrict__ Ylo)
{
    extern __shared__ __align__(128) unsigned char asmem[];
    uint32_t sb = s2u(asmem);
    int tid = threadIdx.x, lane = tid & 31, wid = tid >> 5;
    int qt = blockIdx.x, bh = blockIdx.y;
    int b = bh >> 4, h = bh & 15;

    size_t rowbase = (size_t)b * T_;
    size_t qoff = (rowbase + qt * 128) * E_ + h * HS_;

    int chb = tid * 4;
    int lrow[4], lch[4];
    uint32_t soff[4];
    #pragma unroll
    for (int i = 0; i < 4; i++) {
        lrow[i] = (chb + i) >> 3;
        lch[i]  = (chb + i) & 7;
        soff[i] = (uint32_t)(lrow[i] * AROWB + lch[i] * 16);
    }

    #pragma unroll
    for (int i = 0; i < 4; i++) {
        size_t g = qoff + (size_t)lrow[i] * E_ + lch[i] * 8;
        cp16(sb + ASM_QHI + soff[i], Qhi + g);
        cp16(sb + ASM_QLO + soff[i], Qlo + g);
    }
    asm volatile("cp.async.commit_group;" ::: "memory");

    auto load_kv = [&](int kt, int buf) {
        size_t ko = (rowbase + kt * 128) * E_ + h * HS_;
        uint32_t base = sb + ASM_KV + buf * AKVSTAGE;
        #pragma unroll
        for (int i = 0; i < 4; i++) {
            size_t g = ko + (size_t)lrow[i] * E_ + lch[i] * 8;
            cp16(base + AKV_KHI + soff[i], Khi + g);
            cp16(base + AKV_KLO + soff[i], Klo + g);
            cp16(base + AKV_VHI + soff[i], Vhi + g);
            cp16(base + AKV_VLO + soff[i], Vlo + g);
        }
        asm volatile("cp.async.commit_group;" ::: "memory");
    };
    load_kv(0, 0);

    asm volatile("cp.async.wait_group 1;" ::: "memory");
    __syncthreads();

    uint32_t a_row = (uint32_t)(wid * 16 + (lane & 15));
    uint32_t a_cb  = (uint32_t)((lane >> 4) * 16);
    uint32_t qfh[4][4], qfl[4][4];
    #pragma unroll
    for (int s = 0; s < 4; s++) {
        uint32_t ao = a_row * AROWB + s * 32 + a_cb;
        ldm4(qfh[s], sb + ASM_QHI + ao);
        ldm4(qfl[s], sb + ASM_QLO + ao);
    }

    float oacc[8][4];
    #pragma unroll
    for (int i = 0; i < 8; i++)
        #pragma unroll
        for (int j = 0; j < 4; j++) oacc[i][j] = 0.f;
    float m0 = -1e30f, m1 = -1e30f, l0 = 0.f, l1 = 0.f;

    uint32_t b_rowo = (uint32_t)((lane & 7) + ((lane >> 4) & 1) * 8);
    uint32_t b_cbo  = (uint32_t)(((lane >> 3) & 1) * 16);
    uint32_t v_rowo = (uint32_t)(lane & 15);
    uint32_t v_cbo  = (uint32_t)(((lane >> 4) & 1) * 16);

    for (int kt = 0; kt <= qt; kt++) {
        int buf = kt & 1;
        if (kt < qt) {
            load_kv(kt + 1, buf ^ 1);
            asm volatile("cp.async.wait_group 1;" ::: "memory");
        } else {
            asm volatile("cp.async.wait_group 0;" ::: "memory");
        }
        __syncthreads();
        uint32_t kb = sb + ASM_KV + buf * AKVSTAGE;

        // ---- S = Q K^T (3-pass hi/lo) ----
        float sacc[16][4];
        #pragma unroll
        for (int j = 0; j < 16; j++)
            #pragma unroll
            for (int q = 0; q < 4; q++) sacc[j][q] = 0.f;

        #pragma unroll
        for (int g = 0; g < 2; g++) {
            #pragma unroll
            for (int s = 0; s < 4; s++) {
                uint32_t kfh[4][4], kfl[4][4];
                #pragma unroll
                for (int np = 0; np < 4; np++) {
                    uint32_t bo = (uint32_t)(g * 64 + np * 16 + b_rowo) * AROWB + s * 32 + b_cbo;
                    ldm4(kfh[np], kb + AKV_KHI + bo);
                    ldm4(kfl[np], kb + AKV_KLO + bo);
                }
                #pragma unroll
                for (int np = 0; np < 4; np++)
                    #pragma unroll
                    for (int hf = 0; hf < 2; hf++)
                        mma_bf16(sacc[g*8+np*2+hf], qfh[s], kfh[np][hf*2], kfh[np][hf*2+1]);
                #pragma unroll
                for (int np = 0; np < 4; np++)
                    #pragma unroll
                    for (int hf = 0; hf < 2; hf++)
                        mma_bf16(sacc[g*8+np*2+hf], qfh[s], kfl[np][hf*2], kfl[np][hf*2+1]);
                #pragma unroll
                for (int np = 0; np < 4; np++)
                    #pragma unroll
                    for (int hf = 0; hf < 2; hf++)
                        mma_bf16(sacc[g*8+np*2+hf], qfl[s], kfh[np][hf*2], kfh[np][hf*2+1]);
            }
        }

        if (kt == qt) {
            int qr0 = wid * 16 + (lane >> 2);
            int kc  = (lane & 3) * 2;
            #pragma unroll
            for (int j = 0; j < 16; j++) {
                int k0i = j * 8 + kc;
                if (k0i     > qr0)     sacc[j][0] = -1e30f;
                if (k0i + 1 > qr0)     sacc[j][1] = -1e30f;
                if (k0i     > qr0 + 8) sacc[j][2] = -1e30f;
                if (k0i + 1 > qr0 + 8) sacc[j][3] = -1e30f;
            }
        }

        // ---- online softmax ----
        float mx0 = m0, mx1 = m1;
        #pragma unroll
        for (int j = 0; j < 16; j++) {
            mx0 = fmaxf(mx0, fmaxf(sacc[j][0], sacc[j][1]));
            mx1 = fmaxf(mx1, fmaxf(sacc[j][2], sacc[j][3]));
        }
        mx0 = fmaxf(mx0, __shfl_xor_sync(0xFFFFFFFFu, mx0, 1));
        mx0 = fmaxf(mx0, __shfl_xor_sync(0xFFFFFFFFu, mx0, 2));
        mx1 = fmaxf(mx1, __shfl_xor_sync(0xFFFFFFFFu, mx1, 1));
        mx1 = fmaxf(mx1, __shfl_xor_sync(0xFFFFFFFFu, mx1, 2));
        float cor0 = __expf(m0 - mx0);
        float cor1 = __expf(m1 - mx1);
        m0 = mx0; m1 = mx1;
        float rs0 = 0.f, rs1 = 0.f;
        #pragma unroll
        for (int j = 0; j < 16; j++) {
            float p0 = __expf(sacc[j][0] - m0);
            float p1 = __expf(sacc[j][1] - m0);
            float p2 = __expf(sacc[j][2] - m1);
            float p3 = __expf(sacc[j][3] - m1);
            sacc[j][0] = p0; sacc[j][1] = p1; sacc[j][2] = p2; sacc[j][3] = p3;
            rs0 += p0 + p1; rs1 += p2 + p3;
        }
        rs0 += __shfl_xor_sync(0xFFFFFFFFu, rs0, 1);
        rs0 += __shfl_xor_sync(0xFFFFFFFFu, rs0, 2);
        rs1 += __shfl_xor_sync(0xFFFFFFFFu, rs1, 1);
        rs1 += __shfl_xor_sync(0xFFFFFFFFu, rs1, 2);
        l0 = l0 * cor0 + rs0;
        l1 = l1 * cor1 + rs1;
        #pragma unroll
        for (int dt = 0; dt < 8; dt++) {
            oacc[dt][0] *= cor0; oacc[dt][1] *= cor0;
            oacc[dt][2] *= cor1; oacc[dt][3] *= cor1;
        }

        // ---- O += P V  (P single-pass bf16; V hi/lo 2-pass) ----
        #pragma unroll
        for (int s = 0; s < 8; s++) {
            uint32_t pah[4];
            #pragma unroll
            for (int tt = 0; tt < 2; tt++) {
                const float* sc = sacc[2*s + tt];
                pah[tt*2+0] = packbf(sc[0], sc[1]);
                pah[tt*2+1] = packbf(sc[2], sc[3]);
            }
            uint32_t vfh[4][4], vfl[4][4];
            #pragma unroll
            for (int dc = 0; dc < 4; dc++) {
                uint32_t vo = (uint32_t)(s * 16 + v_rowo) * AROWB + dc * 32 + v_cbo;
                ldm4t(vfh[dc], kb + AKV_VHI + vo);
                ldm4t(vfl[dc], kb + AKV_VLO + vo);
            }
            #pragma unroll
            for (int dc = 0; dc < 4; dc++) {
                mma_bf16(oacc[dc*2+0], pah, vfh[dc][0], vfh[dc][1]);
                mma_bf16(oacc[dc*2+1], pah, vfh[dc][2], vfh[dc][3]);
            }
            #pragma unroll
            for (int dc = 0; dc < 4; dc++) {
                mma_bf16(oacc[dc*2+0], pah, vfl[dc][0], vfl[dc][1]);
                mma_bf16(oacc[dc*2+1], pah, vfl[dc][2], vfl[dc][3]);
            }
        }
        __syncthreads();
    }

    float inv0 = 1.0f / l0;
    float inv1 = 1.0f / l1;
    int qr = qt * 128 + wid * 16 + (lane >> 2);
    size_t y0 = (rowbase + qr) * E_ + h * HS_ + (lane & 3) * 2;
    size_t y1 = y0 + (size_t)8 * E_;
    #pragma unroll
    for (int dt = 0; dt < 8; dt++) {
        float w0 = oacc[dt][0] * inv0, w1 = oacc[dt][1] * inv0;
        float w2 = oacc[dt][2] * inv1, w3 = oacc[dt][3] * inv1;
        bf16 h0,lo0,h1,lo1,h2,lo2,h3,lo3;
        split_bf16(w0,h0,lo0); split_bf16(w1,h1,lo1);
        split_bf16(w2,h2,lo2); split_bf16(w3,h3,lo3);
        __nv_bfloat162 hh0; hh0.x=h0; hh0.y=h1;
        __nv_bfloat162 ll0; ll0.x=lo0; ll0.y=lo1;
        __nv_bfloat162 hh1; hh1.x=h2; hh1.y=h3;
        __nv_bfloat162 ll1; ll1.x=lo2; ll1.y=lo3;
        *(__nv_bfloat162*)(Yhi + y0 + dt*8) = hh0;
        *(__nv_bfloat162*)(Ylo + y0 + dt*8) = ll0;
        *(__nv_bfloat162*)(Yhi + y1 + dt*8) = hh1;
        *(__nv_bfloat162*)(Ylo + y1 + dt*8) = ll1;
    }
}

// ======================= launch =======================
extern "C" void kernel_launch(void* const* d_in, const int* in_sizes, int n_in,
                              void* d_out, int out_size)
{
    const float* x    = (const float*)d_in[0];
    const float* Wq   = (const float*)d_in[1];
    const float* Wk   = (const float*)d_in[2];
    const float* Wv   = (const float*)d_in[3];
    const float* Wo   = (const float*)d_in[4];
    const float* bo   = (const float*)d_in[5];
    const float* ln1w = (const float*)d_in[6];
    const float* ln2w = (const float*)d_in[7];
    const float* W1   = (const float*)d_in[8];
    const float* b1   = (const float*)d_in[9];
    const float* W2   = (const float*)d_in[10];
    const float* b2   = (const float*)d_in[11];
    float* out = (float*)d_out;

    unsigned char* pool;
    cudaGetSymbolAddress((void**)&pool, g_pool);

    bf16*  hhi  = (bf16*)(pool + O_HHI);
    bf16*  hlo  = (bf16*)(pool + O_HLO);
    bf16*  qhi  = (bf16*)(pool + O_QHI), *qlo = (bf16*)(pool + O_QLO);
    bf16*  khi  = (bf16*)(pool + O_KHI), *klo = (bf16*)(pool + O_KLO);
    bf16*  vhi  = (bf16*)(pool + O_VHI), *vlo = (bf16*)(pool + O_VLO);
    bf16*  yhi  = (bf16*)(pool + O_YHI), *ylo = (bf16*)(pool + O_YLO);
    float* x2   = (float*)(pool + O_X2);
    bf16*  ffhi = (bf16*)(pool + O_FFHI);
    bf16*  fflo = (bf16*)(pool + O_FFLO);
    bf16*  wqh = (bf16*)(pool + O_WQH), *wql = (bf16*)(pool + O_WQL);
    bf16*  wkh = (bf16*)(pool + O_WKH), *wkl = (bf16*)(pool + O_WKL);
    bf16*  wvh = (bf16*)(pool + O_WVH), *wvl = (bf16*)(pool + O_WVL);
    bf16*  woh = (bf16*)(pool + O_WOH), *wol = (bf16*)(pool + O_WOL);
    bf16*  w1h = (bf16*)(pool + O_W1H), *w1l = (bf16*)(pool + O_W1L);
    bf16*  w2h = (bf16*)(pool + O_W2H), *w2l = (bf16*)(pool + O_W2L);

    cudaFuncSetAttribute((const void*)gemm_tc<1,3>, cudaFuncAttributeMaxDynamicSharedMemorySize, SMEM_SZ);
    cudaFuncSetAttribute((const void*)gemm_tc<2,3>, cudaFuncAttributeMaxDynamicSharedMemorySize, SMEM_SZ);
    cudaFuncSetAttribute((const void*)gemm_tc<3,3>, cudaFuncAttributeMaxDynamicSharedMemorySize, SMEM_SZ);
    cudaFuncSetAttribute((const void*)attn_tc,      cudaFuncAttributeMaxDynamicSharedMemorySize, ASMEM);

    dim3 tb(32, 8);
    dim3 gE (E_  / BN, M_ / BM);       // (8, 64)
    dim3 gQKV(3 * (E_ / BN), M_ / BM); // (24, 64)
    dim3 g4E(FF_ / BN, M_ / BM);       // (32, 64)

    // Launch order arranged so launch #6 (ncu -s 5 -c 1) is the fused QKV GEMM.
    // 1-4) weight splits needed before QKV/Wo GEMMs
    wsplit_kernel<<<dim3(E_/32,  E_/32),  tb>>>(Wq, wqh, wql, E_,  E_);
    wsplit_kernel<<<dim3(E_/32,  E_/32),  tb>>>(Wk, wkh, wkl, E_,  E_);
    wsplit_kernel<<<dim3(E_/32,  E_/32),  tb>>>(Wv, wvh, wvl, E_,  E_);
    wsplit_kernel<<<dim3(E_/32,  E_/32),  tb>>>(Wo, woh, wol, E_,  E_);
    // 5) h = LN1(x)
    ln_split_kernel<<<M_, 256>>>(x, ln1w, hhi, hlo);
    // 6) fused q,k,v projections (3-pass) -> bf16 hi/lo  [ncu captures this]
    gemm_tc<3,3><<<gQKV, 256, SMEM_SZ>>>(hhi, hlo,
        wqh, wql, wkh, wkl, wvh, wvl,
        nullptr, nullptr, nullptr,
        qhi, qlo, khi, klo, vhi, vlo, M_, E_, E_);
    // 7) y = causal attention (QK^T 3-pass, PV 2-pass w/ bf16 P)
    attn_tc<<<dim3(T_/128, B_*H_), 256, ASMEM>>>(qhi, qlo, khi, klo, vhi, vlo, yhi, ylo);
    // 8-9) MLP weight splits
    wsplit_kernel<<<dim3(FF_/32, E_/32),  tb>>>(W1, w1h, w1l, E_,  FF_);
    wsplit_kernel<<<dim3(E_/32,  FF_/32), tb>>>(W2, w2h, w2l, FF_, E_);
    // 10) x2 = x + y @ Wo + bo (3-pass)
    gemm_tc<1,3><<<gE, 256, SMEM_SZ>>>(yhi, ylo,
        woh, wol, woh, wol, woh, wol,
        bo, x, x2,
        nullptr, nullptr, nullptr, nullptr, nullptr, nullptr, M_, E_, E_);
    // 11) h2 = LN2(x2)
    ln_split_kernel<<<M_, 256>>>(x2, ln2w, hhi, hlo);
    // 12) ff = relu(h2 @ W1 + b1)  (3-pass)
    gemm_tc<2,3><<<g4E, 256, SMEM_SZ>>>(hhi, hlo,
        w1h, w1l, w1h, w1l, w1h, w1l,
        b1, nullptr, nullptr,
        ffhi, fflo, nullptr, nullptr, nullptr, nullptr, M_, FF_, E_);
    // 13) out = x2 + ff @ W2 + b2  (3-pass)
    gemm_tc<1,3><<<gE, 256, SMEM_SZ>>>(ffhi, fflo,
        w2h, w2l, w2h, w2l, w2h, w2l,
        b2, x2, out,
        nullptr, nullptr, nullptr, nullptr, nullptr, nullptr, M_, E_, FF_);
}

// round 11
// speedup vs baseline: 2.6357x; 1.1919x over previous
#include <cuda_runtime.h>
#include <cuda_bf16.h>
#include <cstdint>

#define B_  4
#define T_  2048
#define E_  1024
#define H_  16
#define HS_ 64
#define M_  (B_*T_)    // 8192
#define FF_ (4*E_)     // 4096

typedef unsigned long long u64;
typedef __nv_bfloat16 bf16;

// ======================= scratch pool (__device__ global) =======================
#define SZ_HB   ((size_t)M_*E_*2)
#define SZ_F32  ((size_t)M_*E_*4)
#define SZ_FFB  ((size_t)M_*FF_*2)
#define SZ_WB   ((size_t)E_*E_*2)
#define SZ_W1B  ((size_t)E_*FF_*2)

constexpr size_t O_HHI  = 0;
constexpr size_t O_HLO  = O_HHI  + SZ_HB;
constexpr size_t O_QHI  = O_HLO  + SZ_HB;
constexpr size_t O_QLO  = O_QHI  + SZ_HB;
constexpr size_t O_KHI  = O_QLO  + SZ_HB;
constexpr size_t O_KLO  = O_KHI  + SZ_HB;
constexpr size_t O_VHI  = O_KLO  + SZ_HB;
constexpr size_t O_VLO  = O_VHI  + SZ_HB;
constexpr size_t O_YHI  = O_VLO  + SZ_HB;
constexpr size_t O_YLO  = O_YHI  + SZ_HB;
constexpr size_t O_X2   = O_YLO  + SZ_HB;
constexpr size_t O_FFHI = O_X2   + SZ_F32;
constexpr size_t O_FFLO = O_FFHI + SZ_FFB;
constexpr size_t O_WQH  = O_FFLO + SZ_FFB;
constexpr size_t O_WQL  = O_WQH  + SZ_WB;
constexpr size_t O_WKH  = O_WQL  + SZ_WB;
constexpr size_t O_WKL  = O_WKH  + SZ_WB;
constexpr size_t O_WVH  = O_WKL  + SZ_WB;
constexpr size_t O_WVL  = O_WVH  + SZ_WB;
constexpr size_t O_WOH  = O_WVL  + SZ_WB;
constexpr size_t O_WOL  = O_WOH  + SZ_WB;
constexpr size_t O_W1H  = O_WOL  + SZ_WB;
constexpr size_t O_W1L  = O_W1H  + SZ_W1B;
constexpr size_t O_W2H  = O_W1L  + SZ_W1B;
constexpr size_t O_W2L  = O_W2H  + SZ_W1B;
constexpr size_t POOLSZ = O_W2L  + SZ_W1B;

__device__ __align__(1024) unsigned char g_pool[POOLSZ];

// ======================= PTX helpers =======================
__device__ __forceinline__ uint32_t s2u(const void* p){
    uint32_t a;
    asm("{ .reg .u64 t; cvta.to.shared.u64 t, %1; cvt.u32.u64 %0, t; }" : "=r"(a) : "l"(p));
    return a;
}
__device__ __forceinline__ void cp16(uint32_t s, const void* g){
    asm volatile("cp.async.cg.shared.global [%0], [%1], 16;" :: "r"(s), "l"(g));
}
__device__ __forceinline__ void ldm4(uint32_t (&r)[4], uint32_t a){
    asm volatile("ldmatrix.sync.aligned.m8n8.x4.shared.b16 {%0,%1,%2,%3}, [%4];"
                 : "=r"(r[0]), "=r"(r[1]), "=r"(r[2]), "=r"(r[3]) : "r"(a));
}
__device__ __forceinline__ void ldm4t(uint32_t (&r)[4], uint32_t a){
    asm volatile("ldmatrix.sync.aligned.m8n8.x4.trans.shared.b16 {%0,%1,%2,%3}, [%4];"
                 : "=r"(r[0]), "=r"(r[1]), "=r"(r[2]), "=r"(r[3]) : "r"(a));
}
__device__ __forceinline__ void mma_bf16(float (&c)[4], const uint32_t* a, uint32_t b0, uint32_t b1){
    asm volatile(
        "mma.sync.aligned.m16n8k16.row.col.f32.bf16.bf16.f32 "
        "{%0,%1,%2,%3}, {%4,%5,%6,%7}, {%8,%9}, {%0,%1,%2,%3};"
        : "+f"(c[0]), "+f"(c[1]), "+f"(c[2]), "+f"(c[3])
        : "r"(a[0]), "r"(a[1]), "r"(a[2]), "r"(a[3]), "r"(b0), "r"(b1));
}
__device__ __forceinline__ uint32_t packbf(float lo_val, float hi_val){
    uint32_t r;
    asm("cvt.rn.bf16x2.f32 %0, %1, %2;" : "=r"(r) : "f"(hi_val), "f"(lo_val));
    return r;
}
__device__ __forceinline__ void split_bf16(float v, bf16 &hi, bf16 &lo){
    hi = __float2bfloat16(v);
    lo = __float2bfloat16(v - __bfloat162float(hi));
}

// ======================= LayerNorm -> bf16 hi/lo splits =======================
__global__ __launch_bounds__(256) void ln_split_kernel(
    const float* __restrict__ X, const float* __restrict__ w,
    bf16* __restrict__ Ohi, bf16* __restrict__ Olo)
{
    int row = blockIdx.x;
    int tid = threadIdx.x;
    const float* x = X + (size_t)row * E_;

    float4 v = *(const float4*)(x + tid * 4);
    float s  = v.x + v.y + v.z + v.w;
    float sq = v.x*v.x + v.y*v.y + v.z*v.z + v.w*v.w;

    #pragma unroll
    for (int o = 16; o; o >>= 1) {
        s  += __shfl_xor_sync(0xFFFFFFFFu, s,  o);
        sq += __shfl_xor_sync(0xFFFFFFFFu, sq, o);
    }
    __shared__ float ss[8], ssq[8], red[2];
    int wid = tid >> 5, lane = tid & 31;
    if (lane == 0) { ss[wid] = s; ssq[wid] = sq; }
    __syncthreads();
    if (tid == 0) {
        float a = 0.f, b = 0.f;
        #pragma unroll
        for (int i = 0; i < 8; i++) { a += ss[i]; b += ssq[i]; }
        float mean = a * (1.0f / E_);
        float var  = b * (1.0f / E_) - mean * mean;
        red[0] = mean;
        red[1] = rsqrtf(var + 1e-5f);
    }
    __syncthreads();
    float mean = red[0], rs = red[1];
    float4 wv = *(const float4*)(w + tid * 4);
    float o0 = (v.x - mean) * rs * wv.x;
    float o1 = (v.y - mean) * rs * wv.y;
    float o2 = (v.z - mean) * rs * wv.z;
    float o3 = (v.w - mean) * rs * wv.w;

    bf16 h0,h1,h2,h3,l0,l1,l2,l3;
    split_bf16(o0,h0,l0); split_bf16(o1,h1,l1);
    split_bf16(o2,h2,l2); split_bf16(o3,h3,l3);
    size_t off = (size_t)row * E_ + tid * 4;
    __nv_bfloat162 ph0; ph0.x=h0; ph0.y=h1;
    __nv_bfloat162 ph1; ph1.x=h2; ph1.y=h3;
    __nv_bfloat162 pl0; pl0.x=l0; pl0.y=l1;
    __nv_bfloat162 pl1; pl1.x=l2; pl1.y=l3;
    *(__nv_bfloat162*)(Ohi + off)     = ph0;
    *(__nv_bfloat162*)(Ohi + off + 2) = ph1;
    *(__nv_bfloat162*)(Olo + off)     = pl0;
    *(__nv_bfloat162*)(Olo + off + 2) = pl1;
}

// ======================= weight transpose + split =======================
__global__ __launch_bounds__(256) void wsplit_kernel(
    const float* __restrict__ W, bf16* __restrict__ Whi, bf16* __restrict__ Wlo,
    int K, int N)
{
    __shared__ float t[32][33];
    int n0 = blockIdx.x * 32, k0 = blockIdx.y * 32;
    int tx = threadIdx.x, ty0 = threadIdx.y;
    #pragma unroll
    for (int dy = 0; dy < 32; dy += 8) {
        int ty = ty0 + dy;
        t[ty][tx] = W[(size_t)(k0 + ty) * N + n0 + tx];
    }
    __syncthreads();
    #pragma unroll
    for (int dy = 0; dy < 32; dy += 8) {
        int ty = ty0 + dy;
        float v = t[tx][ty];
        bf16 hi, lo; split_bf16(v, hi, lo);
        size_t o = (size_t)(n0 + ty) * K + k0 + tx;
        Whi[o] = hi;
        Wlo[o] = lo;
    }
}

// ======================= HMMA GEMM (bf16 split, fp32 accum) ============
// BK=32, 80KB smem, __launch_bounds__(256,2) -> 2 CTAs/SM.
// Pass order ah*bh, al*bh, ah*bl with deferred fragment loads to cap liveness.
// OP: 1 = acc+bias+res -> f32; 2 = relu(acc+bias) -> bf16 hi/lo;
// OP: 3 = fused QKV (sel = blockIdx.x>>3; q scaled by 1/32)
#define BM 128
#define BN 128
#define BK 32
#define ROWB   80
#define MTILE  (128*ROWB)     // 10240
#define BUFSZ  (4*MTILE)      // 40960
#define SMEM_SZ (2*BUFSZ)     // 81920

template<int OP, int NPASS>
__global__ __launch_bounds__(256, 2) void gemm_tc(
    const bf16* __restrict__ Ahi, const bf16* __restrict__ Alo,
    const bf16* __restrict__ B0h, const bf16* __restrict__ B0l,
    const bf16* __restrict__ B1h, const bf16* __restrict__ B1l,
    const bf16* __restrict__ B2h, const bf16* __restrict__ B2l,
    const float* __restrict__ bias, const float* __restrict__ res,
    float* __restrict__ C,
    bf16* __restrict__ C0h, bf16* __restrict__ C0l,
    bf16* __restrict__ C1h, bf16* __restrict__ C1l,
    bf16* __restrict__ C2h, bf16* __restrict__ C2l,
    int M, int N, int K)
{
    extern __shared__ __align__(128) unsigned char smem[];
    uint32_t sb = s2u(smem);
    int tid = threadIdx.x;
    int lane = tid & 31, wid = tid >> 5;
    int warp_m = wid & 1, warp_n = wid >> 1;

    int sel = 0, bxi = blockIdx.x;
    if (OP == 3) { sel = blockIdx.x >> 3; bxi = blockIdx.x & 7; }
    int bx = bxi * BN, by = blockIdx.y * BM;

    const bf16* Bhi = (OP == 3) ? (sel == 0 ? B0h : sel == 1 ? B1h : B2h) : B0h;
    const bf16* Blo = (OP == 3) ? (sel == 0 ? B0l : sel == 1 ? B1l : B2l) : B0l;
    bf16* Chi = (OP == 3) ? (sel == 0 ? C0h : sel == 1 ? C1h : C2h) : C0h;
    bf16* Clo = (OP == 3) ? (sel == 0 ? C0l : sel == 1 ? C1l : C2l) : C0l;
    float scale = (OP == 3 && sel == 0) ? 0.03125f : 1.0f;

    // loader: 2 chunks (16B) per thread per matrix (128 rows x 4 chunks)
    int ch0 = tid * 2;
    int r0l = ch0 >> 2,        c0l = ch0 & 3;
    int r1l = (ch0 + 1) >> 2,  c1l = (ch0 + 1) & 3;
    uint32_t so0 = (uint32_t)(r0l * ROWB + c0l * 16);
    uint32_t so1 = (uint32_t)(r1l * ROWB + c1l * 16);

    const bf16* gAhi = Ahi + (size_t)(by) * K;
    const bf16* gAlo = (NPASS == 3) ? (Alo + (size_t)(by) * K) : nullptr;
    const bf16* gBhi = Bhi + (size_t)(bx) * K;
    const bf16* gBlo = Blo + (size_t)(bx) * K;

    float acc[4][4][4];
    #pragma unroll
    for (int i = 0; i < 4; i++)
        #pragma unroll
        for (int j = 0; j < 4; j++)
            #pragma unroll
            for (int q = 0; q < 4; q++) acc[i][j][q] = 0.f;

    int nt = K / BK;

    auto issue_tile = [&](int t, int buf) {
        uint32_t base = sb + buf * BUFSZ;
        int k0 = t * BK;
        size_t g0 = (size_t)r0l * K + k0 + c0l * 8;
        size_t g1 = (size_t)r1l * K + k0 + c1l * 8;
        cp16(base + so0,           gAhi + g0);
        cp16(base + so1,           gAhi + g1);
        if (NPASS == 3) {
            cp16(base + MTILE + so0, gAlo + g0);
            cp16(base + MTILE + so1, gAlo + g1);
        }
        cp16(base + 2*MTILE + so0, gBhi + g0);
        cp16(base + 2*MTILE + so1, gBhi + g1);
        cp16(base + 3*MTILE + so0, gBlo + g0);
        cp16(base + 3*MTILE + so1, gBlo + g1);
        asm volatile("cp.async.commit_group;" ::: "memory");
    };

    issue_tile(0, 0);

    uint32_t a_row = (uint32_t)(warp_m * 64 + (lane & 15));
    uint32_t a_cb  = (uint32_t)((lane >> 4) * 16);
    uint32_t b_row = (uint32_t)(warp_n * 32 + (lane & 7) + ((lane >> 4) & 1) * 8);
    uint32_t b_cb  = (uint32_t)(((lane >> 3) & 1) * 16);

    for (int t = 0; t < nt; t++) {
        int buf = t & 1;
        if (t + 1 < nt) {
            issue_tile(t + 1, buf ^ 1);
            asm volatile("cp.async.wait_group 1;" ::: "memory");
        } else {
            asm volatile("cp.async.wait_group 0;" ::: "memory");
        }
        __syncthreads();

        uint32_t base  = sb + buf * BUFSZ;
        uint32_t sAhi = base;
        uint32_t sAlo = base + MTILE;
        uint32_t sBhi = base + 2*MTILE;
        uint32_t sBlo = base + 3*MTILE;

        #pragma unroll
        for (int s = 0; s < 2; s++) {               // two k16 steps in BK=32
            uint32_t kb = (uint32_t)(s * 32);

            // --- load ahi + bhi, pass1: ah*bh ---
            uint32_t ahi[4][4];
            #pragma unroll
            for (int mt = 0; mt < 4; mt++)
                ldm4(ahi[mt], sAhi + (a_row + mt * 16) * ROWB + kb + a_cb);
            uint32_t bhi[2][4];
            #pragma unroll
            for (int ntp = 0; ntp < 2; ntp++)
                ldm4(bhi[ntp], sBhi + (b_row + ntp * 16) * ROWB + kb + b_cb);
            #pragma unroll
            for (int mt = 0; mt < 4; mt++)
                #pragma unroll
                for (int ntp = 0; ntp < 2; ntp++)
                    #pragma unroll
                    for (int hf = 0; hf < 2; hf++)
                        mma_bf16(acc[mt][ntp*2+hf], ahi[mt], bhi[ntp][hf*2], bhi[ntp][hf*2+1]);

            // --- load alo, pass2: al*bh (alo dies after) ---
            if (NPASS == 3) {
                uint32_t alo[4][4];
                #pragma unroll
                for (int mt = 0; mt < 4; mt++)
                    ldm4(alo[mt], sAlo + (a_row + mt * 16) * ROWB + kb + a_cb);
                #pragma unroll
                for (int mt = 0; mt < 4; mt++)
                    #pragma unroll
                    for (int ntp = 0; ntp < 2; ntp++)
                        #pragma unroll
                        for (int hf = 0; hf < 2; hf++)
                            mma_bf16(acc[mt][ntp*2+hf], alo[mt], bhi[ntp][hf*2], bhi[ntp][hf*2+1]);
            }

            // --- load blo, pass3: ah*bl ---
            uint32_t blo[2][4];
            #pragma unroll
            for (int ntp = 0; ntp < 2; ntp++)
                ldm4(blo[ntp], sBlo + (b_row + ntp * 16) * ROWB + kb + b_cb);
            #pragma unroll
            for (int mt = 0; mt < 4; mt++)
                #pragma unroll
                for (int ntp = 0; ntp < 2; ntp++)
                    #pragma unroll
                    for (int hf = 0; hf < 2; hf++)
                        mma_bf16(acc[mt][ntp*2+hf], ahi[mt], blo[ntp][hf*2], blo[ntp][hf*2+1]);
        }
        __syncthreads();
    }

    // -------- epilogue --------
    int er = by + warp_m * 64 + (lane >> 2);
    int ec = bx + warp_n * 32 + (lane & 3) * 2;
    #pragma unroll
    for (int mt = 0; mt < 4; mt++) {
        #pragma unroll
        for (int half = 0; half < 2; half++) {
            int row = er + mt * 16 + half * 8;
            #pragma unroll
            for (int ntj = 0; ntj < 4; ntj++) {
                int col = ec + ntj * 8;
                float v0 = acc[mt][ntj][half*2];
                float v1 = acc[mt][ntj][half*2+1];
                if (OP == 1) {
                    float2 rv = *(const float2*)&res[(size_t)row * N + col];
                    float2 bv = *(const float2*)&bias[col];
                    *(float2*)&C[(size_t)row * N + col] =
                        make_float2(v0 + bv.x + rv.x, v1 + bv.y + rv.y);
                } else {
                    float w0, w1;
                    if (OP == 2) {
                        float2 bv = *(const float2*)&bias[col];
                        w0 = fmaxf(v0 + bv.x, 0.0f);
                        w1 = fmaxf(v1 + bv.y, 0.0f);
                    } else {
                        w0 = v0 * scale;
                        w1 = v1 * scale;
                    }
                    bf16 h0,l0,h1,l1;
                    split_bf16(w0, h0, l0);
                    split_bf16(w1, h1, l1);
                    __nv_bfloat162 hh; hh.x = h0; hh.y = h1;
                    __nv_bfloat162 ll; ll.x = l0; ll.y = l1;
                    *(__nv_bfloat162*)&Chi[(size_t)row * N + col] = hh;
                    *(__nv_bfloat162*)&Clo[(size_t)row * N + col] = ll;
                }
            }
        }
    }
}

// ======================= Tensor-core causal flash attention ====================
// QK^T 3-pass hi/lo. PV: P single-pass bf16 x V hi/lo (2-pass). (R6-validated)
#define AROWB 144
#define ATILE (128*AROWB)
#define ASM_QHI 0
#define ASM_QLO ATILE
#define ASM_KV  (2*ATILE)
#define AKV_KHI 0
#define AKV_KLO ATILE
#define AKV_VHI (2*ATILE)
#define AKV_VLO (3*ATILE)
#define AKVSTAGE (4*ATILE)
#define ASMEM (2*ATILE + 2*AKVSTAGE)

__global__ __launch_bounds__(256, 1) void attn_tc(
    const bf16* __restrict__ Qhi, const bf16* __restrict__ Qlo,
    const bf16* __restrict__ Khi, const bf16* __restrict__ Klo,
    const bf16* __restrict__ Vhi, const bf16* __restrict__ Vlo,
    bf16* __restrict__ Yhi, bf16* __restrict__ Ylo)
{
    extern __shared__ __align__(128) unsigned char asmem[];
    uint32_t sb = s2u(asmem);
    int tid = threadIdx.x, lane = tid & 31, wid = tid >> 5;
    int qt = blockIdx.x, bh = blockIdx.y;
    int b = bh >> 4, h = bh & 15;

    size_t rowbase = (size_t)b * T_;
    size_t qoff = (rowbase + qt * 128) * E_ + h * HS_;

    int chb = tid * 4;
    int lrow[4], lch[4];
    uint32_t soff[4];
    #pragma unroll
    for (int i = 0; i < 4; i++) {
        lrow[i] = (chb + i) >> 3;
        lch[i]  = (chb + i) & 7;
        soff[i] = (uint32_t)(lrow[i] * AROWB + lch[i] * 16);
    }

    #pragma unroll
    for (int i = 0; i < 4; i++) {
        size_t g = qoff + (size_t)lrow[i] * E_ + lch[i] * 8;
        cp16(sb + ASM_QHI + soff[i], Qhi + g);
        cp16(sb + ASM_QLO + soff[i], Qlo + g);
    }
    asm volatile("cp.async.commit_group;" ::: "memory");

    auto load_kv = [&](int kt, int buf) {
        size_t ko = (rowbase + kt * 128) * E_ + h * HS_;
        uint32_t base = sb + ASM_KV + buf * AKVSTAGE;
        #pragma unroll
        for (int i = 0; i < 4; i++) {
            size_t g = ko + (size_t)lrow[i] * E_ + lch[i] * 8;
            cp16(base + AKV_KHI + soff[i], Khi + g);
            cp16(base + AKV_KLO + soff[i], Klo + g);
            cp16(base + AKV_VHI + soff[i], Vhi + g);
            cp16(base + AKV_VLO + soff[i], Vlo + g);
        }
        asm volatile("cp.async.commit_group;" ::: "memory");
    };
    load_kv(0, 0);

    asm volatile("cp.async.wait_group 1;" ::: "memory");
    __syncthreads();

    uint32_t a_row = (uint32_t)(wid * 16 + (lane & 15));
    uint32_t a_cb  = (uint32_t)((lane >> 4) * 16);
    uint32_t qfh[4][4], qfl[4][4];
    #pragma unroll
    for (int s = 0; s < 4; s++) {
        uint32_t ao = a_row * AROWB + s * 32 + a_cb;
        ldm4(qfh[s], sb + ASM_QHI + ao);
        ldm4(qfl[s], sb + ASM_QLO + ao);
    }

    float oacc[8][4];
    #pragma unroll
    for (int i = 0; i < 8; i++)
        #pragma unroll
        for (int j = 0; j < 4; j++) oacc[i][j] = 0.f;
    float m0 = -1e30f, m1 = -1e30f, l0 = 0.f, l1 = 0.f;

    uint32_t b_rowo = (uint32_t)((lane & 7) + ((lane >> 4) & 1) * 8);
    uint32_t b_cbo  = (uint32_t)(((lane >> 3) & 1) * 16);
    uint32_t v_rowo = (uint32_t)(lane & 15);
    uint32_t v_cbo  = (uint32_t)(((lane >> 4) & 1) * 16);

    for (int kt = 0; kt <= qt; kt++) {
        int buf = kt & 1;
        if (kt < qt) {
            load_kv(kt + 1, buf ^ 1);
            asm volatile("cp.async.wait_group 1;" ::: "memory");
        } else {
            asm volatile("cp.async.wait_group 0;" ::: "memory");
        }
        __syncthreads();
        uint32_t kb = sb + ASM_KV + buf * AKVSTAGE;

        // ---- S = Q K^T (3-pass hi/lo) ----
        float sacc[16][4];
        #pragma unroll
        for (int j = 0; j < 16; j++)
            #pragma unroll
            for (int q = 0; q < 4; q++) sacc[j][q] = 0.f;

        #pragma unroll
        for (int g = 0; g < 2; g++) {
            #pragma unroll
            for (int s = 0; s < 4; s++) {
                uint32_t kfh[4][4], kfl[4][4];
                #pragma unroll
                for (int np = 0; np < 4; np++) {
                    uint32_t bo = (uint32_t)(g * 64 + np * 16 + b_rowo) * AROWB + s * 32 + b_cbo;
                    ldm4(kfh[np], kb + AKV_KHI + bo);
                    ldm4(kfl[np], kb + AKV_KLO + bo);
                }
                #pragma unroll
                for (int np = 0; np < 4; np++)
                    #pragma unroll
                    for (int hf = 0; hf < 2; hf++)
                        mma_bf16(sacc[g*8+np*2+hf], qfh[s], kfh[np][hf*2], kfh[np][hf*2+1]);
                #pragma unroll
                for (int np = 0; np < 4; np++)
                    #pragma unroll
                    for (int hf = 0; hf < 2; hf++)
                        mma_bf16(sacc[g*8+np*2+hf], qfh[s], kfl[np][hf*2], kfl[np][hf*2+1]);
                #pragma unroll
                for (int np = 0; np < 4; np++)
                    #pragma unroll
                    for (int hf = 0; hf < 2; hf++)
                        mma_bf16(sacc[g*8+np*2+hf], qfl[s], kfh[np][hf*2], kfh[np][hf*2+1]);
            }
        }

        if (kt == qt) {
            int qr0 = wid * 16 + (lane >> 2);
            int kc  = (lane & 3) * 2;
            #pragma unroll
            for (int j = 0; j < 16; j++) {
                int k0i = j * 8 + kc;
                if (k0i     > qr0)     sacc[j][0] = -1e30f;
                if (k0i + 1 > qr0)     sacc[j][1] = -1e30f;
                if (k0i     > qr0 + 8) sacc[j][2] = -1e30f;
                if (k0i + 1 > qr0 + 8) sacc[j][3] = -1e30f;
            }
        }

        // ---- online softmax ----
        float mx0 = m0, mx1 = m1;
        #pragma unroll
        for (int j = 0; j < 16; j++) {
            mx0 = fmaxf(mx0, fmaxf(sacc[j][0], sacc[j][1]));
            mx1 = fmaxf(mx1, fmaxf(sacc[j][2], sacc[j][3]));
        }
        mx0 = fmaxf(mx0, __shfl_xor_sync(0xFFFFFFFFu, mx0, 1));
        mx0 = fmaxf(mx0, __shfl_xor_sync(0xFFFFFFFFu, mx0, 2));
        mx1 = fmaxf(mx1, __shfl_xor_sync(0xFFFFFFFFu, mx1, 1));
        mx1 = fmaxf(mx1, __shfl_xor_sync(0xFFFFFFFFu, mx1, 2));
        float cor0 = __expf(m0 - mx0);
        float cor1 = __expf(m1 - mx1);
        m0 = mx0; m1 = mx1;
        float rs0 = 0.f, rs1 = 0.f;
        #pragma unroll
        for (int j = 0; j < 16; j++) {
            float p0 = __expf(sacc[j][0] - m0);
            float p1 = __expf(sacc[j][1] - m0);
            float p2 = __expf(sacc[j][2] - m1);
            float p3 = __expf(sacc[j][3] - m1);
            sacc[j][0] = p0; sacc[j][1] = p1; sacc[j][2] = p2; sacc[j][3] = p3;
            rs0 += p0 + p1; rs1 += p2 + p3;
        }
        rs0 += __shfl_xor_sync(0xFFFFFFFFu, rs0, 1);
        rs0 += __shfl_xor_sync(0xFFFFFFFFu, rs0, 2);
        rs1 += __shfl_xor_sync(0xFFFFFFFFu, rs1, 1);
        rs1 += __shfl_xor_sync(0xFFFFFFFFu, rs1, 2);
        l0 = l0 * cor0 + rs0;
        l1 = l1 * cor1 + rs1;
        #pragma unroll
        for (int dt = 0; dt < 8; dt++) {
            oacc[dt][0] *= cor0; oacc[dt][1] *= cor0;
            oacc[dt][2] *= cor1; oacc[dt][3] *= cor1;
        }

        // ---- O += P V ----
        #pragma unroll
        for (int s = 0; s < 8; s++) {
            uint32_t pah[4];
            #pragma unroll
            for (int tt = 0; tt < 2; tt++) {
                const float* sc = sacc[2*s + tt];
                pah[tt*2+0] = packbf(sc[0], sc[1]);
                pah[tt*2+1] = packbf(sc[2], sc[3]);
            }
            uint32_t vfh[4][4], vfl[4][4];
            #pragma unroll
            for (int dc = 0; dc < 4; dc++) {
                uint32_t vo = (uint32_t)(s * 16 + v_rowo) * AROWB + dc * 32 + v_cbo;
                ldm4t(vfh[dc], kb + AKV_VHI + vo);
                ldm4t(vfl[dc], kb + AKV_VLO + vo);
            }
            #pragma unroll
            for (int dc = 0; dc < 4; dc++) {
                mma_bf16(oacc[dc*2+0], pah, vfh[dc][0], vfh[dc][1]);
                mma_bf16(oacc[dc*2+1], pah, vfh[dc][2], vfh[dc][3]);
            }
            #pragma unroll
            for (int dc = 0; dc < 4; dc++) {
                mma_bf16(oacc[dc*2+0], pah, vfl[dc][0], vfl[dc][1]);
                mma_bf16(oacc[dc*2+1], pah, vfl[dc][2], vfl[dc][3]);
            }
        }
        __syncthreads();
    }

    float inv0 = 1.0f / l0;
    float inv1 = 1.0f / l1;
    int qr = qt * 128 + wid * 16 + (lane >> 2);
    size_t y0 = (rowbase + qr) * E_ + h * HS_ + (lane & 3) * 2;
    size_t y1 = y0 + (size_t)8 * E_;
    #pragma unroll
    for (int dt = 0; dt < 8; dt++) {
        float w0 = oacc[dt][0] * inv0, w1 = oacc[dt][1] * inv0;
        float w2 = oacc[dt][2] * inv1, w3 = oacc[dt][3] * inv1;
        bf16 h0,lo0,h1,lo1,h2,lo2,h3,lo3;
        split_bf16(w0,h0,lo0); split_bf16(w1,h1,lo1);
        split_bf16(w2,h2,lo2); split_bf16(w3,h3,lo3);
        __nv_bfloat162 hh0; hh0.x=h0; hh0.y=h1;
        __nv_bfloat162 ll0; ll0.x=lo0; ll0.y=lo1;
        __nv_bfloat162 hh1; hh1.x=h2; hh1.y=h3;
        __nv_bfloat162 ll1; ll1.x=lo2; ll1.y=lo3;
        *(__nv_bfloat162*)(Yhi + y0 + dt*8) = hh0;
        *(__nv_bfloat162*)(Ylo + y0 + dt*8) = ll0;
        *(__nv_bfloat162*)(Yhi + y1 + dt*8) = hh1;
        *(__nv_bfloat162*)(Ylo + y1 + dt*8) = ll1;
    }
}

// ======================= launch =======================
extern "C" void kernel_launch(void* const* d_in, const int* in_sizes, int n_in,
                              void* d_out, int out_size)
{
    const float* x    = (const float*)d_in[0];
    const float* Wq   = (const float*)d_in[1];
    const float* Wk   = (const float*)d_in[2];
    const float* Wv   = (const float*)d_in[3];
    const float* Wo   = (const float*)d_in[4];
    const float* bo   = (const float*)d_in[5];
    const float* ln1w = (const float*)d_in[6];
    const float* ln2w = (const float*)d_in[7];
    const float* W1   = (const float*)d_in[8];
    const float* b1   = (const float*)d_in[9];
    const float* W2   = (const float*)d_in[10];
    const float* b2   = (const float*)d_in[11];
    float* out = (float*)d_out;

    unsigned char* pool;
    cudaGetSymbolAddress((void**)&pool, g_pool);

    bf16*  hhi  = (bf16*)(pool + O_HHI);
    bf16*  hlo  = (bf16*)(pool + O_HLO);
    bf16*  qhi  = (bf16*)(pool + O_QHI), *qlo = (bf16*)(pool + O_QLO);
    bf16*  khi  = (bf16*)(pool + O_KHI), *klo = (bf16*)(pool + O_KLO);
    bf16*  vhi  = (bf16*)(pool + O_VHI), *vlo = (bf16*)(pool + O_VLO);
    bf16*  yhi  = (bf16*)(pool + O_YHI), *ylo = (bf16*)(pool + O_YLO);
    float* x2   = (float*)(pool + O_X2);
    bf16*  ffhi = (bf16*)(pool + O_FFHI);
    bf16*  fflo = (bf16*)(pool + O_FFLO);
    bf16*  wqh = (bf16*)(pool + O_WQH), *wql = (bf16*)(pool + O_WQL);
    bf16*  wkh = (bf16*)(pool + O_WKH), *wkl = (bf16*)(pool + O_WKL);
    bf16*  wvh = (bf16*)(pool + O_WVH), *wvl = (bf16*)(pool + O_WVL);
    bf16*  woh = (bf16*)(pool + O_WOH), *wol = (bf16*)(pool + O_WOL);
    bf16*  w1h = (bf16*)(pool + O_W1H), *w1l = (bf16*)(pool + O_W1L);
    bf16*  w2h = (bf16*)(pool + O_W2H), *w2l = (bf16*)(pool + O_W2L);

    cudaFuncSetAttribute((const void*)gemm_tc<1,3>, cudaFuncAttributeMaxDynamicSharedMemorySize, SMEM_SZ);
    cudaFuncSetAttribute((const void*)gemm_tc<2,3>, cudaFuncAttributeMaxDynamicSharedMemorySize, SMEM_SZ);
    cudaFuncSetAttribute((const void*)gemm_tc<3,3>, cudaFuncAttributeMaxDynamicSharedMemorySize, SMEM_SZ);
    cudaFuncSetAttribute((const void*)attn_tc,      cudaFuncAttributeMaxDynamicSharedMemorySize, ASMEM);

    dim3 tb(32, 8);
    dim3 gE (E_  / BN, M_ / BM);       // (8, 64)
    dim3 gQKV(3 * (E_ / BN), M_ / BM); // (24, 64)
    dim3 g4E(FF_ / BN, M_ / BM);       // (32, 64)

    // 1-4) weight splits needed before QKV/Wo GEMMs
    wsplit_kernel<<<dim3(E_/32,  E_/32),  tb>>>(Wq, wqh, wql, E_,  E_);
    wsplit_kernel<<<dim3(E_/32,  E_/32),  tb>>>(Wk, wkh, wkl, E_,  E_);
    wsplit_kernel<<<dim3(E_/32,  E_/32),  tb>>>(Wv, wvh, wvl, E_,  E_);
    wsplit_kernel<<<dim3(E_/32,  E_/32),  tb>>>(Wo, woh, wol, E_,  E_);
    // 5) h = LN1(x)
    ln_split_kernel<<<M_, 256>>>(x, ln1w, hhi, hlo);
    // 6) fused q,k,v projections (3-pass) -> bf16 hi/lo
    gemm_tc<3,3><<<gQKV, 256, SMEM_SZ>>>(hhi, hlo,
        wqh, wql, wkh, wkl, wvh, wvl,
        nullptr, nullptr, nullptr,
        qhi, qlo, khi, klo, vhi, vlo, M_, E_, E_);
    // 7) y = causal attention (QK^T 3-pass, PV 2-pass w/ bf16 P)
    attn_tc<<<dim3(T_/128, B_*H_), 256, ASMEM>>>(qhi, qlo, khi, klo, vhi, vlo, yhi, ylo);
    // 8-9) MLP weight splits
    wsplit_kernel<<<dim3(FF_/32, E_/32),  tb>>>(W1, w1h, w1l, E_,  FF_);
    wsplit_kernel<<<dim3(E_/32,  FF_/32), tb>>>(W2, w2h, w2l, FF_, E_);
    // 10) x2 = x + y @ Wo + bo (3-pass)
    gemm_tc<1,3><<<gE, 256, SMEM_SZ>>>(yhi, ylo,
        woh, wol, woh, wol, woh, wol,
        bo, x, x2,
        nullptr, nullptr, nullptr, nullptr, nullptr, nullptr, M_, E_, E_);
    // 11) h2 = LN2(x2)
    ln_split_kernel<<<M_, 256>>>(x2, ln2w, hhi, hlo);
    // 12) ff = relu(h2 @ W1 + b1)  (3-pass)
    gemm_tc<2,3><<<g4E, 256, SMEM_SZ>>>(hhi, hlo,
        w1h, w1l, w1h, w1l, w1h, w1l,
        b1, nullptr, nullptr,
        ffhi, fflo, nullptr, nullptr, nullptr, nullptr, M_, FF_, E_);
    // 13) out = x2 + ff @ W2 + b2  (3-pass)
    gemm_tc<1,3><<<gE, 256, SMEM_SZ>>>(ffhi, fflo,
        w2h, w2l, w2h, w2l, w2h, w2l,
        b2, x2, out,
        nullptr, nullptr, nullptr, nullptr, nullptr, nullptr, M_, E_, FF_);
}

// round 12
// speedup vs baseline: 2.6693x; 1.0127x over previous
#include <cuda_runtime.h>
#include <cuda_bf16.h>
#include <cstdint>

#define B_  4
#define T_  2048
#define E_  1024
#define H_  16
#define HS_ 64
#define M_  (B_*T_)    // 8192
#define FF_ (4*E_)     // 4096

typedef unsigned long long u64;
typedef __nv_bfloat16 bf16;

// ======================= scratch pool (__device__ global) =======================
#define SZ_HB   ((size_t)M_*E_*2)
#define SZ_F32  ((size_t)M_*E_*4)
#define SZ_FFB  ((size_t)M_*FF_*2)
#define SZ_WB   ((size_t)E_*E_*2)
#define SZ_W1B  ((size_t)E_*FF_*2)

constexpr size_t O_HHI  = 0;
constexpr size_t O_HLO  = O_HHI  + SZ_HB;
constexpr size_t O_QHI  = O_HLO  + SZ_HB;
constexpr size_t O_QLO  = O_QHI  + SZ_HB;
constexpr size_t O_KHI  = O_QLO  + SZ_HB;
constexpr size_t O_KLO  = O_KHI  + SZ_HB;
constexpr size_t O_VHI  = O_KLO  + SZ_HB;
constexpr size_t O_VLO  = O_VHI  + SZ_HB;
constexpr size_t O_YHI  = O_VLO  + SZ_HB;
constexpr size_t O_YLO  = O_YHI  + SZ_HB;
constexpr size_t O_X2   = O_YLO  + SZ_HB;
constexpr size_t O_FFHI = O_X2   + SZ_F32;
constexpr size_t O_FFLO = O_FFHI + SZ_FFB;
constexpr size_t O_WQH  = O_FFLO + SZ_FFB;
constexpr size_t O_WQL  = O_WQH  + SZ_WB;
constexpr size_t O_WKH  = O_WQL  + SZ_WB;
constexpr size_t O_WKL  = O_WKH  + SZ_WB;
constexpr size_t O_WVH  = O_WKL  + SZ_WB;
constexpr size_t O_WVL  = O_WVH  + SZ_WB;
constexpr size_t O_WOH  = O_WVL  + SZ_WB;
constexpr size_t O_WOL  = O_WOH  + SZ_WB;
constexpr size_t O_W1H  = O_WOL  + SZ_WB;
constexpr size_t O_W1L  = O_W1H  + SZ_W1B;
constexpr size_t O_W2H  = O_W1L  + SZ_W1B;
constexpr size_t O_W2L  = O_W2H  + SZ_W1B;
constexpr size_t POOLSZ = O_W2L  + SZ_W1B;

__device__ __align__(1024) unsigned char g_pool[POOLSZ];

// ======================= PTX helpers =======================
__device__ __forceinline__ uint32_t s2u(const void* p){
    uint32_t a;
    asm("{ .reg .u64 t; cvta.to.shared.u64 t, %1; cvt.u32.u64 %0, t; }" : "=r"(a) : "l"(p));
    return a;
}
__device__ __forceinline__ void cp16(uint32_t s, const void* g){
    asm volatile("cp.async.cg.shared.global [%0], [%1], 16;" :: "r"(s), "l"(g));
}
__device__ __forceinline__ void ldm4(uint32_t (&r)[4], uint32_t a){
    asm volatile("ldmatrix.sync.aligned.m8n8.x4.shared.b16 {%0,%1,%2,%3}, [%4];"
                 : "=r"(r[0]), "=r"(r[1]), "=r"(r[2]), "=r"(r[3]) : "r"(a));
}
__device__ __forceinline__ void ldm4t(uint32_t (&r)[4], uint32_t a){
    asm volatile("ldmatrix.sync.aligned.m8n8.x4.trans.shared.b16 {%0,%1,%2,%3}, [%4];"
                 : "=r"(r[0]), "=r"(r[1]), "=r"(r[2]), "=r"(r[3]) : "r"(a));
}
__device__ __forceinline__ void mma_bf16(float (&c)[4], const uint32_t* a, uint32_t b0, uint32_t b1){
    asm volatile(
        "mma.sync.aligned.m16n8k16.row.col.f32.bf16.bf16.f32 "
        "{%0,%1,%2,%3}, {%4,%5,%6,%7}, {%8,%9}, {%0,%1,%2,%3};"
        : "+f"(c[0]), "+f"(c[1]), "+f"(c[2]), "+f"(c[3])
        : "r"(a[0]), "r"(a[1]), "r"(a[2]), "r"(a[3]), "r"(b0), "r"(b1));
}
__device__ __forceinline__ uint32_t packbf(float lo_val, float hi_val){
    uint32_t r;
    asm("cvt.rn.bf16x2.f32 %0, %1, %2;" : "=r"(r) : "f"(hi_val), "f"(lo_val));
    return r;
}
__device__ __forceinline__ void split_bf16(float v, bf16 &hi, bf16 &lo){
    hi = __float2bfloat16(v);
    lo = __float2bfloat16(v - __bfloat162float(hi));
}

// ======================= LayerNorm -> bf16 hi/lo splits =======================
__global__ __launch_bounds__(256) void ln_split_kernel(
    const float* __restrict__ X, const float* __restrict__ w,
    bf16* __restrict__ Ohi, bf16* __restrict__ Olo)
{
    int row = blockIdx.x;
    int tid = threadIdx.x;
    const float* x = X + (size_t)row * E_;

    float4 v = *(const float4*)(x + tid * 4);
    float s  = v.x + v.y + v.z + v.w;
    float sq = v.x*v.x + v.y*v.y + v.z*v.z + v.w*v.w;

    #pragma unroll
    for (int o = 16; o; o >>= 1) {
        s  += __shfl_xor_sync(0xFFFFFFFFu, s,  o);
        sq += __shfl_xor_sync(0xFFFFFFFFu, sq, o);
    }
    __shared__ float ss[8], ssq[8], red[2];
    int wid = tid >> 5, lane = tid & 31;
    if (lane == 0) { ss[wid] = s; ssq[wid] = sq; }
    __syncthreads();
    if (tid == 0) {
        float a = 0.f, b = 0.f;
        #pragma unroll
        for (int i = 0; i < 8; i++) { a += ss[i]; b += ssq[i]; }
        float mean = a * (1.0f / E_);
        float var  = b * (1.0f / E_) - mean * mean;
        red[0] = mean;
        red[1] = rsqrtf(var + 1e-5f);
    }
    __syncthreads();
    float mean = red[0], rs = red[1];
    float4 wv = *(const float4*)(w + tid * 4);
    float o0 = (v.x - mean) * rs * wv.x;
    float o1 = (v.y - mean) * rs * wv.y;
    float o2 = (v.z - mean) * rs * wv.z;
    float o3 = (v.w - mean) * rs * wv.w;

    bf16 h0,h1,h2,h3,l0,l1,l2,l3;
    split_bf16(o0,h0,l0); split_bf16(o1,h1,l1);
    split_bf16(o2,h2,l2); split_bf16(o3,h3,l3);
    size_t off = (size_t)row * E_ + tid * 4;
    __nv_bfloat162 ph0; ph0.x=h0; ph0.y=h1;
    __nv_bfloat162 ph1; ph1.x=h2; ph1.y=h3;
    __nv_bfloat162 pl0; pl0.x=l0; pl0.y=l1;
    __nv_bfloat162 pl1; pl1.x=l2; pl1.y=l3;
    *(__nv_bfloat162*)(Ohi + off)     = ph0;
    *(__nv_bfloat162*)(Ohi + off + 2) = ph1;
    *(__nv_bfloat162*)(Olo + off)     = pl0;
    *(__nv_bfloat162*)(Olo + off + 2) = pl1;
}

// ======================= weight transpose + split =======================
__global__ __launch_bounds__(256) void wsplit_kernel(
    const float* __restrict__ W, bf16* __restrict__ Whi, bf16* __restrict__ Wlo,
    int K, int N)
{
    __shared__ float t[32][33];
    int n0 = blockIdx.x * 32, k0 = blockIdx.y * 32;
    int tx = threadIdx.x, ty0 = threadIdx.y;
    #pragma unroll
    for (int dy = 0; dy < 32; dy += 8) {
        int ty = ty0 + dy;
        t[ty][tx] = W[(size_t)(k0 + ty) * N + n0 + tx];
    }
    __syncthreads();
    #pragma unroll
    for (int dy = 0; dy < 32; dy += 8) {
        int ty = ty0 + dy;
        float v = t[tx][ty];
        bf16 hi, lo; split_bf16(v, hi, lo);
        size_t o = (size_t)(n0 + ty) * K + k0 + tx;
        Whi[o] = hi;
        Wlo[o] = lo;
    }
}

// ======================= HMMA GEMM (bf16 split, fp32 accum) ============
// BK=32, 80KB smem, __launch_bounds__(256,2) -> 2 CTAs/SM.  (R10-validated)
#define BM 128
#define BN 128
#define BK 32
#define ROWB   80
#define MTILE  (128*ROWB)     // 10240
#define BUFSZ  (4*MTILE)      // 40960
#define SMEM_SZ (2*BUFSZ)     // 81920

template<int OP, int NPASS>
__global__ __launch_bounds__(256, 2) void gemm_tc(
    const bf16* __restrict__ Ahi, const bf16* __restrict__ Alo,
    const bf16* __restrict__ B0h, const bf16* __restrict__ B0l,
    const bf16* __restrict__ B1h, const bf16* __restrict__ B1l,
    const bf16* __restrict__ B2h, const bf16* __restrict__ B2l,
    const float* __restrict__ bias, const float* __restrict__ res,
    float* __restrict__ C,
    bf16* __restrict__ C0h, bf16* __restrict__ C0l,
    bf16* __restrict__ C1h, bf16* __restrict__ C1l,
    bf16* __restrict__ C2h, bf16* __restrict__ C2l,
    int M, int N, int K)
{
    extern __shared__ __align__(128) unsigned char smem[];
    uint32_t sb = s2u(smem);
    int tid = threadIdx.x;
    int lane = tid & 31, wid = tid >> 5;
    int warp_m = wid & 1, warp_n = wid >> 1;

    int sel = 0, bxi = blockIdx.x;
    if (OP == 3) { sel = blockIdx.x >> 3; bxi = blockIdx.x & 7; }
    int bx = bxi * BN, by = blockIdx.y * BM;

    const bf16* Bhi = (OP == 3) ? (sel == 0 ? B0h : sel == 1 ? B1h : B2h) : B0h;
    const bf16* Blo = (OP == 3) ? (sel == 0 ? B0l : sel == 1 ? B1l : B2l) : B0l;
    bf16* Chi = (OP == 3) ? (sel == 0 ? C0h : sel == 1 ? C1h : C2h) : C0h;
    bf16* Clo = (OP == 3) ? (sel == 0 ? C0l : sel == 1 ? C1l : C2l) : C0l;
    float scale = (OP == 3 && sel == 0) ? 0.03125f : 1.0f;

    int ch0 = tid * 2;
    int r0l = ch0 >> 2,        c0l = ch0 & 3;
    int r1l = (ch0 + 1) >> 2,  c1l = (ch0 + 1) & 3;
    uint32_t so0 = (uint32_t)(r0l * ROWB + c0l * 16);
    uint32_t so1 = (uint32_t)(r1l * ROWB + c1l * 16);

    const bf16* gAhi = Ahi + (size_t)(by) * K;
    const bf16* gAlo = (NPASS == 3) ? (Alo + (size_t)(by) * K) : nullptr;
    const bf16* gBhi = Bhi + (size_t)(bx) * K;
    const bf16* gBlo = Blo + (size_t)(bx) * K;

    float acc[4][4][4];
    #pragma unroll
    for (int i = 0; i < 4; i++)
        #pragma unroll
        for (int j = 0; j < 4; j++)
            #pragma unroll
            for (int q = 0; q < 4; q++) acc[i][j][q] = 0.f;

    int nt = K / BK;

    auto issue_tile = [&](int t, int buf) {
        uint32_t base = sb + buf * BUFSZ;
        int k0 = t * BK;
        size_t g0 = (size_t)r0l * K + k0 + c0l * 8;
        size_t g1 = (size_t)r1l * K + k0 + c1l * 8;
        cp16(base + so0,           gAhi + g0);
        cp16(base + so1,           gAhi + g1);
        if (NPASS == 3) {
            cp16(base + MTILE + so0, gAlo + g0);
            cp16(base + MTILE + so1, gAlo + g1);
        }
        cp16(base + 2*MTILE + so0, gBhi + g0);
        cp16(base + 2*MTILE + so1, gBhi + g1);
        cp16(base + 3*MTILE + so0, gBlo + g0);
        cp16(base + 3*MTILE + so1, gBlo + g1);
        asm volatile("cp.async.commit_group;" ::: "memory");
    };

    issue_tile(0, 0);

    uint32_t a_row = (uint32_t)(warp_m * 64 + (lane & 15));
    uint32_t a_cb  = (uint32_t)((lane >> 4) * 16);
    uint32_t b_row = (uint32_t)(warp_n * 32 + (lane & 7) + ((lane >> 4) & 1) * 8);
    uint32_t b_cb  = (uint32_t)(((lane >> 3) & 1) * 16);

    for (int t = 0; t < nt; t++) {
        int buf = t & 1;
        if (t + 1 < nt) {
            issue_tile(t + 1, buf ^ 1);
            asm volatile("cp.async.wait_group 1;" ::: "memory");
        } else {
            asm volatile("cp.async.wait_group 0;" ::: "memory");
        }
        __syncthreads();

        uint32_t base  = sb + buf * BUFSZ;
        uint32_t sAhi = base;
        uint32_t sAlo = base + MTILE;
        uint32_t sBhi = base + 2*MTILE;
        uint32_t sBlo = base + 3*MTILE;

        #pragma unroll
        for (int s = 0; s < 2; s++) {
            uint32_t kb = (uint32_t)(s * 32);

            uint32_t ahi[4][4];
            #pragma unroll
            for (int mt = 0; mt < 4; mt++)
                ldm4(ahi[mt], sAhi + (a_row + mt * 16) * ROWB + kb + a_cb);
            uint32_t bhi[2][4];
            #pragma unroll
            for (int ntp = 0; ntp < 2; ntp++)
                ldm4(bhi[ntp], sBhi + (b_row + ntp * 16) * ROWB + kb + b_cb);
            #pragma unroll
            for (int mt = 0; mt < 4; mt++)
                #pragma unroll
                for (int ntp = 0; ntp < 2; ntp++)
                    #pragma unroll
                    for (int hf = 0; hf < 2; hf++)
                        mma_bf16(acc[mt][ntp*2+hf], ahi[mt], bhi[ntp][hf*2], bhi[ntp][hf*2+1]);

            if (NPASS == 3) {
                uint32_t alo[4][4];
                #pragma unroll
                for (int mt = 0; mt < 4; mt++)
                    ldm4(alo[mt], sAlo + (a_row + mt * 16) * ROWB + kb + a_cb);
                #pragma unroll
                for (int mt = 0; mt < 4; mt++)
                    #pragma unroll
                    for (int ntp = 0; ntp < 2; ntp++)
                        #pragma unroll
                        for (int hf = 0; hf < 2; hf++)
                            mma_bf16(acc[mt][ntp*2+hf], alo[mt], bhi[ntp][hf*2], bhi[ntp][hf*2+1]);
            }

            uint32_t blo[2][4];
            #pragma unroll
            for (int ntp = 0; ntp < 2; ntp++)
                ldm4(blo[ntp], sBlo + (b_row + ntp * 16) * ROWB + kb + b_cb);
            #pragma unroll
            for (int mt = 0; mt < 4; mt++)
                #pragma unroll
                for (int ntp = 0; ntp < 2; ntp++)
                    #pragma unroll
                    for (int hf = 0; hf < 2; hf++)
                        mma_bf16(acc[mt][ntp*2+hf], ahi[mt], blo[ntp][hf*2], blo[ntp][hf*2+1]);
        }
        __syncthreads();
    }

    // -------- epilogue --------
    int er = by + warp_m * 64 + (lane >> 2);
    int ec = bx + warp_n * 32 + (lane & 3) * 2;
    #pragma unroll
    for (int mt = 0; mt < 4; mt++) {
        #pragma unroll
        for (int half = 0; half < 2; half++) {
            int row = er + mt * 16 + half * 8;
            #pragma unroll
            for (int ntj = 0; ntj < 4; ntj++) {
                int col = ec + ntj * 8;
                float v0 = acc[mt][ntj][half*2];
                float v1 = acc[mt][ntj][half*2+1];
                if (OP == 1) {
                    float2 rv = *(const float2*)&res[(size_t)row * N + col];
                    float2 bv = *(const float2*)&bias[col];
                    *(float2*)&C[(size_t)row * N + col] =
                        make_float2(v0 + bv.x + rv.x, v1 + bv.y + rv.y);
                } else {
                    float w0, w1;
                    if (OP == 2) {
                        float2 bv = *(const float2*)&bias[col];
                        w0 = fmaxf(v0 + bv.x, 0.0f);
                        w1 = fmaxf(v1 + bv.y, 0.0f);
                    } else {
                        w0 = v0 * scale;
                        w1 = v1 * scale;
                    }
                    bf16 h0,l0,h1,l1;
                    split_bf16(w0, h0, l0);
                    split_bf16(w1, h1, l1);
                    __nv_bfloat162 hh; hh.x = h0; hh.y = h1;
                    __nv_bfloat162 ll; ll.x = l0; ll.y = l1;
                    *(__nv_bfloat162*)&Chi[(size_t)row * N + col] = hh;
                    *(__nv_bfloat162*)&Clo[(size_t)row * N + col] = ll;
                }
            }
        }
    }
}

// ======================= Tensor-core causal flash attention ====================
// 64-key KV tiles, double-buffered; 110.6KB smem -> 2 CTAs/SM (256 thr, 128 regs).
// QK^T 3-pass hi/lo; PV: P single-pass bf16 x V hi/lo.
#define AROWB 144
#define AQTILE (128*AROWB)    // 18432
#define AKTILE (64*AROWB)     // 9216
#define ASM_QHI 0
#define ASM_QLO AQTILE
#define ASM_KV  (2*AQTILE)
#define AKV_KHI 0
#define AKV_KLO AKTILE
#define AKV_VHI (2*AKTILE)
#define AKV_VLO (3*AKTILE)
#define AKVSTAGE (4*AKTILE)   // 36864
#define ASMEM (2*AQTILE + 2*AKVSTAGE)  // 110592

__global__ __launch_bounds__(256, 2) void attn_tc(
    const bf16* __restrict__ Qhi, const bf16* __restrict__ Qlo,
    const bf16* __restrict__ Khi, const bf16* __restrict__ Klo,
    const bf16* __restrict__ Vhi, const bf16* __restrict__ Vlo,
    bf16* __restrict__ Yhi, bf16* __restrict__ Ylo)
{
    extern __shared__ __align__(128) unsigned char asmem[];
    uint32_t sb = s2u(asmem);
    int tid = threadIdx.x, lane = tid & 31, wid = tid >> 5;
    int qt = blockIdx.x, bh = blockIdx.y;
    int b = bh >> 4, h = bh & 15;

    size_t rowbase = (size_t)b * T_;
    size_t qoff = (rowbase + qt * 128) * E_ + h * HS_;

    // Q loader: 128 rows x 8 chunks = 1024 chunks; 4 chunks/thread
    {
        int chb = tid * 4;
        #pragma unroll
        for (int i = 0; i < 4; i++) {
            int lr = (chb + i) >> 3;
            int lc = (chb + i) & 7;
            uint32_t so = (uint32_t)(lr * AROWB + lc * 16);
            size_t g = qoff + (size_t)lr * E_ + lc * 8;
            cp16(sb + ASM_QHI + so, Qhi + g);
            cp16(sb + ASM_QLO + so, Qlo + g);
        }
    }
    asm volatile("cp.async.commit_group;" ::: "memory");

    // KV loader: 64 rows x 8 chunks = 512 chunks per matrix; 2 chunks/thread (same row)
    int kv_row = tid >> 2;                       // 0..63
    int kv_c   = (tid & 3) * 2;                  // 0,2,4,6 (16B chunk pairs)
    uint32_t kv_so = (uint32_t)(kv_row * AROWB + kv_c * 16);

    auto load_kv = [&](int kt, int buf) {
        size_t ko = (rowbase + kt * 64 + kv_row) * E_ + h * HS_ + kv_c * 8;
        uint32_t base = sb + ASM_KV + buf * AKVSTAGE + kv_so;
        cp16(base + AKV_KHI,      Khi + ko);
        cp16(base + AKV_KHI + 16, Khi + ko + 8);
        cp16(base + AKV_KLO,      Klo + ko);
        cp16(base + AKV_KLO + 16, Klo + ko + 8);
        cp16(base + AKV_VHI,      Vhi + ko);
        cp16(base + AKV_VHI + 16, Vhi + ko + 8);
        cp16(base + AKV_VLO,      Vlo + ko);
        cp16(base + AKV_VLO + 16, Vlo + ko + 8);
        asm volatile("cp.async.commit_group;" ::: "memory");
    };
    load_kv(0, 0);

    asm volatile("cp.async.wait_group 1;" ::: "memory");
    __syncthreads();

    uint32_t a_row = (uint32_t)(wid * 16 + (lane & 15));
    uint32_t a_cb  = (uint32_t)((lane >> 4) * 16);
    uint32_t qfh[4][4], qfl[4][4];
    #pragma unroll
    for (int s = 0; s < 4; s++) {
        uint32_t ao = a_row * AROWB + s * 32 + a_cb;
        ldm4(qfh[s], sb + ASM_QHI + ao);
        ldm4(qfl[s], sb + ASM_QLO + ao);
    }

    float oacc[8][4];
    #pragma unroll
    for (int i = 0; i < 8; i++)
        #pragma unroll
        for (int j = 0; j < 4; j++) oacc[i][j] = 0.f;
    float m0 = -1e30f, m1 = -1e30f, l0 = 0.f, l1 = 0.f;

    uint32_t b_rowo = (uint32_t)((lane & 7) + ((lane >> 4) & 1) * 8);
    uint32_t b_cbo  = (uint32_t)(((lane >> 3) & 1) * 16);
    uint32_t v_rowo = (uint32_t)(lane & 15);
    uint32_t v_cbo  = (uint32_t)(((lane >> 4) & 1) * 16);

    int nkt = 2 * qt + 2;
    for (int kt = 0; kt < nkt; kt++) {
        int buf = kt & 1;
        if (kt + 1 < nkt) {
            load_kv(kt + 1, buf ^ 1);
            asm volatile("cp.async.wait_group 1;" ::: "memory");
        } else {
            asm volatile("cp.async.wait_group 0;" ::: "memory");
        }
        __syncthreads();
        uint32_t kb = sb + ASM_KV + buf * AKVSTAGE;

        // ---- S = Q K^T over 64 keys (3-pass hi/lo), per-np fragment loads ----
        float sacc[8][4];
        #pragma unroll
        for (int j = 0; j < 8; j++)
            #pragma unroll
            for (int q = 0; q < 4; q++) sacc[j][q] = 0.f;

        #pragma unroll
        for (int s = 0; s < 4; s++) {
            #pragma unroll
            for (int np = 0; np < 4; np++) {
                uint32_t bo = (uint32_t)(np * 16 + b_rowo) * AROWB + s * 32 + b_cbo;
                uint32_t kfh[4], kfl[4];
                ldm4(kfh, kb + AKV_KHI + bo);
                ldm4(kfl, kb + AKV_KLO + bo);
                #pragma unroll
                for (int hf = 0; hf < 2; hf++)
                    mma_bf16(sacc[np*2+hf], qfh[s], kfh[hf*2], kfh[hf*2+1]);
                #pragma unroll
                for (int hf = 0; hf < 2; hf++)
                    mma_bf16(sacc[np*2+hf], qfh[s], kfl[hf*2], kfl[hf*2+1]);
                #pragma unroll
                for (int hf = 0; hf < 2; hf++)
                    mma_bf16(sacc[np*2+hf], qfl[s], kfh[hf*2], kfh[hf*2+1]);
            }
        }

        // ---- causal mask (only tiles overlapping the diagonal) ----
        if (kt >= 2 * qt) {
            int qr0 = qt * 128 + wid * 16 + (lane >> 2);
            int kc  = kt * 64 + (lane & 3) * 2;
            #pragma unroll
            for (int j = 0; j < 8; j++) {
                int k0i = kc + j * 8;
                if (k0i     > qr0)     sacc[j][0] = -1e30f;
                if (k0i + 1 > qr0)     sacc[j][1] = -1e30f;
                if (k0i     > qr0 + 8) sacc[j][2] = -1e30f;
                if (k0i + 1 > qr0 + 8) sacc[j][3] = -1e30f;
            }
        }

        // ---- online softmax (64-key chunk) ----
        float mx0 = m0, mx1 = m1;
        #pragma unroll
        for (int j = 0; j < 8; j++) {
            mx0 = fmaxf(mx0, fmaxf(sacc[j][0], sacc[j][1]));
            mx1 = fmaxf(mx1, fmaxf(sacc[j][2], sacc[j][3]));
        }
        mx0 = fmaxf(mx0, __shfl_xor_sync(0xFFFFFFFFu, mx0, 1));
        mx0 = fmaxf(mx0, __shfl_xor_sync(0xFFFFFFFFu, mx0, 2));
        mx1 = fmaxf(mx1, __shfl_xor_sync(0xFFFFFFFFu, mx1, 1));
        mx1 = fmaxf(mx1, __shfl_xor_sync(0xFFFFFFFFu, mx1, 2));
        float cor0 = __expf(m0 - mx0);
        float cor1 = __expf(m1 - mx1);
        m0 = mx0; m1 = mx1;
        float rs0 = 0.f, rs1 = 0.f;
        #pragma unroll
        for (int j = 0; j < 8; j++) {
            float p0 = __expf(sacc[j][0] - m0);
            float p1 = __expf(sacc[j][1] - m0);
            float p2 = __expf(sacc[j][2] - m1);
            float p3 = __expf(sacc[j][3] - m1);
            sacc[j][0] = p0; sacc[j][1] = p1; sacc[j][2] = p2; sacc[j][3] = p3;
            rs0 += p0 + p1; rs1 += p2 + p3;
        }
        rs0 += __shfl_xor_sync(0xFFFFFFFFu, rs0, 1);
        rs0 += __shfl_xor_sync(0xFFFFFFFFu, rs0, 2);
        rs1 += __shfl_xor_sync(0xFFFFFFFFu, rs1, 1);
        rs1 += __shfl_xor_sync(0xFFFFFFFFu, rs1, 2);
        l0 = l0 * cor0 + rs0;
        l1 = l1 * cor1 + rs1;
        #pragma unroll
        for (int dt = 0; dt < 8; dt++) {
            oacc[dt][0] *= cor0; oacc[dt][1] *= cor0;
            oacc[dt][2] *= cor1; oacc[dt][3] *= cor1;
        }

        // ---- O += P V  (per-dc V fragment loads to cap liveness) ----
        #pragma unroll
        for (int s = 0; s < 4; s++) {
            uint32_t pah[4];
            #pragma unroll
            for (int tt = 0; tt < 2; tt++) {
                const float* sc = sacc[2*s + tt];
                pah[tt*2+0] = packbf(sc[0], sc[1]);
                pah[tt*2+1] = packbf(sc[2], sc[3]);
            }
            #pragma unroll
            for (int dc = 0; dc < 4; dc++) {
                uint32_t vo = (uint32_t)(s * 16 + v_rowo) * AROWB + dc * 32 + v_cbo;
                uint32_t vf[4];
                ldm4t(vf, kb + AKV_VHI + vo);
                mma_bf16(oacc[dc*2+0], pah, vf[0], vf[1]);
                mma_bf16(oacc[dc*2+1], pah, vf[2], vf[3]);
                ldm4t(vf, kb + AKV_VLO + vo);
                mma_bf16(oacc[dc*2+0], pah, vf[0], vf[1]);
                mma_bf16(oacc[dc*2+1], pah, vf[2], vf[3]);
            }
        }
        __syncthreads();
    }

    float inv0 = 1.0f / l0;
    float inv1 = 1.0f / l1;
    int qr = qt * 128 + wid * 16 + (lane >> 2);
    size_t y0 = (rowbase + qr) * E_ + h * HS_ + (lane & 3) * 2;
    size_t y1 = y0 + (size_t)8 * E_;
    #pragma unroll
    for (int dt = 0; dt < 8; dt++) {
        float w0 = oacc[dt][0] * inv0, w1 = oacc[dt][1] * inv0;
        float w2 = oacc[dt][2] * inv1, w3 = oacc[dt][3] * inv1;
        bf16 h0,lo0,h1,lo1,h2,lo2,h3,lo3;
        split_bf16(w0,h0,lo0); split_bf16(w1,h1,lo1);
        split_bf16(w2,h2,lo2); split_bf16(w3,h3,lo3);
        __nv_bfloat162 hh0; hh0.x=h0; hh0.y=h1;
        __nv_bfloat162 ll0; ll0.x=lo0; ll0.y=lo1;
        __nv_bfloat162 hh1; hh1.x=h2; hh1.y=h3;
        __nv_bfloat162 ll1; ll1.x=lo2; ll1.y=lo3;
        *(__nv_bfloat162*)(Yhi + y0 + dt*8) = hh0;
        *(__nv_bfloat162*)(Ylo + y0 + dt*8) = ll0;
        *(__nv_bfloat162*)(Yhi + y1 + dt*8) = hh1;
        *(__nv_bfloat162*)(Ylo + y1 + dt*8) = ll1;
    }
}

// ======================= launch =======================
extern "C" void kernel_launch(void* const* d_in, const int* in_sizes, int n_in,
                              void* d_out, int out_size)
{
    const float* x    = (const float*)d_in[0];
    const float* Wq   = (const float*)d_in[1];
    const float* Wk   = (const float*)d_in[2];
    const float* Wv   = (const float*)d_in[3];
    const float* Wo   = (const float*)d_in[4];
    const float* bo   = (const float*)d_in[5];
    const float* ln1w = (const float*)d_in[6];
    const float* ln2w = (const float*)d_in[7];
    const float* W1   = (const float*)d_in[8];
    const float* b1   = (const float*)d_in[9];
    const float* W2   = (const float*)d_in[10];
    const float* b2   = (const float*)d_in[11];
    float* out = (float*)d_out;

    unsigned char* pool;
    cudaGetSymbolAddress((void**)&pool, g_pool);

    bf16*  hhi  = (bf16*)(pool + O_HHI);
    bf16*  hlo  = (bf16*)(pool + O_HLO);
    bf16*  qhi  = (bf16*)(pool + O_QHI), *qlo = (bf16*)(pool + O_QLO);
    bf16*  khi  = (bf16*)(pool + O_KHI), *klo = (bf16*)(pool + O_KLO);
    bf16*  vhi  = (bf16*)(pool + O_VHI), *vlo = (bf16*)(pool + O_VLO);
    bf16*  yhi  = (bf16*)(pool + O_YHI), *ylo = (bf16*)(pool + O_YLO);
    float* x2   = (float*)(pool + O_X2);
    bf16*  ffhi = (bf16*)(pool + O_FFHI);
    bf16*  fflo = (bf16*)(pool + O_FFLO);
    bf16*  wqh = (bf16*)(pool + O_WQH), *wql = (bf16*)(pool + O_WQL);
    bf16*  wkh = (bf16*)(pool + O_WKH), *wkl = (bf16*)(pool + O_WKL);
    bf16*  wvh = (bf16*)(pool + O_WVH), *wvl = (bf16*)(pool + O_WVL);
    bf16*  woh = (bf16*)(pool + O_WOH), *wol = (bf16*)(pool + O_WOL);
    bf16*  w1h = (bf16*)(pool + O_W1H), *w1l = (bf16*)(pool + O_W1L);
    bf16*  w2h = (bf16*)(pool + O_W2H), *w2l = (bf16*)(pool + O_W2L);

    cudaFuncSetAttribute((const void*)gemm_tc<1,3>, cudaFuncAttributeMaxDynamicSharedMemorySize, SMEM_SZ);
    cudaFuncSetAttribute((const void*)gemm_tc<2,3>, cudaFuncAttributeMaxDynamicSharedMemorySize, SMEM_SZ);
    cudaFuncSetAttribute((const void*)gemm_tc<3,3>, cudaFuncAttributeMaxDynamicSharedMemorySize, SMEM_SZ);
    cudaFuncSetAttribute((const void*)attn_tc,      cudaFuncAttributeMaxDynamicSharedMemorySize, ASMEM);

    dim3 tb(32, 8);
    dim3 gE (E_  / BN, M_ / BM);       // (8, 64)
    dim3 gQKV(3 * (E_ / BN), M_ / BM); // (24, 64)
    dim3 g4E(FF_ / BN, M_ / BM);       // (32, 64)

    // 1-4) weight splits needed before QKV/Wo GEMMs
    wsplit_kernel<<<dim3(E_/32,  E_/32),  tb>>>(Wq, wqh, wql, E_,  E_);
    wsplit_kernel<<<dim3(E_/32,  E_/32),  tb>>>(Wk, wkh, wkl, E_,  E_);
    wsplit_kernel<<<dim3(E_/32,  E_/32),  tb>>>(Wv, wvh, wvl, E_,  E_);
    wsplit_kernel<<<dim3(E_/32,  E_/32),  tb>>>(Wo, woh, wol, E_,  E_);
    // 5) h = LN1(x)
    ln_split_kernel<<<M_, 256>>>(x, ln1w, hhi, hlo);
    // 6) fused q,k,v projections (3-pass) -> bf16 hi/lo
    gemm_tc<3,3><<<gQKV, 256, SMEM_SZ>>>(hhi, hlo,
        wqh, wql, wkh, wkl, wvh, wvl,
        nullptr, nullptr, nullptr,
        qhi, qlo, khi, klo, vhi, vlo, M_, E_, E_);
    // 7) y = causal attention (64-key tiles, 2 CTAs/SM)
    attn_tc<<<dim3(T_/128, B_*H_), 256, ASMEM>>>(qhi, qlo, khi, klo, vhi, vlo, yhi, ylo);
    // 8-9) MLP weight splits
    wsplit_kernel<<<dim3(FF_/32, E_/32),  tb>>>(W1, w1h, w1l, E_,  FF_);
    wsplit_kernel<<<dim3(E_/32,  FF_/32), tb>>>(W2, w2h, w2l, FF_, E_);
    // 10) x2 = x + y @ Wo + bo (3-pass)
    gemm_tc<1,3><<<gE, 256, SMEM_SZ>>>(yhi, ylo,
        woh, wol, woh, wol, woh, wol,
        bo, x, x2,
        nullptr, nullptr, nullptr, nullptr, nullptr, nullptr, M_, E_, E_);
    // 11) h2 = LN2(x2)
    ln_split_kernel<<<M_, 256>>>(x2, ln2w, hhi, hlo);
    // 12) ff = relu(h2 @ W1 + b1)  (3-pass)
    gemm_tc<2,3><<<g4E, 256, SMEM_SZ>>>(hhi, hlo,
        w1h, w1l, w1h, w1l, w1h, w1l,
        b1, nullptr, nullptr,
        ffhi, fflo, nullptr, nullptr, nullptr, nullptr, M_, FF_, E_);
    // 13) out = x2 + ff @ W2 + b2  (3-pass)
    gemm_tc<1,3><<<gE, 256, SMEM_SZ>>>(ffhi, fflo,
        w2h, w2l, w2h, w2l, w2h, w2l,
        b2, x2, out,
        nullptr, nullptr, nullptr, nullptr, nullptr, nullptr, M_, E_, FF_);
}

// round 13
// speedup vs baseline: 3.4768x; 1.3025x over previous
#include <cuda_runtime.h>
#include <cuda_fp16.h>
#include <cstdint>

#define B_  4
#define T_  2048
#define E_  1024
#define H_  16
#define HS_ 64
#define M_  (B_*T_)    // 8192
#define FF_ (4*E_)     // 4096

typedef unsigned long long u64;
typedef __half fp16;

// weight pre-scale (avoids fp16 subnormals in weight-lo); epilogues undo it
#define WSC   64.0f
#define WSI   0.015625f          // 1/64
#define QSI   (0.015625f * 0.03125f)  // 1/64 * E^-0.5

// ======================= scratch pool (__device__ global) =======================
#define SZ_HB   ((size_t)M_*E_*2)
#define SZ_F32  ((size_t)M_*E_*4)
#define SZ_FFB  ((size_t)M_*FF_*2)
#define SZ_WB   ((size_t)E_*E_*2)
#define SZ_W1B  ((size_t)E_*FF_*2)

constexpr size_t O_H    = 0;
constexpr size_t O_Q    = O_H    + SZ_HB;
constexpr size_t O_KHI  = O_Q    + SZ_HB;
constexpr size_t O_KLO  = O_KHI  + SZ_HB;
constexpr size_t O_VHI  = O_KLO  + SZ_HB;
constexpr size_t O_VLO  = O_VHI  + SZ_HB;
constexpr size_t O_Y    = O_VLO  + SZ_HB;
constexpr size_t O_X2   = O_Y    + SZ_HB;
constexpr size_t O_FF   = O_X2   + SZ_F32;
constexpr size_t O_WQH  = O_FF   + SZ_FFB;
constexpr size_t O_WQL  = O_WQH  + SZ_WB;
constexpr size_t O_WKH  = O_WQL  + SZ_WB;
constexpr size_t O_WKL  = O_WKH  + SZ_WB;
constexpr size_t O_WVH  = O_WKL  + SZ_WB;
constexpr size_t O_WVL  = O_WVH  + SZ_WB;
constexpr size_t O_WOH  = O_WVL  + SZ_WB;
constexpr size_t O_WOL  = O_WOH  + SZ_WB;
constexpr size_t O_W1H  = O_WOL  + SZ_WB;
constexpr size_t O_W1L  = O_W1H  + SZ_W1B;
constexpr size_t O_W2H  = O_W1L  + SZ_W1B;
constexpr size_t O_W2L  = O_W2H  + SZ_W1B;
constexpr size_t POOLSZ = O_W2L  + SZ_W1B;

__device__ __align__(1024) unsigned char g_pool[POOLSZ];

// ======================= PTX helpers =======================
__device__ __forceinline__ uint32_t s2u(const void* p){
    uint32_t a;
    asm("{ .reg .u64 t; cvta.to.shared.u64 t, %1; cvt.u32.u64 %0, t; }" : "=r"(a) : "l"(p));
    return a;
}
__device__ __forceinline__ void cp16(uint32_t s, const void* g){
    asm volatile("cp.async.cg.shared.global [%0], [%1], 16;" :: "r"(s), "l"(g));
}
__device__ __forceinline__ void ldm4(uint32_t (&r)[4], uint32_t a){
    asm volatile("ldmatrix.sync.aligned.m8n8.x4.shared.b16 {%0,%1,%2,%3}, [%4];"
                 : "=r"(r[0]), "=r"(r[1]), "=r"(r[2]), "=r"(r[3]) : "r"(a));
}
__device__ __forceinline__ void ldm4t(uint32_t (&r)[4], uint32_t a){
    asm volatile("ldmatrix.sync.aligned.m8n8.x4.trans.shared.b16 {%0,%1,%2,%3}, [%4];"
                 : "=r"(r[0]), "=r"(r[1]), "=r"(r[2]), "=r"(r[3]) : "r"(a));
}
__device__ __forceinline__ void mma_f16(float (&c)[4], const uint32_t* a, uint32_t b0, uint32_t b1){
    asm volatile(
        "mma.sync.aligned.m16n8k16.row.col.f32.f16.f16.f32 "
        "{%0,%1,%2,%3}, {%4,%5,%6,%7}, {%8,%9}, {%0,%1,%2,%3};"
        : "+f"(c[0]), "+f"(c[1]), "+f"(c[2]), "+f"(c[3])
        : "r"(a[0]), "r"(a[1]), "r"(a[2]), "r"(a[3]), "r"(b0), "r"(b1));
}
// pack two f32 -> f16x2 reg: low half = lo_val, high half = hi_val
__device__ __forceinline__ uint32_t packh(float lo_val, float hi_val){
    uint32_t r;
    asm("cvt.rn.f16x2.f32 %0, %1, %2;" : "=r"(r) : "f"(hi_val), "f"(lo_val));
    return r;
}
__device__ __forceinline__ void split_h(float v, fp16 &hi, fp16 &lo){
    hi = __float2half_rn(v);
    lo = __float2half_rn(v - __half2float(hi));
}

// ======================= LayerNorm -> single fp16 =======================
__global__ __launch_bounds__(256) void ln_kernel(
    const float* __restrict__ X, const float* __restrict__ w,
    fp16* __restrict__ O)
{
    int row = blockIdx.x;
    int tid = threadIdx.x;
    const float* x = X + (size_t)row * E_;

    float4 v = *(const float4*)(x + tid * 4);
    float s  = v.x + v.y + v.z + v.w;
    float sq = v.x*v.x + v.y*v.y + v.z*v.z + v.w*v.w;

    #pragma unroll
    for (int o = 16; o; o >>= 1) {
        s  += __shfl_xor_sync(0xFFFFFFFFu, s,  o);
        sq += __shfl_xor_sync(0xFFFFFFFFu, sq, o);
    }
    __shared__ float ss[8], ssq[8], red[2];
    int wid = tid >> 5, lane = tid & 31;
    if (lane == 0) { ss[wid] = s; ssq[wid] = sq; }
    __syncthreads();
    if (tid == 0) {
        float a = 0.f, b = 0.f;
        #pragma unroll
        for (int i = 0; i < 8; i++) { a += ss[i]; b += ssq[i]; }
        float mean = a * (1.0f / E_);
        float var  = b * (1.0f / E_) - mean * mean;
        red[0] = mean;
        red[1] = rsqrtf(var + 1e-5f);
    }
    __syncthreads();
    float mean = red[0], rs = red[1];
    float4 wv = *(const float4*)(w + tid * 4);
    float o0 = (v.x - mean) * rs * wv.x;
    float o1 = (v.y - mean) * rs * wv.y;
    float o2 = (v.z - mean) * rs * wv.z;
    float o3 = (v.w - mean) * rs * wv.w;

    __half2 p0 = __floats2half2_rn(o0, o1);
    __half2 p1 = __floats2half2_rn(o2, o3);
    size_t off = (size_t)row * E_ + tid * 4;
    *(__half2*)(O + off)     = p0;
    *(__half2*)(O + off + 2) = p1;
}

// ======================= weight transpose + split (x64 scale) ===================
__global__ __launch_bounds__(256) void wsplit_kernel(
    const float* __restrict__ W, fp16* __restrict__ Whi, fp16* __restrict__ Wlo,
    int K, int N)
{
    __shared__ float t[32][33];
    int n0 = blockIdx.x * 32, k0 = blockIdx.y * 32;
    int tx = threadIdx.x, ty0 = threadIdx.y;
    #pragma unroll
    for (int dy = 0; dy < 32; dy += 8) {
        int ty = ty0 + dy;
        t[ty][tx] = W[(size_t)(k0 + ty) * N + n0 + tx];
    }
    __syncthreads();
    #pragma unroll
    for (int dy = 0; dy < 32; dy += 8) {
        int ty = ty0 + dy;
        float v = t[tx][ty] * WSC;
        fp16 hi, lo; split_h(v, hi, lo);
        size_t o = (size_t)(n0 + ty) * K + k0 + tx;
        Whi[o] = hi;
        Wlo[o] = lo;
    }
}

// ======================= HMMA GEMM (fp16 2-pass: a*bh + a*bl) ============
// BK=64, 110.6KB smem, 2 CTAs/SM. Weights pre-scaled x64; epilogue applies 1/64.
// OP: 1 = acc*WSI+bias+res -> f32; 2 = relu(acc*WSI+bias) -> fp16;
// OP: 3 = fused QKV: sel0 -> q fp16 (x QSI); sel1/2 -> k/v hi/lo splits (x WSI)
#define BM 128
#define BN 128
#define BK 64
#define ROWB   144
#define MTILE  (128*ROWB)     // 18432
#define BUFSZ  (3*MTILE)      // 55296  (A, Bh, Bl)
#define SMEM_SZ (2*BUFSZ)     // 110592

template<int OP>
__global__ __launch_bounds__(256, 2) void gemm_tc(
    const fp16* __restrict__ A,
    const fp16* __restrict__ B0h, const fp16* __restrict__ B0l,
    const fp16* __restrict__ B1h, const fp16* __restrict__ B1l,
    const fp16* __restrict__ B2h, const fp16* __restrict__ B2l,
    const float* __restrict__ bias, const float* __restrict__ res,
    float* __restrict__ C,
    fp16* __restrict__ C0,
    fp16* __restrict__ C1h, fp16* __restrict__ C1l,
    fp16* __restrict__ C2h, fp16* __restrict__ C2l,
    int M, int N, int K)
{
    extern __shared__ __align__(128) unsigned char smem[];
    uint32_t sb = s2u(smem);
    int tid = threadIdx.x;
    int lane = tid & 31, wid = tid >> 5;
    int warp_m = wid & 1, warp_n = wid >> 1;

    int sel = 0, bxi = blockIdx.x;
    if (OP == 3) { sel = blockIdx.x >> 3; bxi = blockIdx.x & 7; }
    int bx = bxi * BN, by = blockIdx.y * BM;

    const fp16* Bhi = (OP == 3) ? (sel == 0 ? B0h : sel == 1 ? B1h : B2h) : B0h;
    const fp16* Blo = (OP == 3) ? (sel == 0 ? B0l : sel == 1 ? B1l : B2l) : B0l;

    // loader: 128 rows x 8 chunks(16B) per matrix; 4 chunks/thread/matrix
    int chb = tid * 4;
    int lrow[4], lc16[4];
    uint32_t soff[4];
    #pragma unroll
    for (int i = 0; i < 4; i++) {
        lrow[i] = (chb + i) >> 3;
        lc16[i] = (chb + i) & 7;
        soff[i] = (uint32_t)(lrow[i] * ROWB + lc16[i] * 16);
    }

    const fp16* gA   = A   + (size_t)(by) * K;
    const fp16* gBhi = Bhi + (size_t)(bx) * K;
    const fp16* gBlo = Blo + (size_t)(bx) * K;

    float acc[4][4][4];
    #pragma unroll
    for (int i = 0; i < 4; i++)
        #pragma unroll
        for (int j = 0; j < 4; j++)
            #pragma unroll
            for (int q = 0; q < 4; q++) acc[i][j][q] = 0.f;

    int nt = K / BK;

    auto issue_tile = [&](int t, int buf) {
        uint32_t base = sb + buf * BUFSZ;
        int k0 = t * BK;
        #pragma unroll
        for (int i = 0; i < 4; i++) {
            size_t go = (size_t)lrow[i] * K + k0 + lc16[i] * 8;
            cp16(base + soff[i],           gA   + go);
            cp16(base + MTILE + soff[i],   gBhi + go);
            cp16(base + 2*MTILE + soff[i], gBlo + go);
        }
        asm volatile("cp.async.commit_group;" ::: "memory");
    };

    issue_tile(0, 0);

    uint32_t a_row = (uint32_t)(warp_m * 64 + (lane & 15));
    uint32_t a_cb  = (uint32_t)((lane >> 4) * 16);
    uint32_t b_row = (uint32_t)(warp_n * 32 + (lane & 7) + ((lane >> 4) & 1) * 8);
    uint32_t b_cb  = (uint32_t)(((lane >> 3) & 1) * 16);

    for (int t = 0; t < nt; t++) {
        int buf = t & 1;
        if (t + 1 < nt) {
            issue_tile(t + 1, buf ^ 1);
            asm volatile("cp.async.wait_group 1;" ::: "memory");
        } else {
            asm volatile("cp.async.wait_group 0;" ::: "memory");
        }
        __syncthreads();

        uint32_t base = sb + buf * BUFSZ;
        uint32_t sA   = base;
        uint32_t sBhi = base + MTILE;
        uint32_t sBlo = base + 2*MTILE;

        #pragma unroll
        for (int s = 0; s < 4; s++) {               // four k16 steps in BK=64
            uint32_t kb = (uint32_t)(s * 32);

            uint32_t af[4][4];
            #pragma unroll
            for (int mt = 0; mt < 4; mt++)
                ldm4(af[mt], sA + (a_row + mt * 16) * ROWB + kb + a_cb);
            uint32_t bhf[2][4];
            #pragma unroll
            for (int ntp = 0; ntp < 2; ntp++)
                ldm4(bhf[ntp], sBhi + (b_row + ntp * 16) * ROWB + kb + b_cb);
            #pragma unroll
            for (int mt = 0; mt < 4; mt++)
                #pragma unroll
                for (int ntp = 0; ntp < 2; ntp++)
                    #pragma unroll
                    for (int hf = 0; hf < 2; hf++)
                        mma_f16(acc[mt][ntp*2+hf], af[mt], bhf[ntp][hf*2], bhf[ntp][hf*2+1]);

            uint32_t blf[2][4];
            #pragma unroll
            for (int ntp = 0; ntp < 2; ntp++)
                ldm4(blf[ntp], sBlo + (b_row + ntp * 16) * ROWB + kb + b_cb);
            #pragma unroll
            for (int mt = 0; mt < 4; mt++)
                #pragma unroll
                for (int ntp = 0; ntp < 2; ntp++)
                    #pragma unroll
                    for (int hf = 0; hf < 2; hf++)
                        mma_f16(acc[mt][ntp*2+hf], af[mt], blf[ntp][hf*2], blf[ntp][hf*2+1]);
        }
        __syncthreads();
    }

    // -------- epilogue --------
    int er = by + warp_m * 64 + (lane >> 2);
    int ec = bx + warp_n * 32 + (lane & 3) * 2;
    #pragma unroll
    for (int mt = 0; mt < 4; mt++) {
        #pragma unroll
        for (int half = 0; half < 2; half++) {
            int row = er + mt * 16 + half * 8;
            #pragma unroll
            for (int ntj = 0; ntj < 4; ntj++) {
                int col = ec + ntj * 8;
                float v0 = acc[mt][ntj][half*2];
                float v1 = acc[mt][ntj][half*2+1];
                if (OP == 1) {
                    float2 rv = *(const float2*)&res[(size_t)row * N + col];
                    float2 bv = *(const float2*)&bias[col];
                    *(float2*)&C[(size_t)row * N + col] =
                        make_float2(v0 * WSI + bv.x + rv.x, v1 * WSI + bv.y + rv.y);
                } else if (OP == 2) {
                    float2 bv = *(const float2*)&bias[col];
                    float w0 = fmaxf(v0 * WSI + bv.x, 0.0f);
                    float w1 = fmaxf(v1 * WSI + bv.y, 0.0f);
                    *(__half2*)&C0[(size_t)row * N + col] = __floats2half2_rn(w0, w1);
                } else {
                    if (sel == 0) {
                        *(__half2*)&C0[(size_t)row * N + col] =
                            __floats2half2_rn(v0 * QSI, v1 * QSI);
                    } else {
                        fp16* Ch = (sel == 1) ? C1h : C2h;
                        fp16* Cl = (sel == 1) ? C1l : C2l;
                        float w0 = v0 * WSI, w1 = v1 * WSI;
                        fp16 h0,l0,h1,l1;
                        split_h(w0, h0, l0);
                        split_h(w1, h1, l1);
                        __half2 hh; hh.x = h0; hh.y = h1;
                        __half2 ll; ll.x = l0; ll.y = l1;
                        *(__half2*)&Ch[(size_t)row * N + col] = hh;
                        *(__half2*)&Cl[(size_t)row * N + col] = ll;
                    }
                }
            }
        }
    }
}

// ======================= Tensor-core causal flash attention ====================
// q single fp16; QK^T 2-pass (q*kh + q*kl); PV 2-pass (P fp16 x V hi/lo).
// 64-key KV tiles, double-buffered; 92.2KB smem -> 2 CTAs/SM.
#define AROWB 144
#define AQTILE (128*AROWB)    // 18432
#define AKTILE (64*AROWB)     // 9216
#define ASM_Q  0
#define ASM_KV AQTILE
#define AKV_KHI 0
#define AKV_KLO AKTILE
#define AKV_VHI (2*AKTILE)
#define AKV_VLO (3*AKTILE)
#define AKVSTAGE (4*AKTILE)   // 36864
#define ASMEM (AQTILE + 2*AKVSTAGE)  // 92160

__global__ __launch_bounds__(256, 2) void attn_tc(
    const fp16* __restrict__ Q,
    const fp16* __restrict__ Khi, const fp16* __restrict__ Klo,
    const fp16* __restrict__ Vhi, const fp16* __restrict__ Vlo,
    fp16* __restrict__ Y)
{
    extern __shared__ __align__(128) unsigned char asmem[];
    uint32_t sb = s2u(asmem);
    int tid = threadIdx.x, lane = tid & 31, wid = tid >> 5;
    int qt = blockIdx.x, bh = blockIdx.y;
    int b = bh >> 4, h = bh & 15;

    size_t rowbase = (size_t)b * T_;
    size_t qoff = (rowbase + qt * 128) * E_ + h * HS_;

    // Q loader: 128 rows x 8 chunks = 1024 chunks; 4 chunks/thread
    {
        int chb = tid * 4;
        #pragma unroll
        for (int i = 0; i < 4; i++) {
            int lr = (chb + i) >> 3;
            int lc = (chb + i) & 7;
            uint32_t so = (uint32_t)(lr * AROWB + lc * 16);
            cp16(sb + ASM_Q + so, Q + qoff + (size_t)lr * E_ + lc * 8);
        }
    }
    asm volatile("cp.async.commit_group;" ::: "memory");

    // KV loader: 64 rows x 8 chunks = 512 chunks per matrix; 2 chunks/thread
    int kv_row = tid >> 2;
    int kv_c   = (tid & 3) * 2;
    uint32_t kv_so = (uint32_t)(kv_row * AROWB + kv_c * 16);

    auto load_kv = [&](int kt, int buf) {
        size_t ko = (rowbase + kt * 64 + kv_row) * E_ + h * HS_ + kv_c * 8;
        uint32_t base = sb + ASM_KV + buf * AKVSTAGE + kv_so;
        cp16(base + AKV_KHI,      Khi + ko);
        cp16(base + AKV_KHI + 16, Khi + ko + 8);
        cp16(base + AKV_KLO,      Klo + ko);
        cp16(base + AKV_KLO + 16, Klo + ko + 8);
        cp16(base + AKV_VHI,      Vhi + ko);
        cp16(base + AKV_VHI + 16, Vhi + ko + 8);
        cp16(base + AKV_VLO,      Vlo + ko);
        cp16(base + AKV_VLO + 16, Vlo + ko + 8);
        asm volatile("cp.async.commit_group;" ::: "memory");
    };
    load_kv(0, 0);

    asm volatile("cp.async.wait_group 1;" ::: "memory");
    __syncthreads();

    uint32_t a_row = (uint32_t)(wid * 16 + (lane & 15));
    uint32_t a_cb  = (uint32_t)((lane >> 4) * 16);
    uint32_t qf[4][4];
    #pragma unroll
    for (int s = 0; s < 4; s++)
        ldm4(qf[s], sb + ASM_Q + a_row * AROWB + s * 32 + a_cb);

    float oacc[8][4];
    #pragma unroll
    for (int i = 0; i < 8; i++)
        #pragma unroll
        for (int j = 0; j < 4; j++) oacc[i][j] = 0.f;
    float m0 = -1e30f, m1 = -1e30f, l0 = 0.f, l1 = 0.f;

    uint32_t b_rowo = (uint32_t)((lane & 7) + ((lane >> 4) & 1) * 8);
    uint32_t b_cbo  = (uint32_t)(((lane >> 3) & 1) * 16);
    uint32_t v_rowo = (uint32_t)(lane & 15);
    uint32_t v_cbo  = (uint32_t)(((lane >> 4) & 1) * 16);

    int nkt = 2 * qt + 2;
    for (int kt = 0; kt < nkt; kt++) {
        int buf = kt & 1;
        if (kt + 1 < nkt) {
            load_kv(kt + 1, buf ^ 1);
            asm volatile("cp.async.wait_group 1;" ::: "memory");
        } else {
            asm volatile("cp.async.wait_group 0;" ::: "memory");
        }
        __syncthreads();
        uint32_t kb = sb + ASM_KV + buf * AKVSTAGE;

        // ---- S = Q K^T over 64 keys (2-pass) ----
        float sacc[8][4];
        #pragma unroll
        for (int j = 0; j < 8; j++)
            #pragma unroll
            for (int q = 0; q < 4; q++) sacc[j][q] = 0.f;

        #pragma unroll
        for (int s = 0; s < 4; s++) {
            #pragma unroll
            for (int np = 0; np < 4; np++) {
                uint32_t bo = (uint32_t)(np * 16 + b_rowo) * AROWB + s * 32 + b_cbo;
                uint32_t kfh[4], kfl[4];
                ldm4(kfh, kb + AKV_KHI + bo);
                ldm4(kfl, kb + AKV_KLO + bo);
                #pragma unroll
                for (int hf = 0; hf < 2; hf++)
                    mma_f16(sacc[np*2+hf], qf[s], kfh[hf*2], kfh[hf*2+1]);
                #pragma unroll
                for (int hf = 0; hf < 2; hf++)
                    mma_f16(sacc[np*2+hf], qf[s], kfl[hf*2], kfl[hf*2+1]);
            }
        }

        // scores carry weight pre-scale (K was scaled x64 via WSI in epilogue? no —
        // k was written with WSI applied, so S is true scale already).

        // ---- causal mask (tiles overlapping the diagonal) ----
        if (kt >= 2 * qt) {
            int qr0 = qt * 128 + wid * 16 + (lane >> 2);
            int kc  = kt * 64 + (lane & 3) * 2;
            #pragma unroll
            for (int j = 0; j < 8; j++) {
                int k0i = kc + j * 8;
                if (k0i     > qr0)     sacc[j][0] = -1e30f;
                if (k0i + 1 > qr0)     sacc[j][1] = -1e30f;
                if (k0i     > qr0 + 8) sacc[j][2] = -1e30f;
                if (k0i + 1 > qr0 + 8) sacc[j][3] = -1e30f;
            }
        }

        // ---- online softmax ----
        float mx0 = m0, mx1 = m1;
        #pragma unroll
        for (int j = 0; j < 8; j++) {
            mx0 = fmaxf(mx0, fmaxf(sacc[j][0], sacc[j][1]));
            mx1 = fmaxf(mx1, fmaxf(sacc[j][2], sacc[j][3]));
        }
        mx0 = fmaxf(mx0, __shfl_xor_sync(0xFFFFFFFFu, mx0, 1));
        mx0 = fmaxf(mx0, __shfl_xor_sync(0xFFFFFFFFu, mx0, 2));
        mx1 = fmaxf(mx1, __shfl_xor_sync(0xFFFFFFFFu, mx1, 1));
        mx1 = fmaxf(mx1, __shfl_xor_sync(0xFFFFFFFFu, mx1, 2));
        float cor0 = __expf(m0 - mx0);
        float cor1 = __expf(m1 - mx1);
        m0 = mx0; m1 = mx1;
        float rs0 = 0.f, rs1 = 0.f;
        #pragma unroll
        for (int j = 0; j < 8; j++) {
            float p0 = __expf(sacc[j][0] - m0);
            float p1 = __expf(sacc[j][1] - m0);
            float p2 = __expf(sacc[j][2] - m1);
            float p3 = __expf(sacc[j][3] - m1);
            sacc[j][0] = p0; sacc[j][1] = p1; sacc[j][2] = p2; sacc[j][3] = p3;
            rs0 += p0 + p1; rs1 += p2 + p3;
        }
        rs0 += __shfl_xor_sync(0xFFFFFFFFu, rs0, 1);
        rs0 += __shfl_xor_sync(0xFFFFFFFFu, rs0, 2);
        rs1 += __shfl_xor_sync(0xFFFFFFFFu, rs1, 1);
        rs1 += __shfl_xor_sync(0xFFFFFFFFu, rs1, 2);
        l0 = l0 * cor0 + rs0;
        l1 = l1 * cor1 + rs1;
        #pragma unroll
        for (int dt = 0; dt < 8; dt++) {
            oacc[dt][0] *= cor0; oacc[dt][1] *= cor0;
            oacc[dt][2] *= cor1; oacc[dt][3] *= cor1;
        }

        // ---- O += P V  (P fp16 x V hi/lo) ----
        #pragma unroll
        for (int s = 0; s < 4; s++) {
            uint32_t pah[4];
            #pragma unroll
            for (int tt = 0; tt < 2; tt++) {
                const float* sc = sacc[2*s + tt];
                pah[tt*2+0] = packh(sc[0], sc[1]);
                pah[tt*2+1] = packh(sc[2], sc[3]);
            }
            #pragma unroll
            for (int dc = 0; dc < 4; dc++) {
                uint32_t vo = (uint32_t)(s * 16 + v_rowo) * AROWB + dc * 32 + v_cbo;
                uint32_t vf[4];
                ldm4t(vf, kb + AKV_VHI + vo);
                mma_f16(oacc[dc*2+0], pah, vf[0], vf[1]);
                mma_f16(oacc[dc*2+1], pah, vf[2], vf[3]);
                ldm4t(vf, kb + AKV_VLO + vo);
                mma_f16(oacc[dc*2+0], pah, vf[0], vf[1]);
                mma_f16(oacc[dc*2+1], pah, vf[2], vf[3]);
            }
        }
        __syncthreads();
    }

    float inv0 = 1.0f / l0;
    float inv1 = 1.0f / l1;
    int qr = qt * 128 + wid * 16 + (lane >> 2);
    size_t y0 = (rowbase + qr) * E_ + h * HS_ + (lane & 3) * 2;
    size_t y1 = y0 + (size_t)8 * E_;
    #pragma unroll
    for (int dt = 0; dt < 8; dt++) {
        *(__half2*)(Y + y0 + dt*8) = __floats2half2_rn(oacc[dt][0]*inv0, oacc[dt][1]*inv0);
        *(__half2*)(Y + y1 + dt*8) = __floats2half2_rn(oacc[dt][2]*inv1, oacc[dt][3]*inv1);
    }
}

// ======================= launch =======================
extern "C" void kernel_launch(void* const* d_in, const int* in_sizes, int n_in,
                              void* d_out, int out_size)
{
    const float* x    = (const float*)d_in[0];
    const float* Wq   = (const float*)d_in[1];
    const float* Wk   = (const float*)d_in[2];
    const float* Wv   = (const float*)d_in[3];
    const float* Wo   = (const float*)d_in[4];
    const float* bo   = (const float*)d_in[5];
    const float* ln1w = (const float*)d_in[6];
    const float* ln2w = (const float*)d_in[7];
    const float* W1   = (const float*)d_in[8];
    const float* b1   = (const float*)d_in[9];
    const float* W2   = (const float*)d_in[10];
    const float* b2   = (const float*)d_in[11];
    float* out = (float*)d_out;

    unsigned char* pool;
    cudaGetSymbolAddress((void**)&pool, g_pool);

    fp16*  hh   = (fp16*)(pool + O_H);
    fp16*  q    = (fp16*)(pool + O_Q);
    fp16*  khi  = (fp16*)(pool + O_KHI), *klo = (fp16*)(pool + O_KLO);
    fp16*  vhi  = (fp16*)(pool + O_VHI), *vlo = (fp16*)(pool + O_VLO);
    fp16*  y    = (fp16*)(pool + O_Y);
    float* x2   = (float*)(pool + O_X2);
    fp16*  ff   = (fp16*)(pool + O_FF);
    fp16*  wqh = (fp16*)(pool + O_WQH), *wql = (fp16*)(pool + O_WQL);
    fp16*  wkh = (fp16*)(pool + O_WKH), *wkl = (fp16*)(pool + O_WKL);
    fp16*  wvh = (fp16*)(pool + O_WVH), *wvl = (fp16*)(pool + O_WVL);
    fp16*  woh = (fp16*)(pool + O_WOH), *wol = (fp16*)(pool + O_WOL);
    fp16*  w1h = (fp16*)(pool + O_W1H), *w1l = (fp16*)(pool + O_W1L);
    fp16*  w2h = (fp16*)(pool + O_W2H), *w2l = (fp16*)(pool + O_W2L);

    cudaFuncSetAttribute((const void*)gemm_tc<1>, cudaFuncAttributeMaxDynamicSharedMemorySize, SMEM_SZ);
    cudaFuncSetAttribute((const void*)gemm_tc<2>, cudaFuncAttributeMaxDynamicSharedMemorySize, SMEM_SZ);
    cudaFuncSetAttribute((const void*)gemm_tc<3>, cudaFuncAttributeMaxDynamicSharedMemorySize, SMEM_SZ);
    cudaFuncSetAttribute((const void*)attn_tc,    cudaFuncAttributeMaxDynamicSharedMemorySize, ASMEM);

    dim3 tb(32, 8);
    dim3 gE (E_  / BN, M_ / BM);       // (8, 64)
    dim3 gQKV(3 * (E_ / BN), M_ / BM); // (24, 64)
    dim3 g4E(FF_ / BN, M_ / BM);       // (32, 64)

    // weight splits (x64 pre-scale)
    wsplit_kernel<<<dim3(E_/32,  E_/32),  tb>>>(Wq, wqh, wql, E_,  E_);
    wsplit_kernel<<<dim3(E_/32,  E_/32),  tb>>>(Wk, wkh, wkl, E_,  E_);
    wsplit_kernel<<<dim3(E_/32,  E_/32),  tb>>>(Wv, wvh, wvl, E_,  E_);
    wsplit_kernel<<<dim3(E_/32,  E_/32),  tb>>>(Wo, woh, wol, E_,  E_);
    // h = LN1(x)
    ln_kernel<<<M_, 256>>>(x, ln1w, hh);
    // fused q,k,v projections: q fp16 single (scaled), k/v fp16 hi/lo
    gemm_tc<3><<<gQKV, 256, SMEM_SZ>>>(hh,
        wqh, wql, wkh, wkl, wvh, wvl,
        nullptr, nullptr, nullptr,
        q, khi, klo, vhi, vlo, M_, E_, E_);
    // y = causal attention
    attn_tc<<<dim3(T_/128, B_*H_), 256, ASMEM>>>(q, khi, klo, vhi, vlo, y);
    // MLP weight splits
    wsplit_kernel<<<dim3(FF_/32, E_/32),  tb>>>(W1, w1h, w1l, E_,  FF_);
    wsplit_kernel<<<dim3(E_/32,  FF_/32), tb>>>(W2, w2h, w2l, FF_, E_);
    // x2 = x + y @ Wo + bo
    gemm_tc<1><<<gE, 256, SMEM_SZ>>>(y,
        woh, wol, woh, wol, woh, wol,
        bo, x, x2,
        nullptr, nullptr, nullptr, nullptr, nullptr, M_, E_, E_);
    // h2 = LN2(x2)
    ln_kernel<<<M_, 256>>>(x2, ln2w, hh);
    // ff = relu(h2 @ W1 + b1)
    gemm_tc<2><<<g4E, 256, SMEM_SZ>>>(hh,
        w1h, w1l, w1h, w1l, w1h, w1l,
        b1, nullptr, nullptr,
        ff, nullptr, nullptr, nullptr, nullptr, M_, FF_, E_);
    // out = x2 + ff @ W2 + b2
    gemm_tc<1><<<gE, 256, SMEM_SZ>>>(ff,
        w2h, w2l, w2h, w2l, w2h, w2l,
        b2, x2, out,
        nullptr, nullptr, nullptr, nullptr, nullptr, M_, E_, FF_);
}

// round 14
// speedup vs baseline: 3.7116x; 1.0675x over previous
#include <cuda_runtime.h>
#include <cuda_fp16.h>
#include <cstdint>

#define B_  4
#define T_  2048
#define E_  1024
#define H_  16
#define HS_ 64
#define M_  (B_*T_)    // 8192
#define FF_ (4*E_)     // 4096

typedef unsigned long long u64;
typedef __half fp16;

// weight pre-scale (avoids fp16 subnormals in weight-lo); epilogues undo it
#define WSC   64.0f
#define WSI   0.015625f               // 1/64
#define QSI   (0.015625f * 0.03125f)  // 1/64 * E^-0.5

// ======================= scratch pool (__device__ global) =======================
#define SZ_HB   ((size_t)M_*E_*2)
#define SZ_F32  ((size_t)M_*E_*4)
#define SZ_FFB  ((size_t)M_*FF_*2)
#define SZ_WB   ((size_t)E_*E_*2)
#define SZ_W1B  ((size_t)E_*FF_*2)

constexpr size_t O_H    = 0;
constexpr size_t O_Q    = O_H    + SZ_HB;
constexpr size_t O_K    = O_Q    + SZ_HB;
constexpr size_t O_V    = O_K    + SZ_HB;
constexpr size_t O_Y    = O_V    + SZ_HB;
constexpr size_t O_X2   = O_Y    + SZ_HB;
constexpr size_t O_FF   = O_X2   + SZ_F32;
constexpr size_t O_WQH  = O_FF   + SZ_FFB;
constexpr size_t O_WQL  = O_WQH  + SZ_WB;
constexpr size_t O_WKH  = O_WQL  + SZ_WB;
constexpr size_t O_WKL  = O_WKH  + SZ_WB;
constexpr size_t O_WVH  = O_WKL  + SZ_WB;
constexpr size_t O_WVL  = O_WVH  + SZ_WB;
constexpr size_t O_WOH  = O_WVL  + SZ_WB;
constexpr size_t O_WOL  = O_WOH  + SZ_WB;
constexpr size_t O_W1H  = O_WOL  + SZ_WB;
constexpr size_t O_W1L  = O_W1H  + SZ_W1B;
constexpr size_t O_W2H  = O_W1L  + SZ_W1B;
constexpr size_t O_W2L  = O_W2H  + SZ_W1B;
constexpr size_t POOLSZ = O_W2L  + SZ_W1B;

__device__ __align__(1024) unsigned char g_pool[POOLSZ];

// ======================= PTX helpers =======================
__device__ __forceinline__ uint32_t s2u(const void* p){
    uint32_t a;
    asm("{ .reg .u64 t; cvta.to.shared.u64 t, %1; cvt.u32.u64 %0, t; }" : "=r"(a) : "l"(p));
    return a;
}
__device__ __forceinline__ void cp16(uint32_t s, const void* g){
    asm volatile("cp.async.cg.shared.global [%0], [%1], 16;" :: "r"(s), "l"(g));
}
__device__ __forceinline__ void ldm4(uint32_t (&r)[4], uint32_t a){
    asm volatile("ldmatrix.sync.aligned.m8n8.x4.shared.b16 {%0,%1,%2,%3}, [%4];"
                 : "=r"(r[0]), "=r"(r[1]), "=r"(r[2]), "=r"(r[3]) : "r"(a));
}
__device__ __forceinline__ void ldm4t(uint32_t (&r)[4], uint32_t a){
    asm volatile("ldmatrix.sync.aligned.m8n8.x4.trans.shared.b16 {%0,%1,%2,%3}, [%4];"
                 : "=r"(r[0]), "=r"(r[1]), "=r"(r[2]), "=r"(r[3]) : "r"(a));
}
__device__ __forceinline__ void mma_f16(float (&c)[4], const uint32_t* a, uint32_t b0, uint32_t b1){
    asm volatile(
        "mma.sync.aligned.m16n8k16.row.col.f32.f16.f16.f32 "
        "{%0,%1,%2,%3}, {%4,%5,%6,%7}, {%8,%9}, {%0,%1,%2,%3};"
        : "+f"(c[0]), "+f"(c[1]), "+f"(c[2]), "+f"(c[3])
        : "r"(a[0]), "r"(a[1]), "r"(a[2]), "r"(a[3]), "r"(b0), "r"(b1));
}
__device__ __forceinline__ uint32_t packh(float lo_val, float hi_val){
    uint32_t r;
    asm("cvt.rn.f16x2.f32 %0, %1, %2;" : "=r"(r) : "f"(hi_val), "f"(lo_val));
    return r;
}
__device__ __forceinline__ void split_h(float v, fp16 &hi, fp16 &lo){
    hi = __float2half_rn(v);
    lo = __float2half_rn(v - __half2float(hi));
}

// ======================= LayerNorm -> single fp16 =======================
__global__ __launch_bounds__(256) void ln_kernel(
    const float* __restrict__ X, const float* __restrict__ w,
    fp16* __restrict__ O)
{
    int row = blockIdx.x;
    int tid = threadIdx.x;
    const float* x = X + (size_t)row * E_;

    float4 v = *(const float4*)(x + tid * 4);
    float s  = v.x + v.y + v.z + v.w;
    float sq = v.x*v.x + v.y*v.y + v.z*v.z + v.w*v.w;

    #pragma unroll
    for (int o = 16; o; o >>= 1) {
        s  += __shfl_xor_sync(0xFFFFFFFFu, s,  o);
        sq += __shfl_xor_sync(0xFFFFFFFFu, sq, o);
    }
    __shared__ float ss[8], ssq[8], red[2];
    int wid = tid >> 5, lane = tid & 31;
    if (lane == 0) { ss[wid] = s; ssq[wid] = sq; }
    __syncthreads();
    if (tid == 0) {
        float a = 0.f, b = 0.f;
        #pragma unroll
        for (int i = 0; i < 8; i++) { a += ss[i]; b += ssq[i]; }
        float mean = a * (1.0f / E_);
        float var  = b * (1.0f / E_) - mean * mean;
        red[0] = mean;
        red[1] = rsqrtf(var + 1e-5f);
    }
    __syncthreads();
    float mean = red[0], rs = red[1];
    float4 wv = *(const float4*)(w + tid * 4);
    float o0 = (v.x - mean) * rs * wv.x;
    float o1 = (v.y - mean) * rs * wv.y;
    float o2 = (v.z - mean) * rs * wv.z;
    float o3 = (v.w - mean) * rs * wv.w;

    __half2 p0 = __floats2half2_rn(o0, o1);
    __half2 p1 = __floats2half2_rn(o2, o3);
    size_t off = (size_t)row * E_ + tid * 4;
    *(__half2*)(O + off)     = p0;
    *(__half2*)(O + off + 2) = p1;
}

// ======================= weight transpose + split (x64 scale) ===================
__global__ __launch_bounds__(256) void wsplit_kernel(
    const float* __restrict__ W, fp16* __restrict__ Whi, fp16* __restrict__ Wlo,
    int K, int N)
{
    __shared__ float t[32][33];
    int n0 = blockIdx.x * 32, k0 = blockIdx.y * 32;
    int tx = threadIdx.x, ty0 = threadIdx.y;
    #pragma unroll
    for (int dy = 0; dy < 32; dy += 8) {
        int ty = ty0 + dy;
        t[ty][tx] = W[(size_t)(k0 + ty) * N + n0 + tx];
    }
    __syncthreads();
    #pragma unroll
    for (int dy = 0; dy < 32; dy += 8) {
        int ty = ty0 + dy;
        float v = t[tx][ty] * WSC;
        fp16 hi, lo; split_h(v, hi, lo);
        size_t o = (size_t)(n0 + ty) * K + k0 + tx;
        Whi[o] = hi;
        Wlo[o] = lo;
    }
}

// ======================= HMMA GEMM (fp16 2-pass: a*bh + a*bl) ============
// BK=64, 110.6KB smem, 2 CTAs/SM. Weights pre-scaled x64; epilogue applies 1/64.
// OP: 1 = acc*WSI+bias+res -> f32; 2 = relu(acc*WSI+bias) -> fp16;
// OP: 3 = fused QKV: sel0 -> q (x QSI); sel1/2 -> k/v (x WSI), all single fp16
#define BM 128
#define BN 128
#define BK 64
#define ROWB   144
#define MTILE  (128*ROWB)     // 18432
#define BUFSZ  (3*MTILE)      // 55296  (A, Bh, Bl)
#define SMEM_SZ (2*BUFSZ)     // 110592

template<int OP>
__global__ __launch_bounds__(256, 2) void gemm_tc(
    const fp16* __restrict__ A,
    const fp16* __restrict__ B0h, const fp16* __restrict__ B0l,
    const fp16* __restrict__ B1h, const fp16* __restrict__ B1l,
    const fp16* __restrict__ B2h, const fp16* __restrict__ B2l,
    const float* __restrict__ bias, const float* __restrict__ res,
    float* __restrict__ C,
    fp16* __restrict__ C0, fp16* __restrict__ C1, fp16* __restrict__ C2,
    int M, int N, int K)
{
    extern __shared__ __align__(128) unsigned char smem[];
    uint32_t sb = s2u(smem);
    int tid = threadIdx.x;
    int lane = tid & 31, wid = tid >> 5;
    int warp_m = wid & 1, warp_n = wid >> 1;

    int sel = 0, bxi = blockIdx.x;
    if (OP == 3) { sel = blockIdx.x >> 3; bxi = blockIdx.x & 7; }
    int bx = bxi * BN, by = blockIdx.y * BM;

    const fp16* Bhi = (OP == 3) ? (sel == 0 ? B0h : sel == 1 ? B1h : B2h) : B0h;
    const fp16* Blo = (OP == 3) ? (sel == 0 ? B0l : sel == 1 ? B1l : B2l) : B0l;
    fp16* Cout = (OP == 3) ? (sel == 0 ? C0 : sel == 1 ? C1 : C2) : C0;
    float oscale = (OP == 3 && sel == 0) ? QSI : WSI;

    int chb = tid * 4;
    int lrow[4], lc16[4];
    uint32_t soff[4];
    #pragma unroll
    for (int i = 0; i < 4; i++) {
        lrow[i] = (chb + i) >> 3;
        lc16[i] = (chb + i) & 7;
        soff[i] = (uint32_t)(lrow[i] * ROWB + lc16[i] * 16);
    }

    const fp16* gA   = A   + (size_t)(by) * K;
    const fp16* gBhi = Bhi + (size_t)(bx) * K;
    const fp16* gBlo = Blo + (size_t)(bx) * K;

    float acc[4][4][4];
    #pragma unroll
    for (int i = 0; i < 4; i++)
        #pragma unroll
        for (int j = 0; j < 4; j++)
            #pragma unroll
            for (int q = 0; q < 4; q++) acc[i][j][q] = 0.f;

    int nt = K / BK;

    auto issue_tile = [&](int t, int buf) {
        uint32_t base = sb + buf * BUFSZ;
        int k0 = t * BK;
        #pragma unroll
        for (int i = 0; i < 4; i++) {
            size_t go = (size_t)lrow[i] * K + k0 + lc16[i] * 8;
            cp16(base + soff[i],           gA   + go);
            cp16(base + MTILE + soff[i],   gBhi + go);
            cp16(base + 2*MTILE + soff[i], gBlo + go);
        }
        asm volatile("cp.async.commit_group;" ::: "memory");
    };

    issue_tile(0, 0);

    uint32_t a_row = (uint32_t)(warp_m * 64 + (lane & 15));
    uint32_t a_cb  = (uint32_t)((lane >> 4) * 16);
    uint32_t b_row = (uint32_t)(warp_n * 32 + (lane & 7) + ((lane >> 4) & 1) * 8);
    uint32_t b_cb  = (uint32_t)(((lane >> 3) & 1) * 16);

    for (int t = 0; t < nt; t++) {
        int buf = t & 1;
        if (t + 1 < nt) {
            issue_tile(t + 1, buf ^ 1);
            asm volatile("cp.async.wait_group 1;" ::: "memory");
        } else {
            asm volatile("cp.async.wait_group 0;" ::: "memory");
        }
        __syncthreads();

        uint32_t base = sb + buf * BUFSZ;
        uint32_t sA   = base;
        uint32_t sBhi = base + MTILE;
        uint32_t sBlo = base + 2*MTILE;

        #pragma unroll
        for (int s = 0; s < 4; s++) {
            uint32_t kb = (uint32_t)(s * 32);

            uint32_t af[4][4];
            #pragma unroll
            for (int mt = 0; mt < 4; mt++)
                ldm4(af[mt], sA + (a_row + mt * 16) * ROWB + kb + a_cb);
            uint32_t bhf[2][4];
            #pragma unroll
            for (int ntp = 0; ntp < 2; ntp++)
                ldm4(bhf[ntp], sBhi + (b_row + ntp * 16) * ROWB + kb + b_cb);
            #pragma unroll
            for (int mt = 0; mt < 4; mt++)
                #pragma unroll
                for (int ntp = 0; ntp < 2; ntp++)
                    #pragma unroll
                    for (int hf = 0; hf < 2; hf++)
                        mma_f16(acc[mt][ntp*2+hf], af[mt], bhf[ntp][hf*2], bhf[ntp][hf*2+1]);

            uint32_t blf[2][4];
            #pragma unroll
            for (int ntp = 0; ntp < 2; ntp++)
                ldm4(blf[ntp], sBlo + (b_row + ntp * 16) * ROWB + kb + b_cb);
            #pragma unroll
            for (int mt = 0; mt < 4; mt++)
                #pragma unroll
                for (int ntp = 0; ntp < 2; ntp++)
                    #pragma unroll
                    for (int hf = 0; hf < 2; hf++)
                        mma_f16(acc[mt][ntp*2+hf], af[mt], blf[ntp][hf*2], blf[ntp][hf*2+1]);
        }
        __syncthreads();
    }

    // -------- epilogue --------
    int er = by + warp_m * 64 + (lane >> 2);
    int ec = bx + warp_n * 32 + (lane & 3) * 2;
    #pragma unroll
    for (int mt = 0; mt < 4; mt++) {
        #pragma unroll
        for (int half = 0; half < 2; half++) {
            int row = er + mt * 16 + half * 8;
            #pragma unroll
            for (int ntj = 0; ntj < 4; ntj++) {
                int col = ec + ntj * 8;
                float v0 = acc[mt][ntj][half*2];
                float v1 = acc[mt][ntj][half*2+1];
                if (OP == 1) {
                    float2 rv = *(const float2*)&res[(size_t)row * N + col];
                    float2 bv = *(const float2*)&bias[col];
                    *(float2*)&C[(size_t)row * N + col] =
                        make_float2(v0 * WSI + bv.x + rv.x, v1 * WSI + bv.y + rv.y);
                } else if (OP == 2) {
                    float2 bv = *(const float2*)&bias[col];
                    float w0 = fmaxf(v0 * WSI + bv.x, 0.0f);
                    float w1 = fmaxf(v1 * WSI + bv.y, 0.0f);
                    *(__half2*)&C0[(size_t)row * N + col] = __floats2half2_rn(w0, w1);
                } else {
                    *(__half2*)&Cout[(size_t)row * N + col] =
                        __floats2half2_rn(v0 * oscale, v1 * oscale);
                }
            }
        }
    }
}

// ======================= Tensor-core causal flash attention ====================
// q, K, V all single fp16: QK^T 1-pass, PV 1-pass.
// 64-key KV tiles, double-buffered; 55.3KB smem -> 2 CTAs/SM.
#define AROWB 144
#define AQTILE (128*AROWB)    // 18432
#define AKTILE (64*AROWB)     // 9216
#define ASM_Q  0
#define ASM_KV AQTILE
#define AKV_K  0
#define AKV_V  AKTILE
#define AKVSTAGE (2*AKTILE)   // 18432
#define ASMEM (AQTILE + 2*AKVSTAGE)  // 55296

__global__ __launch_bounds__(256, 2) void attn_tc(
    const fp16* __restrict__ Q,
    const fp16* __restrict__ Kg,
    const fp16* __restrict__ V,
    fp16* __restrict__ Y)
{
    extern __shared__ __align__(128) unsigned char asmem[];
    uint32_t sb = s2u(asmem);
    int tid = threadIdx.x, lane = tid & 31, wid = tid >> 5;
    int qt = blockIdx.x, bh = blockIdx.y;
    int b = bh >> 4, h = bh & 15;

    size_t rowbase = (size_t)b * T_;
    size_t qoff = (rowbase + qt * 128) * E_ + h * HS_;

    // Q loader: 128 rows x 8 chunks = 1024 chunks; 4 chunks/thread
    {
        int chb = tid * 4;
        #pragma unroll
        for (int i = 0; i < 4; i++) {
            int lr = (chb + i) >> 3;
            int lc = (chb + i) & 7;
            uint32_t so = (uint32_t)(lr * AROWB + lc * 16);
            cp16(sb + ASM_Q + so, Q + qoff + (size_t)lr * E_ + lc * 8);
        }
    }
    asm volatile("cp.async.commit_group;" ::: "memory");

    // KV loader: 64 rows x 8 chunks x 2 matrices = 1024 chunks; 4/thread
    int kv_row = tid >> 2;
    int kv_c   = (tid & 3) * 2;
    uint32_t kv_so = (uint32_t)(kv_row * AROWB + kv_c * 16);

    auto load_kv = [&](int kt, int buf) {
        size_t ko = (rowbase + kt * 64 + kv_row) * E_ + h * HS_ + kv_c * 8;
        uint32_t base = sb + ASM_KV + buf * AKVSTAGE + kv_so;
        cp16(base + AKV_K,      Kg + ko);
        cp16(base + AKV_K + 16, Kg + ko + 8);
        cp16(base + AKV_V,      V + ko);
        cp16(base + AKV_V + 16, V + ko + 8);
        asm volatile("cp.async.commit_group;" ::: "memory");
    };
    load_kv(0, 0);

    asm volatile("cp.async.wait_group 1;" ::: "memory");
    __syncthreads();

    uint32_t a_row = (uint32_t)(wid * 16 + (lane & 15));
    uint32_t a_cb  = (uint32_t)((lane >> 4) * 16);
    uint32_t qf[4][4];
    #pragma unroll
    for (int s = 0; s < 4; s++)
        ldm4(qf[s], sb + ASM_Q + a_row * AROWB + s * 32 + a_cb);

    float oacc[8][4];
    #pragma unroll
    for (int i = 0; i < 8; i++)
        #pragma unroll
        for (int j = 0; j < 4; j++) oacc[i][j] = 0.f;
    float m0 = -1e30f, m1 = -1e30f, l0 = 0.f, l1 = 0.f;

    uint32_t b_rowo = (uint32_t)((lane & 7) + ((lane >> 4) & 1) * 8);
    uint32_t b_cbo  = (uint32_t)(((lane >> 3) & 1) * 16);
    uint32_t v_rowo = (uint32_t)(lane & 15);
    uint32_t v_cbo  = (uint32_t)(((lane >> 4) & 1) * 16);

    int nkt = 2 * qt + 2;
    for (int kt = 0; kt < nkt; kt++) {
        int buf = kt & 1;
        if (kt + 1 < nkt) {
            load_kv(kt + 1, buf ^ 1);
            asm volatile("cp.async.wait_group 1;" ::: "memory");
        } else {
            asm volatile("cp.async.wait_group 0;" ::: "memory");
        }
        __syncthreads();
        uint32_t kb = sb + ASM_KV + buf * AKVSTAGE;

        // ---- S = Q K^T over 64 keys (1-pass) ----
        float sacc[8][4];
        #pragma unroll
        for (int j = 0; j < 8; j++)
            #pragma unroll
            for (int q = 0; q < 4; q++) sacc[j][q] = 0.f;

        #pragma unroll
        for (int s = 0; s < 4; s++) {
            #pragma unroll
            for (int np = 0; np < 4; np++) {
                uint32_t bo = (uint32_t)(np * 16 + b_rowo) * AROWB + s * 32 + b_cbo;
                uint32_t kf[4];
                ldm4(kf, kb + AKV_K + bo);
                #pragma unroll
                for (int hf = 0; hf < 2; hf++)
                    mma_f16(sacc[np*2+hf], qf[s], kf[hf*2], kf[hf*2+1]);
            }
        }

        // ---- causal mask (tiles overlapping the diagonal) ----
        if (kt >= 2 * qt) {
            int qr0 = qt * 128 + wid * 16 + (lane >> 2);
            int kc  = kt * 64 + (lane & 3) * 2;
            #pragma unroll
            for (int j = 0; j < 8; j++) {
                int k0i = kc + j * 8;
                if (k0i     > qr0)     sacc[j][0] = -1e30f;
                if (k0i + 1 > qr0)     sacc[j][1] = -1e30f;
                if (k0i     > qr0 + 8) sacc[j][2] = -1e30f;
                if (k0i + 1 > qr0 + 8) sacc[j][3] = -1e30f;
            }
        }

        // ---- online softmax ----
        float mx0 = m0, mx1 = m1;
        #pragma unroll
        for (int j = 0; j < 8; j++) {
            mx0 = fmaxf(mx0, fmaxf(sacc[j][0], sacc[j][1]));
            mx1 = fmaxf(mx1, fmaxf(sacc[j][2], sacc[j][3]));
        }
        mx0 = fmaxf(mx0, __shfl_xor_sync(0xFFFFFFFFu, mx0, 1));
        mx0 = fmaxf(mx0, __shfl_xor_sync(0xFFFFFFFFu, mx0, 2));
        mx1 = fmaxf(mx1, __shfl_xor_sync(0xFFFFFFFFu, mx1, 1));
        mx1 = fmaxf(mx1, __shfl_xor_sync(0xFFFFFFFFu, mx1, 2));
        float cor0 = __expf(m0 - mx0);
        float cor1 = __expf(m1 - mx1);
        m0 = mx0; m1 = mx1;
        float rs0 = 0.f, rs1 = 0.f;
        #pragma unroll
        for (int j = 0; j < 8; j++) {
            float p0 = __expf(sacc[j][0] - m0);
            float p1 = __expf(sacc[j][1] - m0);
            float p2 = __expf(sacc[j][2] - m1);
            float p3 = __expf(sacc[j][3] - m1);
            sacc[j][0] = p0; sacc[j][1] = p1; sacc[j][2] = p2; sacc[j][3] = p3;
            rs0 += p0 + p1; rs1 += p2 + p3;
        }
        rs0 += __shfl_xor_sync(0xFFFFFFFFu, rs0, 1);
        rs0 += __shfl_xor_sync(0xFFFFFFFFu, rs0, 2);
        rs1 += __shfl_xor_sync(0xFFFFFFFFu, rs1, 1);
        rs1 += __shfl_xor_sync(0xFFFFFFFFu, rs1, 2);
        l0 = l0 * cor0 + rs0;
        l1 = l1 * cor1 + rs1;
        #pragma unroll
        for (int dt = 0; dt < 8; dt++) {
            oacc[dt][0] *= cor0; oacc[dt][1] *= cor0;
            oacc[dt][2] *= cor1; oacc[dt][3] *= cor1;
        }

        // ---- O += P V  (1-pass) ----
        #pragma unroll
        for (int s = 0; s < 4; s++) {
            uint32_t pah[4];
            #pragma unroll
            for (int tt = 0; tt < 2; tt++) {
                const float* sc = sacc[2*s + tt];
                pah[tt*2+0] = packh(sc[0], sc[1]);
                pah[tt*2+1] = packh(sc[2], sc[3]);
            }
            #pragma unroll
            for (int dc = 0; dc < 4; dc++) {
                uint32_t vo = (uint32_t)(s * 16 + v_rowo) * AROWB + dc * 32 + v_cbo;
                uint32_t vf[4];
                ldm4t(vf, kb + AKV_V + vo);
                mma_f16(oacc[dc*2+0], pah, vf[0], vf[1]);
                mma_f16(oacc[dc*2+1], pah, vf[2], vf[3]);
            }
        }
        __syncthreads();
    }

    float inv0 = 1.0f / l0;
    float inv1 = 1.0f / l1;
    int qr = qt * 128 + wid * 16 + (lane >> 2);
    size_t y0 = (rowbase + qr) * E_ + h * HS_ + (lane & 3) * 2;
    size_t y1 = y0 + (size_t)8 * E_;
    #pragma unroll
    for (int dt = 0; dt < 8; dt++) {
        *(__half2*)(Y + y0 + dt*8) = __floats2half2_rn(oacc[dt][0]*inv0, oacc[dt][1]*inv0);
        *(__half2*)(Y + y1 + dt*8) = __floats2half2_rn(oacc[dt][2]*inv1, oacc[dt][3]*inv1);
    }
}

// ======================= launch =======================
extern "C" void kernel_launch(void* const* d_in, const int* in_sizes, int n_in,
                              void* d_out, int out_size)
{
    const float* x    = (const float*)d_in[0];
    const float* Wq   = (const float*)d_in[1];
    const float* Wk   = (const float*)d_in[2];
    const float* Wv   = (const float*)d_in[3];
    const float* Wo   = (const float*)d_in[4];
    const float* bo   = (const float*)d_in[5];
    const float* ln1w = (const float*)d_in[6];
    const float* ln2w = (const float*)d_in[7];
    const float* W1   = (const float*)d_in[8];
    const float* b1   = (const float*)d_in[9];
    const float* W2   = (const float*)d_in[10];
    const float* b2   = (const float*)d_in[11];
    float* out = (float*)d_out;

    unsigned char* pool;
    cudaGetSymbolAddress((void**)&pool, g_pool);

    fp16*  hh   = (fp16*)(pool + O_H);
    fp16*  q    = (fp16*)(pool + O_Q);
    fp16*  k    = (fp16*)(pool + O_K);
    fp16*  v    = (fp16*)(pool + O_V);
    fp16*  y    = (fp16*)(pool + O_Y);
    float* x2   = (float*)(pool + O_X2);
    fp16*  ff   = (fp16*)(pool + O_FF);
    fp16*  wqh = (fp16*)(pool + O_WQH), *wql = (fp16*)(pool + O_WQL);
    fp16*  wkh = (fp16*)(pool + O_WKH), *wkl = (fp16*)(pool + O_WKL);
    fp16*  wvh = (fp16*)(pool + O_WVH), *wvl = (fp16*)(pool + O_WVL);
    fp16*  woh = (fp16*)(pool + O_WOH), *wol = (fp16*)(pool + O_WOL);
    fp16*  w1h = (fp16*)(pool + O_W1H), *w1l = (fp16*)(pool + O_W1L);
    fp16*  w2h = (fp16*)(pool + O_W2H), *w2l = (fp16*)(pool + O_W2L);

    cudaFuncSetAttribute((const void*)gemm_tc<1>, cudaFuncAttributeMaxDynamicSharedMemorySize, SMEM_SZ);
    cudaFuncSetAttribute((const void*)gemm_tc<2>, cudaFuncAttributeMaxDynamicSharedMemorySize, SMEM_SZ);
    cudaFuncSetAttribute((const void*)gemm_tc<3>, cudaFuncAttributeMaxDynamicSharedMemorySize, SMEM_SZ);
    cudaFuncSetAttribute((const void*)attn_tc,    cudaFuncAttributeMaxDynamicSharedMemorySize, ASMEM);

    dim3 tb(32, 8);
    dim3 gE (E_  / BN, M_ / BM);       // (8, 64)
    dim3 gQKV(3 * (E_ / BN), M_ / BM); // (24, 64)
    dim3 g4E(FF_ / BN, M_ / BM);       // (32, 64)

    // weight splits (x64 pre-scale)
    wsplit_kernel<<<dim3(E_/32,  E_/32),  tb>>>(Wq, wqh, wql, E_,  E_);
    wsplit_kernel<<<dim3(E_/32,  E_/32),  tb>>>(Wk, wkh, wkl, E_,  E_);
    wsplit_kernel<<<dim3(E_/32,  E_/32),  tb>>>(Wv, wvh, wvl, E_,  E_);
    wsplit_kernel<<<dim3(E_/32,  E_/32),  tb>>>(Wo, woh, wol, E_,  E_);
    // h = LN1(x)
    ln_kernel<<<M_, 256>>>(x, ln1w, hh);
    // fused q,k,v projections -> single fp16 each (q pre-scaled by E^-0.5)
    gemm_tc<3><<<gQKV, 256, SMEM_SZ>>>(hh,
        wqh, wql, wkh, wkl, wvh, wvl,
        nullptr, nullptr, nullptr,
        q, k, v, M_, E_, E_);
    // y = causal attention (all-fp16, 1-pass QK^T + 1-pass PV)
    attn_tc<<<dim3(T_/128, B_*H_), 256, ASMEM>>>(q, k, v, y);
    // MLP weight splits
    wsplit_kernel<<<dim3(FF_/32, E_/32),  tb>>>(W1, w1h, w1l, E_,  FF_);
    wsplit_kernel<<<dim3(E_/32,  FF_/32), tb>>>(W2, w2h, w2l, FF_, E_);
    // x2 = x + y @ Wo + bo
    gemm_tc<1><<<gE, 256, SMEM_SZ>>>(y,
        woh, wol, woh, wol, woh, wol,
        bo, x, x2,
        nullptr, nullptr, nullptr, M_, E_, E_);
    // h2 = LN2(x2)
    ln_kernel<<<M_, 256>>>(x2, ln2w, hh);
    // ff = relu(h2 @ W1 + b1)
    gemm_tc<2><<<g4E, 256, SMEM_SZ>>>(hh,
        w1h, w1l, w1h, w1l, w1h, w1l,
        b1, nullptr, nullptr,
        ff, nullptr, nullptr, M_, FF_, E_);
    // out = x2 + ff @ W2 + b2
    gemm_tc<1><<<gE, 256, SMEM_SZ>>>(ff,
        w2h, w2l, w2h, w2l, w2h, w2l,
        b2, x2, out,
        nullptr, nullptr, nullptr, M_, E_, FF_);
}

// round 15
// speedup vs baseline: 5.6204x; 1.5143x over previous
#include <cuda_runtime.h>
#include <cuda_fp16.h>
#include <cstdint>

#define B_  4
#define T_  2048
#define E_  1024
#define H_  16
#define HS_ 64
#define M_  (B_*T_)    // 8192
#define FF_ (4*E_)     // 4096

typedef unsigned long long u64;
typedef __half fp16;

// weight pre-scale (keeps small weights out of fp16 subnormal range)
#define WSC   64.0f
#define WSI   0.015625f               // 1/64
#define QSI   (0.015625f * 0.03125f)  // 1/64 * E^-0.5

// ======================= scratch pool (__device__ global) =======================
#define SZ_HB   ((size_t)M_*E_*2)
#define SZ_F32  ((size_t)M_*E_*4)
#define SZ_FFB  ((size_t)M_*FF_*2)
#define SZ_WB   ((size_t)E_*E_*2)
#define SZ_W1B  ((size_t)E_*FF_*2)

constexpr size_t O_H    = 0;
constexpr size_t O_Q    = O_H    + SZ_HB;
constexpr size_t O_K    = O_Q    + SZ_HB;
constexpr size_t O_V    = O_K    + SZ_HB;
constexpr size_t O_Y    = O_V    + SZ_HB;
constexpr size_t O_X2   = O_Y    + SZ_HB;
constexpr size_t O_FF   = O_X2   + SZ_F32;
constexpr size_t O_WQ   = O_FF   + SZ_FFB;
constexpr size_t O_WK   = O_WQ   + SZ_WB;
constexpr size_t O_WV   = O_WK   + SZ_WB;
constexpr size_t O_WO   = O_WV   + SZ_WB;
constexpr size_t O_W1   = O_WO   + SZ_WB;
constexpr size_t O_W2   = O_W1   + SZ_W1B;
constexpr size_t POOLSZ = O_W2   + SZ_W1B;

__device__ __align__(1024) unsigned char g_pool[POOLSZ];

// ======================= PTX helpers =======================
__device__ __forceinline__ uint32_t s2u(const void* p){
    uint32_t a;
    asm("{ .reg .u64 t; cvta.to.shared.u64 t, %1; cvt.u32.u64 %0, t; }" : "=r"(a) : "l"(p));
    return a;
}
__device__ __forceinline__ void cp16(uint32_t s, const void* g){
    asm volatile("cp.async.cg.shared.global [%0], [%1], 16;" :: "r"(s), "l"(g));
}
__device__ __forceinline__ void ldm4(uint32_t (&r)[4], uint32_t a){
    asm volatile("ldmatrix.sync.aligned.m8n8.x4.shared.b16 {%0,%1,%2,%3}, [%4];"
                 : "=r"(r[0]), "=r"(r[1]), "=r"(r[2]), "=r"(r[3]) : "r"(a));
}
__device__ __forceinline__ void ldm4t(uint32_t (&r)[4], uint32_t a){
    asm volatile("ldmatrix.sync.aligned.m8n8.x4.trans.shared.b16 {%0,%1,%2,%3}, [%4];"
                 : "=r"(r[0]), "=r"(r[1]), "=r"(r[2]), "=r"(r[3]) : "r"(a));
}
__device__ __forceinline__ void mma_f16(float (&c)[4], const uint32_t* a, uint32_t b0, uint32_t b1){
    asm volatile(
        "mma.sync.aligned.m16n8k16.row.col.f32.f16.f16.f32 "
        "{%0,%1,%2,%3}, {%4,%5,%6,%7}, {%8,%9}, {%0,%1,%2,%3};"
        : "+f"(c[0]), "+f"(c[1]), "+f"(c[2]), "+f"(c[3])
        : "r"(a[0]), "r"(a[1]), "r"(a[2]), "r"(a[3]), "r"(b0), "r"(b1));
}
__device__ __forceinline__ uint32_t packh(float lo_val, float hi_val){
    uint32_t r;
    asm("cvt.rn.f16x2.f32 %0, %1, %2;" : "=r"(r) : "f"(hi_val), "f"(lo_val));
    return r;
}

// ======================= LayerNorm -> single fp16 =======================
__global__ __launch_bounds__(256) void ln_kernel(
    const float* __restrict__ X, const float* __restrict__ w,
    fp16* __restrict__ O)
{
    int row = blockIdx.x;
    int tid = threadIdx.x;
    const float* x = X + (size_t)row * E_;

    float4 v = *(const float4*)(x + tid * 4);
    float s  = v.x + v.y + v.z + v.w;
    float sq = v.x*v.x + v.y*v.y + v.z*v.z + v.w*v.w;

    #pragma unroll
    for (int o = 16; o; o >>= 1) {
        s  += __shfl_xor_sync(0xFFFFFFFFu, s,  o);
        sq += __shfl_xor_sync(0xFFFFFFFFu, sq, o);
    }
    __shared__ float ss[8], ssq[8], red[2];
    int wid = tid >> 5, lane = tid & 31;
    if (lane == 0) { ss[wid] = s; ssq[wid] = sq; }
    __syncthreads();
    if (tid == 0) {
        float a = 0.f, b = 0.f;
        #pragma unroll
        for (int i = 0; i < 8; i++) { a += ss[i]; b += ssq[i]; }
        float mean = a * (1.0f / E_);
        float var  = b * (1.0f / E_) - mean * mean;
        red[0] = mean;
        red[1] = rsqrtf(var + 1e-5f);
    }
    __syncthreads();
    float mean = red[0], rs = red[1];
    float4 wv = *(const float4*)(w + tid * 4);
    float o0 = (v.x - mean) * rs * wv.x;
    float o1 = (v.y - mean) * rs * wv.y;
    float o2 = (v.z - mean) * rs * wv.z;
    float o3 = (v.w - mean) * rs * wv.w;

    __half2 p0 = __floats2half2_rn(o0, o1);
    __half2 p1 = __floats2half2_rn(o2, o3);
    size_t off = (size_t)row * E_ + tid * 4;
    *(__half2*)(O + off)     = p0;
    *(__half2*)(O + off + 2) = p1;
}

// ======================= weight transpose + convert (x64 scale) ================
__global__ __launch_bounds__(256) void wconv_kernel(
    const float* __restrict__ W, fp16* __restrict__ Wo,
    int K, int N)
{
    __shared__ float t[32][33];
    int n0 = blockIdx.x * 32, k0 = blockIdx.y * 32;
    int tx = threadIdx.x, ty0 = threadIdx.y;
    #pragma unroll
    for (int dy = 0; dy < 32; dy += 8) {
        int ty = ty0 + dy;
        t[ty][tx] = W[(size_t)(k0 + ty) * N + n0 + tx];
    }
    __syncthreads();
    #pragma unroll
    for (int dy = 0; dy < 32; dy += 8) {
        int ty = ty0 + dy;
        Wo[(size_t)(n0 + ty) * K + k0 + tx] = __float2half_rn(t[tx][ty] * WSC);
    }
}

// ======================= HMMA GEMM (fp16 1-pass) ============
// BK=64, 73.7KB smem, 2 CTAs/SM. Weights pre-scaled x64; epilogue applies 1/64.
// OP: 1 = acc*WSI+bias+res -> f32; 2 = relu(acc*WSI+bias) -> fp16;
// OP: 3 = fused QKV: sel0 -> q (x QSI); sel1/2 -> k/v (x WSI)
#define BM 128
#define BN 128
#define BK 64
#define ROWB   144
#define MTILE  (128*ROWB)     // 18432
#define BUFSZ  (2*MTILE)      // 36864  (A, B)
#define SMEM_SZ (2*BUFSZ)     // 73728

template<int OP>
__global__ __launch_bounds__(256, 2) void gemm_tc(
    const fp16* __restrict__ A,
    const fp16* __restrict__ B0, const fp16* __restrict__ B1, const fp16* __restrict__ B2,
    const float* __restrict__ bias, const float* __restrict__ res,
    float* __restrict__ C,
    fp16* __restrict__ C0, fp16* __restrict__ C1, fp16* __restrict__ C2,
    int M, int N, int K)
{
    extern __shared__ __align__(128) unsigned char smem[];
    uint32_t sb = s2u(smem);
    int tid = threadIdx.x;
    int lane = tid & 31, wid = tid >> 5;
    int warp_m = wid & 1, warp_n = wid >> 1;

    int sel = 0, bxi = blockIdx.x;
    if (OP == 3) { sel = blockIdx.x >> 3; bxi = blockIdx.x & 7; }
    int bx = bxi * BN, by = blockIdx.y * BM;

    const fp16* Bp = (OP == 3) ? (sel == 0 ? B0 : sel == 1 ? B1 : B2) : B0;
    fp16* Cout = (OP == 3) ? (sel == 0 ? C0 : sel == 1 ? C1 : C2) : C0;
    float oscale = (OP == 3 && sel == 0) ? QSI : WSI;

    int chb = tid * 4;
    int lrow[4], lc16[4];
    uint32_t soff[4];
    #pragma unroll
    for (int i = 0; i < 4; i++) {
        lrow[i] = (chb + i) >> 3;
        lc16[i] = (chb + i) & 7;
        soff[i] = (uint32_t)(lrow[i] * ROWB + lc16[i] * 16);
    }

    const fp16* gA = A  + (size_t)(by) * K;
    const fp16* gB = Bp + (size_t)(bx) * K;

    float acc[4][4][4];
    #pragma unroll
    for (int i = 0; i < 4; i++)
        #pragma unroll
        for (int j = 0; j < 4; j++)
            #pragma unroll
            for (int q = 0; q < 4; q++) acc[i][j][q] = 0.f;

    int nt = K / BK;

    auto issue_tile = [&](int t, int buf) {
        uint32_t base = sb + buf * BUFSZ;
        int k0 = t * BK;
        #pragma unroll
        for (int i = 0; i < 4; i++) {
            size_t go = (size_t)lrow[i] * K + k0 + lc16[i] * 8;
            cp16(base + soff[i],         gA + go);
            cp16(base + MTILE + soff[i], gB + go);
        }
        asm volatile("cp.async.commit_group;" ::: "memory");
    };

    issue_tile(0, 0);

    uint32_t a_row = (uint32_t)(warp_m * 64 + (lane & 15));
    uint32_t a_cb  = (uint32_t)((lane >> 4) * 16);
    uint32_t b_row = (uint32_t)(warp_n * 32 + (lane & 7) + ((lane >> 4) & 1) * 8);
    uint32_t b_cb  = (uint32_t)(((lane >> 3) & 1) * 16);

    for (int t = 0; t < nt; t++) {
        int buf = t & 1;
        if (t + 1 < nt) {
            issue_tile(t + 1, buf ^ 1);
            asm volatile("cp.async.wait_group 1;" ::: "memory");
        } else {
            asm volatile("cp.async.wait_group 0;" ::: "memory");
        }
        __syncthreads();

        uint32_t base = sb + buf * BUFSZ;
        uint32_t sA = base;
        uint32_t sB = base + MTILE;

        #pragma unroll
        for (int s = 0; s < 4; s++) {
            uint32_t kb = (uint32_t)(s * 32);

            uint32_t af[4][4];
            #pragma unroll
            for (int mt = 0; mt < 4; mt++)
                ldm4(af[mt], sA + (a_row + mt * 16) * ROWB + kb + a_cb);
            uint32_t bf[2][4];
            #pragma unroll
            for (int ntp = 0; ntp < 2; ntp++)
                ldm4(bf[ntp], sB + (b_row + ntp * 16) * ROWB + kb + b_cb);
            #pragma unroll
            for (int mt = 0; mt < 4; mt++)
                #pragma unroll
                for (int ntp = 0; ntp < 2; ntp++)
                    #pragma unroll
                    for (int hf = 0; hf < 2; hf++)
                        mma_f16(acc[mt][ntp*2+hf], af[mt], bf[ntp][hf*2], bf[ntp][hf*2+1]);
        }
        __syncthreads();
    }

    // -------- epilogue --------
    int er = by + warp_m * 64 + (lane >> 2);
    int ec = bx + warp_n * 32 + (lane & 3) * 2;
    #pragma unroll
    for (int mt = 0; mt < 4; mt++) {
        #pragma unroll
        for (int half = 0; half < 2; half++) {
            int row = er + mt * 16 + half * 8;
            #pragma unroll
            for (int ntj = 0; ntj < 4; ntj++) {
                int col = ec + ntj * 8;
                float v0 = acc[mt][ntj][half*2];
                float v1 = acc[mt][ntj][half*2+1];
                if (OP == 1) {
                    float2 rv = *(const float2*)&res[(size_t)row * N + col];
                    float2 bv = *(const float2*)&bias[col];
                    *(float2*)&C[(size_t)row * N + col] =
                        make_float2(v0 * WSI + bv.x + rv.x, v1 * WSI + bv.y + rv.y);
                } else if (OP == 2) {
                    float2 bv = *(const float2*)&bias[col];
                    float w0 = fmaxf(v0 * WSI + bv.x, 0.0f);
                    float w1 = fmaxf(v1 * WSI + bv.y, 0.0f);
                    *(__half2*)&C0[(size_t)row * N + col] = __floats2half2_rn(w0, w1);
                } else {
                    *(__half2*)&Cout[(size_t)row * N + col] =
                        __floats2half2_rn(v0 * oscale, v1 * oscale);
                }
            }
        }
    }
}

// ======================= Tensor-core causal flash attention ====================
// q, K, V all single fp16: QK^T 1-pass, PV 1-pass.  (R13-validated)
#define AROWB 144
#define AQTILE (128*AROWB)    // 18432
#define AKTILE (64*AROWB)     // 9216
#define ASM_Q  0
#define ASM_KV AQTILE
#define AKV_K  0
#define AKV_V  AKTILE
#define AKVSTAGE (2*AKTILE)   // 18432
#define ASMEM (AQTILE + 2*AKVSTAGE)  // 55296

__global__ __launch_bounds__(256, 2) void attn_tc(
    const fp16* __restrict__ Q,
    const fp16* __restrict__ Kg,
    const fp16* __restrict__ V,
    fp16* __restrict__ Y)
{
    extern __shared__ __align__(128) unsigned char asmem[];
    uint32_t sb = s2u(asmem);
    int tid = threadIdx.x, lane = tid & 31, wid = tid >> 5;
    int qt = blockIdx.x, bh = blockIdx.y;
    int b = bh >> 4, h = bh & 15;

    size_t rowbase = (size_t)b * T_;
    size_t qoff = (rowbase + qt * 128) * E_ + h * HS_;

    {
        int chb = tid * 4;
        #pragma unroll
        for (int i = 0; i < 4; i++) {
            int lr = (chb + i) >> 3;
            int lc = (chb + i) & 7;
            uint32_t so = (uint32_t)(lr * AROWB + lc * 16);
            cp16(sb + ASM_Q + so, Q + qoff + (size_t)lr * E_ + lc * 8);
        }
    }
    asm volatile("cp.async.commit_group;" ::: "memory");

    int kv_row = tid >> 2;
    int kv_c   = (tid & 3) * 2;
    uint32_t kv_so = (uint32_t)(kv_row * AROWB + kv_c * 16);

    auto load_kv = [&](int kt, int buf) {
        size_t ko = (rowbase + kt * 64 + kv_row) * E_ + h * HS_ + kv_c * 8;
        uint32_t base = sb + ASM_KV + buf * AKVSTAGE + kv_so;
        cp16(base + AKV_K,      Kg + ko);
        cp16(base + AKV_K + 16, Kg + ko + 8);
        cp16(base + AKV_V,      V + ko);
        cp16(base + AKV_V + 16, V + ko + 8);
        asm volatile("cp.async.commit_group;" ::: "memory");
    };
    load_kv(0, 0);

    asm volatile("cp.async.wait_group 1;" ::: "memory");
    __syncthreads();

    uint32_t a_row = (uint32_t)(wid * 16 + (lane & 15));
    uint32_t a_cb  = (uint32_t)((lane >> 4) * 16);
    uint32_t qf[4][4];
    #pragma unroll
    for (int s = 0; s < 4; s++)
        ldm4(qf[s], sb + ASM_Q + a_row * AROWB + s * 32 + a_cb);

    float oacc[8][4];
    #pragma unroll
    for (int i = 0; i < 8; i++)
        #pragma unroll
        for (int j = 0; j < 4; j++) oacc[i][j] = 0.f;
    float m0 = -1e30f, m1 = -1e30f, l0 = 0.f, l1 = 0.f;

    uint32_t b_rowo = (uint32_t)((lane & 7) + ((lane >> 4) & 1) * 8);
    uint32_t b_cbo  = (uint32_t)(((lane >> 3) & 1) * 16);
    uint32_t v_rowo = (uint32_t)(lane & 15);
    uint32_t v_cbo  = (uint32_t)(((lane >> 4) & 1) * 16);

    int nkt = 2 * qt + 2;
    for (int kt = 0; kt < nkt; kt++) {
        int buf = kt & 1;
        if (kt + 1 < nkt) {
            load_kv(kt + 1, buf ^ 1);
            asm volatile("cp.async.wait_group 1;" ::: "memory");
        } else {
            asm volatile("cp.async.wait_group 0;" ::: "memory");
        }
        __syncthreads();
        uint32_t kb = sb + ASM_KV + buf * AKVSTAGE;

        float sacc[8][4];
        #pragma unroll
        for (int j = 0; j < 8; j++)
            #pragma unroll
            for (int q = 0; q < 4; q++) sacc[j][q] = 0.f;

        #pragma unroll
        for (int s = 0; s < 4; s++) {
            #pragma unroll
            for (int np = 0; np < 4; np++) {
                uint32_t bo = (uint32_t)(np * 16 + b_rowo) * AROWB + s * 32 + b_cbo;
                uint32_t kf[4];
                ldm4(kf, kb + AKV_K + bo);
                #pragma unroll
                for (int hf = 0; hf < 2; hf++)
                    mma_f16(sacc[np*2+hf], qf[s], kf[hf*2], kf[hf*2+1]);
            }
        }

        if (kt >= 2 * qt) {
            int qr0 = qt * 128 + wid * 16 + (lane >> 2);
            int kc  = kt * 64 + (lane & 3) * 2;
            #pragma unroll
            for (int j = 0; j < 8; j++) {
                int k0i = kc + j * 8;
                if (k0i     > qr0)     sacc[j][0] = -1e30f;
                if (k0i + 1 > qr0)     sacc[j][1] = -1e30f;
                if (k0i     > qr0 + 8) sacc[j][2] = -1e30f;
                if (k0i + 1 > qr0 + 8) sacc[j][3] = -1e30f;
            }
        }

        float mx0 = m0, mx1 = m1;
        #pragma unroll
        for (int j = 0; j < 8; j++) {
            mx0 = fmaxf(mx0, fmaxf(sacc[j][0], sacc[j][1]));
            mx1 = fmaxf(mx1, fmaxf(sacc[j][2], sacc[j][3]));
        }
        mx0 = fmaxf(mx0, __shfl_xor_sync(0xFFFFFFFFu, mx0, 1));
        mx0 = fmaxf(mx0, __shfl_xor_sync(0xFFFFFFFFu, mx0, 2));
        mx1 = fmaxf(mx1, __shfl_xor_sync(0xFFFFFFFFu, mx1, 1));
        mx1 = fmaxf(mx1, __shfl_xor_sync(0xFFFFFFFFu, mx1, 2));
        float cor0 = __expf(m0 - mx0);
        float cor1 = __expf(m1 - mx1);
        m0 = mx0; m1 = mx1;
        float rs0 = 0.f, rs1 = 0.f;
        #pragma unroll
        for (int j = 0; j < 8; j++) {
            float p0 = __expf(sacc[j][0] - m0);
            float p1 = __expf(sacc[j][1] - m0);
            float p2 = __expf(sacc[j][2] - m1);
            float p3 = __expf(sacc[j][3] - m1);
            sacc[j][0] = p0; sacc[j][1] = p1; sacc[j][2] = p2; sacc[j][3] = p3;
            rs0 += p0 + p1; rs1 += p2 + p3;
        }
        rs0 += __shfl_xor_sync(0xFFFFFFFFu, rs0, 1);
        rs0 += __shfl_xor_sync(0xFFFFFFFFu, rs0, 2);
        rs1 += __shfl_xor_sync(0xFFFFFFFFu, rs1, 1);
        rs1 += __shfl_xor_sync(0xFFFFFFFFu, rs1, 2);
        l0 = l0 * cor0 + rs0;
        l1 = l1 * cor1 + rs1;
        #pragma unroll
        for (int dt = 0; dt < 8; dt++) {
            oacc[dt][0] *= cor0; oacc[dt][1] *= cor0;
            oacc[dt][2] *= cor1; oacc[dt][3] *= cor1;
        }

        #pragma unroll
        for (int s = 0; s < 4; s++) {
            uint32_t pah[4];
            #pragma unroll
            for (int tt = 0; tt < 2; tt++) {
                const float* sc = sacc[2*s + tt];
                pah[tt*2+0] = packh(sc[0], sc[1]);
                pah[tt*2+1] = packh(sc[2], sc[3]);
            }
            #pragma unroll
            for (int dc = 0; dc < 4; dc++) {
                uint32_t vo = (uint32_t)(s * 16 + v_rowo) * AROWB + dc * 32 + v_cbo;
                uint32_t vf[4];
                ldm4t(vf, kb + AKV_V + vo);
                mma_f16(oacc[dc*2+0], pah, vf[0], vf[1]);
                mma_f16(oacc[dc*2+1], pah, vf[2], vf[3]);
            }
        }
        __syncthreads();
    }

    float inv0 = 1.0f / l0;
    float inv1 = 1.0f / l1;
    int qr = qt * 128 + wid * 16 + (lane >> 2);
    size_t y0 = (rowbase + qr) * E_ + h * HS_ + (lane & 3) * 2;
    size_t y1 = y0 + (size_t)8 * E_;
    #pragma unroll
    for (int dt = 0; dt < 8; dt++) {
        *(__half2*)(Y + y0 + dt*8) = __floats2half2_rn(oacc[dt][0]*inv0, oacc[dt][1]*inv0);
        *(__half2*)(Y + y1 + dt*8) = __floats2half2_rn(oacc[dt][2]*inv1, oacc[dt][3]*inv1);
    }
}

// ======================= launch =======================
extern "C" void kernel_launch(void* const* d_in, const int* in_sizes, int n_in,
                              void* d_out, int out_size)
{
    const float* x    = (const float*)d_in[0];
    const float* Wq   = (const float*)d_in[1];
    const float* Wk   = (const float*)d_in[2];
    const float* Wv   = (const float*)d_in[3];
    const float* Wo   = (const float*)d_in[4];
    const float* bo   = (const float*)d_in[5];
    const float* ln1w = (const float*)d_in[6];
    const float* ln2w = (const float*)d_in[7];
    const float* W1   = (const float*)d_in[8];
    const float* b1   = (const float*)d_in[9];
    const float* W2   = (const float*)d_in[10];
    const float* b2   = (const float*)d_in[11];
    float* out = (float*)d_out;

    unsigned char* pool;
    cudaGetSymbolAddress((void**)&pool, g_pool);

    fp16*  hh   = (fp16*)(pool + O_H);
    fp16*  q    = (fp16*)(pool + O_Q);
    fp16*  k    = (fp16*)(pool + O_K);
    fp16*  v    = (fp16*)(pool + O_V);
    fp16*  y    = (fp16*)(pool + O_Y);
    float* x2   = (float*)(pool + O_X2);
    fp16*  ff   = (fp16*)(pool + O_FF);
    fp16*  wq   = (fp16*)(pool + O_WQ);
    fp16*  wk   = (fp16*)(pool + O_WK);
    fp16*  wv   = (fp16*)(pool + O_WV);
    fp16*  wo   = (fp16*)(pool + O_WO);
    fp16*  w1   = (fp16*)(pool + O_W1);
    fp16*  w2   = (fp16*)(pool + O_W2);

    cudaFuncSetAttribute((const void*)gemm_tc<1>, cudaFuncAttributeMaxDynamicSharedMemorySize, SMEM_SZ);
    cudaFuncSetAttribute((const void*)gemm_tc<2>, cudaFuncAttributeMaxDynamicSharedMemorySize, SMEM_SZ);
    cudaFuncSetAttribute((const void*)gemm_tc<3>, cudaFuncAttributeMaxDynamicSharedMemorySize, SMEM_SZ);
    cudaFuncSetAttribute((const void*)attn_tc,    cudaFuncAttributeMaxDynamicSharedMemorySize, ASMEM);

    dim3 tb(32, 8);
    dim3 gE (E_  / BN, M_ / BM);       // (8, 64)
    dim3 gQKV(3 * (E_ / BN), M_ / BM); // (24, 64)
    dim3 g4E(FF_ / BN, M_ / BM);       // (32, 64)

    // weight transpose + convert (x64 pre-scale)
    wconv_kernel<<<dim3(E_/32,  E_/32),  tb>>>(Wq, wq, E_,  E_);
    wconv_kernel<<<dim3(E_/32,  E_/32),  tb>>>(Wk, wk, E_,  E_);
    wconv_kernel<<<dim3(E_/32,  E_/32),  tb>>>(Wv, wv, E_,  E_);
    wconv_kernel<<<dim3(E_/32,  E_/32),  tb>>>(Wo, wo, E_,  E_);
    // h = LN1(x)
    ln_kernel<<<M_, 256>>>(x, ln1w, hh);
    // fused q,k,v projections -> single fp16 each (q pre-scaled by E^-0.5)
    gemm_tc<3><<<gQKV, 256, SMEM_SZ>>>(hh,
        wq, wk, wv,
        nullptr, nullptr, nullptr,
        q, k, v, M_, E_, E_);
    // y = causal attention
    attn_tc<<<dim3(T_/128, B_*H_), 256, ASMEM>>>(q, k, v, y);
    // MLP weight converts
    wconv_kernel<<<dim3(FF_/32, E_/32),  tb>>>(W1, w1, E_,  FF_);
    wconv_kernel<<<dim3(E_/32,  FF_/32), tb>>>(W2, w2, FF_, E_);
    // x2 = x + y @ Wo + bo
    gemm_tc<1><<<gE, 256, SMEM_SZ>>>(y,
        wo, wo, wo,
        bo, x, x2,
        nullptr, nullptr, nullptr, M_, E_, E_);
    // h2 = LN2(x2)
    ln_kernel<<<M_, 256>>>(x2, ln2w, hh);
    // ff = relu(h2 @ W1 + b1)
    gemm_tc<2><<<g4E, 256, SMEM_SZ>>>(hh,
        w1, w1, w1,
        b1, nullptr, nullptr,
        ff, nullptr, nullptr, M_, FF_, E_);
    // out = x2 + ff @ W2 + b2
    gemm_tc<1><<<gE, 256, SMEM_SZ>>>(ff,
        w2, w2, w2,
        b2, x2, out,
        nullptr, nullptr, nullptr, M_, E_, FF_);
}